// round 1
// baseline (speedup 1.0000x reference)
#include <cuda_runtime.h>
#include <math.h>

#define NT    1025
#define EMB   768
#define BATCH 2
#define HEADS 12
#define NREL  3972

// ------------------------- device scratch (no allocs allowed) ---------------
__device__ float g_t[BATCH * NT * EMB];
__device__ float g_h[BATCH * NT * EMB];
__device__ float g_qkv[BATCH * NT * 3 * EMB];
__device__ float g_attn[(size_t)BATCH * HEADS * NT * NT];
__device__ float g_o[BATCH * NT * EMB];
__device__ float g_mlp[BATCH * NT * 4 * EMB];
__device__ float g_patch[BATCH * 1024 * EMB];
__device__ float g_tok[BATCH * 1024 * EMB];
__device__ float g_feat0[BATCH * NT * EMB];
__device__ float g_feat1[BATCH * NT * EMB];
__device__ float g_feat2[BATCH * NT * EMB];
__device__ float g_feat3[BATCH * NT * EMB];
__device__ float g_y[BATCH * 64 * 64 * EMB];
__device__ float g_tmp[(size_t)BATCH * 4096 * 3072];
__device__ float g_wpack[3072 * 768];
__device__ float g_qkvbias[3 * EMB];

__device__ __forceinline__ float gelu_exact(float x) {
    return 0.5f * x * (1.0f + erff(x * 0.70710678118654752f));
}

// ------------------------- patchify: x[B,3,512,512] -> A[B*1024, 768] -------
__global__ void patchify_kernel(const float* __restrict__ x, float* __restrict__ A) {
    int idx = blockIdx.x * 256 + threadIdx.x;
    if (idx >= BATCH * 1024 * EMB) return;
    int col = idx % EMB;
    int m = idx / EMB;
    int b = m / 1024, g = m % 1024;
    int gh = g / 32, gw = g % 32;
    int c = col / 256, rem = col % 256;
    int i = rem / 16, j = rem % 16;
    A[idx] = x[(((size_t)(b * 3 + c) * 512) + gh * 16 + i) * 512 + gw * 16 + j];
}

// t[b][n][d] = (n==0 ? cls : tok[b][n-1]) + pos[n]
__global__ void assemble_kernel(const float* __restrict__ tok, const float* __restrict__ cls,
                                const float* __restrict__ pos, float* __restrict__ t) {
    int idx = blockIdx.x * 256 + threadIdx.x;
    if (idx >= BATCH * NT * EMB) return;
    int d = idx % EMB;
    int n = (idx / EMB) % NT;
    int b = idx / (EMB * NT);
    float v = (n == 0) ? cls[d] : tok[((size_t)b * 1024 + (n - 1)) * EMB + d];
    t[idx] = v + pos[n * EMB + d];
}

// ------------------------- LayerNorm over last dim 768 ----------------------
__global__ void ln_kernel(const float* __restrict__ x, const float* __restrict__ w,
                          const float* __restrict__ b, float* __restrict__ out) {
    int r = blockIdx.x;
    const float* xr = x + (size_t)r * EMB;
    __shared__ float red[256];
    int tid = threadIdx.x;
    float s = 0.f;
    for (int i = tid; i < EMB; i += 256) s += xr[i];
    red[tid] = s; __syncthreads();
    for (int st = 128; st > 0; st >>= 1) { if (tid < st) red[tid] += red[tid + st]; __syncthreads(); }
    float mean = red[0] * (1.0f / EMB);
    __syncthreads();
    float s2 = 0.f;
    for (int i = tid; i < EMB; i += 256) { float d = xr[i] - mean; s2 += d * d; }
    red[tid] = s2; __syncthreads();
    for (int st = 128; st > 0; st >>= 1) { if (tid < st) red[tid] += red[tid + st]; __syncthreads(); }
    float inv = rsqrtf(red[0] * (1.0f / EMB) + 1e-6f);
    for (int i = tid; i < EMB; i += 256)
        out[(size_t)r * EMB + i] = (xr[i] - mean) * inv * w[i] + b[i];
}

// ------------------------- generic SGEMM: C = A[M,K] @ W[N,K]^T -------------
// epilogue: +bias[n], +res[m*N+n], gelu.  Requires K % 16 == 0.
__global__ void gemm_nt(const float* __restrict__ A, const float* __restrict__ W,
                        const float* __restrict__ bias, const float* __restrict__ res,
                        float* __restrict__ C, int M, int N, int K, int do_gelu) {
    __shared__ float As[16][68];
    __shared__ float Bs[16][68];
    int m0 = blockIdx.y * 64, n0 = blockIdx.x * 64;
    int tid = threadIdx.x;
    int tx = tid & 15, ty = tid >> 4;
    float acc[4][4] = {};
    for (int k0 = 0; k0 < K; k0 += 16) {
#pragma unroll
        for (int l = 0; l < 4; l++) {
            int idx = tid + l * 256;
            int r = idx >> 4, k = idx & 15;
            As[k][r] = (m0 + r < M) ? A[(size_t)(m0 + r) * K + k0 + k] : 0.f;
            Bs[k][r] = (n0 + r < N) ? W[(size_t)(n0 + r) * K + k0 + k] : 0.f;
        }
        __syncthreads();
#pragma unroll
        for (int kk = 0; kk < 16; kk++) {
            float a[4], bb[4];
#pragma unroll
            for (int i = 0; i < 4; i++) a[i] = As[kk][ty * 4 + i];
#pragma unroll
            for (int j = 0; j < 4; j++) bb[j] = Bs[kk][tx * 4 + j];
#pragma unroll
            for (int i = 0; i < 4; i++)
#pragma unroll
                for (int j = 0; j < 4; j++) acc[i][j] += a[i] * bb[j];
        }
        __syncthreads();
    }
#pragma unroll
    for (int i = 0; i < 4; i++) {
        int m = m0 + ty * 4 + i;
        if (m >= M) continue;
#pragma unroll
        for (int j = 0; j < 4; j++) {
            int n = n0 + tx * 4 + j;
            if (n >= N) continue;
            float v = acc[i][j];
            if (bias) v += bias[n];
            if (res) v += res[(size_t)m * N + n];
            if (do_gelu) v = gelu_exact(v);
            C[(size_t)m * N + n] = v;
        }
    }
}

// ------------------------- QKV bias pack: [q_bias | 0 | v_bias] -------------
__global__ void biaspack_kernel(const float* __restrict__ qb, const float* __restrict__ vb,
                                float* __restrict__ out) {
    int i = blockIdx.x * 256 + threadIdx.x;
    if (i >= 3 * EMB) return;
    out[i] = (i < EMB) ? qb[i] : ((i < 2 * EMB) ? 0.f : vb[i - 2 * EMB]);
}

// ------------------------- attention scores: QK^T*scale + rel bias ----------
__global__ void qk_kernel(const float* __restrict__ qkv, const float* __restrict__ relt,
                          const int* __restrict__ relidx, float* __restrict__ attn) {
    int z = blockIdx.z;           // b*12+h
    int b = z / HEADS, h = z % HEADS;
    int i0 = blockIdx.y * 32, j0 = blockIdx.x * 32;
    __shared__ float Qs[32][66];
    __shared__ float Ks[32][66];
    const float* qb = qkv + (size_t)b * NT * 2304 + h * 64;
    const float* kb = qb + EMB;
    int tid = threadIdx.x;
#pragma unroll
    for (int l = 0; l < 8; l++) {
        int idx = tid + l * 256;
        int r = idx >> 6, c = idx & 63;
        Qs[r][c] = (i0 + r < NT) ? qb[(size_t)(i0 + r) * 2304 + c] : 0.f;
        Ks[r][c] = (j0 + r < NT) ? kb[(size_t)(j0 + r) * 2304 + c] : 0.f;
    }
    __syncthreads();
    int tx = tid & 15, ty = tid >> 4;
    float acc00 = 0, acc01 = 0, acc10 = 0, acc11 = 0;
#pragma unroll 16
    for (int d = 0; d < 64; d++) {
        float a0 = Qs[ty * 2][d], a1 = Qs[ty * 2 + 1][d];
        float b0 = Ks[tx * 2][d], b1 = Ks[tx * 2 + 1][d];
        acc00 += a0 * b0; acc01 += a0 * b1; acc10 += a1 * b0; acc11 += a1 * b1;
    }
    const float scale = 0.125f;  // 64^-0.5
    float accs[2][2] = {{acc00, acc01}, {acc10, acc11}};
#pragma unroll
    for (int i = 0; i < 2; i++)
#pragma unroll
        for (int j = 0; j < 2; j++) {
            int ii = i0 + ty * 2 + i, jj = j0 + tx * 2 + j;
            if (ii < NT && jj < NT) {
                float r = relt[(size_t)relidx[(size_t)ii * NT + jj] * HEADS + h];
                attn[((size_t)z * NT + ii) * NT + jj] = accs[i][j] * scale + r;
            }
        }
}

// ------------------------- softmax per row (length 1025) --------------------
__global__ void softmax_kernel(float* __restrict__ attn) {
    size_t row = blockIdx.x;
    float* p = attn + row * NT;
    __shared__ float red[256];
    int tid = threadIdx.x;
    float mx = -1e30f;
    for (int i = tid; i < NT; i += 256) mx = fmaxf(mx, p[i]);
    red[tid] = mx; __syncthreads();
    for (int st = 128; st > 0; st >>= 1) { if (tid < st) red[tid] = fmaxf(red[tid], red[tid + st]); __syncthreads(); }
    mx = red[0];
    __syncthreads();
    float s = 0.f;
    for (int i = tid; i < NT; i += 256) { float e = __expf(p[i] - mx); p[i] = e; s += e; }
    red[tid] = s; __syncthreads();
    for (int st = 128; st > 0; st >>= 1) { if (tid < st) red[tid] += red[tid + st]; __syncthreads(); }
    float inv = 1.0f / red[0];
    for (int i = tid; i < NT; i += 256) p[i] *= inv;
}

// ------------------------- AV: o[b,i,h*64+d] = sum_j p[i,j] v[j,d] ----------
__global__ void av_kernel(const float* __restrict__ attn, const float* __restrict__ qkv,
                          float* __restrict__ o) {
    int z = blockIdx.y;
    int b = z / HEADS, h = z % HEADS;
    int i0 = blockIdx.x * 32;
    __shared__ float Ps[32][33];
    __shared__ float Vs[32][66];
    const float* vb = qkv + (size_t)b * NT * 2304 + 2 * EMB + h * 64;
    int tid = threadIdx.x;
    int tx = tid & 15, ty = tid >> 4;
    float acc[2][4] = {};
    for (int j0 = 0; j0 < NT; j0 += 32) {
#pragma unroll
        for (int l = 0; l < 4; l++) {
            int idx = tid + l * 256;
            int r = idx >> 5, c = idx & 31;
            Ps[r][c] = (i0 + r < NT && j0 + c < NT)
                       ? attn[((size_t)z * NT + i0 + r) * NT + j0 + c] : 0.f;
        }
#pragma unroll
        for (int l = 0; l < 8; l++) {
            int idx = tid + l * 256;
            int r = idx >> 6, c = idx & 63;
            Vs[r][c] = (j0 + r < NT) ? vb[(size_t)(j0 + r) * 2304 + c] : 0.f;
        }
        __syncthreads();
#pragma unroll 8
        for (int jj = 0; jj < 32; jj++) {
            float p0 = Ps[ty * 2][jj], p1 = Ps[ty * 2 + 1][jj];
#pragma unroll
            for (int c = 0; c < 4; c++) {
                float v = Vs[jj][tx * 4 + c];
                acc[0][c] += p0 * v; acc[1][c] += p1 * v;
            }
        }
        __syncthreads();
    }
#pragma unroll
    for (int i = 0; i < 2; i++) {
        int ii = i0 + ty * 2 + i;
        if (ii < NT)
#pragma unroll
            for (int c = 0; c < 4; c++)
                o[((size_t)b * NT + ii) * EMB + h * 64 + tx * 4 + c] = acc[i][c];
    }
}

__global__ void copy_kernel(const float* __restrict__ src, float* __restrict__ dst, int n) {
    int i = blockIdx.x * 256 + threadIdx.x;
    if (i < n) dst[i] = src[i];
}

// ------------------------- FPN helpers --------------------------------------
// repack deconv weight [Cin=768, Cout=768, 2, 2] -> wpack[(ij*768+d)][c]
__global__ void repack_w_kernel(const float* __restrict__ w, float* __restrict__ wp) {
    int idx = blockIdx.x * 256 + threadIdx.x;
    if (idx >= 3072 * 768) return;
    int c = idx % 768, n = idx / 768;
    int ij = n / 768, d = n % 768;
    wp[idx] = w[(size_t)c * 3072 + d * 4 + ij];
}

// tmp [B][HW*HW][4*768] -> y BHWC [B][2HW][2HW][768], + bias
__global__ void scatter_bhwc_kernel(const float* __restrict__ tmp, const float* __restrict__ bias,
                                    float* __restrict__ y, int HW) {
    int total = BATCH * HW * HW * 4 * 768;
    int idx = blockIdx.x * 256 + threadIdx.x;
    if (idx >= total) return;
    int d = idx % 768;
    int ij = (idx / 768) % 4;
    int p = (idx / 3072) % (HW * HW);
    int b = idx / (3072 * HW * HW);
    int h = p / HW, w = p % HW, i = ij / 2, j = ij % 2;
    int W2 = 2 * HW;
    y[(((size_t)b * W2 + 2 * h + i) * W2 + (2 * w + j)) * 768 + d] = tmp[idx] + bias[d];
}

// tmp [B][HW*HW][4*768] -> out BCHW [B][768][2HW][2HW], + bias
__global__ void scatter_bchw_kernel(const float* __restrict__ tmp, const float* __restrict__ bias,
                                    float* __restrict__ out, int HW) {
    int total = BATCH * HW * HW * 4 * 768;
    int idx = blockIdx.x * 256 + threadIdx.x;
    if (idx >= total) return;
    int d = idx % 768;
    int ij = (idx / 768) % 4;
    int p = (idx / 3072) % (HW * HW);
    int b = idx / (3072 * HW * HW);
    int h = p / HW, w = p % HW, i = ij / 2, j = ij % 2;
    int W2 = 2 * HW;
    out[(((size_t)b * 768 + d) * W2 + 2 * h + i) * W2 + (2 * w + j)] = tmp[idx] + bias[d];
}

__global__ void bn_gelu_kernel(float* __restrict__ y, const float* __restrict__ w,
                               const float* __restrict__ b, const float* __restrict__ mean,
                               const float* __restrict__ var) {
    int idx = blockIdx.x * 256 + threadIdx.x;
    if (idx >= BATCH * 64 * 64 * 768) return;
    int c = idx % 768;
    float v = y[idx];
    v = (v - mean[c]) * rsqrtf(var[c] + 1e-5f) * w[c] + b[c];
    y[idx] = gelu_exact(v);
}

// feat [B,1025,768] -> map [B,768,32,32] (drop cls)
__global__ void to_map_kernel(const float* __restrict__ feat, float* __restrict__ out) {
    int idx = blockIdx.x * 256 + threadIdx.x;
    if (idx >= BATCH * 768 * 32 * 32) return;
    int xw = idx % 32;
    int yh = (idx / 32) % 32;
    int c = (idx / 1024) % 768;
    int b = idx / (1024 * 768);
    out[idx] = feat[((size_t)b * NT + 1 + yh * 32 + xw) * EMB + c];
}

// o4 = 2x2 maxpool of layer-11 map -> [B,768,16,16]
__global__ void maxpool_kernel(const float* __restrict__ feat, float* __restrict__ out) {
    int idx = blockIdx.x * 256 + threadIdx.x;
    if (idx >= BATCH * 768 * 16 * 16) return;
    int xw = idx % 16;
    int yh = (idx / 16) % 16;
    int c = (idx / 256) % 768;
    int b = idx / (256 * 768);
    float m = -1e30f;
#pragma unroll
    for (int i = 0; i < 2; i++)
#pragma unroll
        for (int j = 0; j < 2; j++) {
            int Y = 2 * yh + i, X = 2 * xw + j;
            m = fmaxf(m, feat[((size_t)b * NT + 1 + Y * 32 + X) * EMB + c]);
        }
    out[idx] = m;
}

// ------------------------- host orchestration -------------------------------
static inline dim3 gemm_grid(int M, int N) { return dim3((N + 63) / 64, (M + 63) / 64); }

extern "C" void kernel_launch(void* const* d_in, const int* in_sizes, int n_in,
                              void* d_out, int out_size) {
    const float* x         = (const float*)d_in[0];
    const float* patch_w   = (const float*)d_in[1];
    const float* patch_b   = (const float*)d_in[2];
    const float* cls_token = (const float*)d_in[3];
    const float* pos_embed = (const float*)d_in[4];
    const float* ln1_w     = (const float*)d_in[5];
    const float* ln1_b     = (const float*)d_in[6];
    const float* qkv_w     = (const float*)d_in[7];
    const float* q_bias    = (const float*)d_in[8];
    const float* v_bias    = (const float*)d_in[9];
    const float* rel_tab   = (const float*)d_in[10];
    const float* proj_w    = (const float*)d_in[11];
    const float* proj_b    = (const float*)d_in[12];
    const float* ln2_w     = (const float*)d_in[13];
    const float* ln2_b     = (const float*)d_in[14];
    const float* fc1_w     = (const float*)d_in[15];
    const float* fc1_b     = (const float*)d_in[16];
    const float* fc2_w     = (const float*)d_in[17];
    const float* fc2_b     = (const float*)d_in[18];
    const float* d1_w      = (const float*)d_in[19];
    const float* d1_b      = (const float*)d_in[20];
    const float* bn_w      = (const float*)d_in[21];
    const float* bn_b      = (const float*)d_in[22];
    const float* bn_mean   = (const float*)d_in[23];
    const float* bn_var    = (const float*)d_in[24];
    const float* d2_w      = (const float*)d_in[25];
    const float* d2_b      = (const float*)d_in[26];
    const float* f2w       = (const float*)d_in[27];
    const float* f2b       = (const float*)d_in[28];
    const int*   rel_idx   = (const int*)d_in[29];

    float* out = (float*)d_out;
    float* out1 = out;
    float* out2 = out1 + (size_t)BATCH * 768 * 128 * 128;
    float* out3 = out2 + (size_t)BATCH * 768 * 64 * 64;
    float* out4 = out3 + (size_t)BATCH * 768 * 32 * 32;

    static float *pt = nullptr, *ph, *pqkv, *pattn, *po, *pmlp, *ppatch, *ptok;
    static float *pf0, *pf1, *pf2, *pf3, *py, *ptmp, *pwp, *pqb;
    if (!pt) {
        cudaGetSymbolAddress((void**)&pt, g_t);
        cudaGetSymbolAddress((void**)&ph, g_h);
        cudaGetSymbolAddress((void**)&pqkv, g_qkv);
        cudaGetSymbolAddress((void**)&pattn, g_attn);
        cudaGetSymbolAddress((void**)&po, g_o);
        cudaGetSymbolAddress((void**)&pmlp, g_mlp);
        cudaGetSymbolAddress((void**)&ppatch, g_patch);
        cudaGetSymbolAddress((void**)&ptok, g_tok);
        cudaGetSymbolAddress((void**)&pf0, g_feat0);
        cudaGetSymbolAddress((void**)&pf1, g_feat1);
        cudaGetSymbolAddress((void**)&pf2, g_feat2);
        cudaGetSymbolAddress((void**)&pf3, g_feat3);
        cudaGetSymbolAddress((void**)&py, g_y);
        cudaGetSymbolAddress((void**)&ptmp, g_tmp);
        cudaGetSymbolAddress((void**)&pwp, g_wpack);
        cudaGetSymbolAddress((void**)&pqb, g_qkvbias);
    }

    const int TOKELEMS = BATCH * NT * EMB;

    // ---- patch embed ----
    patchify_kernel<<<(BATCH * 1024 * EMB + 255) / 256, 256>>>(x, ppatch);
    gemm_nt<<<gemm_grid(BATCH * 1024, EMB), 256>>>(ppatch, patch_w, patch_b, nullptr,
                                                   ptok, BATCH * 1024, EMB, EMB, 0);
    assemble_kernel<<<(TOKELEMS + 255) / 256, 256>>>(ptok, cls_token, pos_embed, pt);

    const int M = BATCH * NT;  // 2050

    // ---- transformer layers ----
    for (int l = 0; l < 12; l++) {
        ln_kernel<<<M, 256>>>(pt, ln1_w + l * EMB, ln1_b + l * EMB, ph);
        biaspack_kernel<<<(3 * EMB + 255) / 256, 256>>>(q_bias + l * EMB, v_bias + l * EMB, pqb);
        gemm_nt<<<gemm_grid(M, 3 * EMB), 256>>>(ph, qkv_w + (size_t)l * 3 * EMB * EMB,
                                                pqb, nullptr, pqkv, M, 3 * EMB, EMB, 0);
        {
            dim3 g((NT + 31) / 32, (NT + 31) / 32, BATCH * HEADS);
            qk_kernel<<<g, 256>>>(pqkv, rel_tab + (size_t)l * NREL * HEADS, rel_idx, pattn);
        }
        softmax_kernel<<<BATCH * HEADS * NT, 256>>>(pattn);
        {
            dim3 g((NT + 31) / 32, BATCH * HEADS);
            av_kernel<<<g, 256>>>(pattn, pqkv, po);
        }
        gemm_nt<<<gemm_grid(M, EMB), 256>>>(po, proj_w + (size_t)l * EMB * EMB,
                                            proj_b + l * EMB, pt, pt, M, EMB, EMB, 0);
        ln_kernel<<<M, 256>>>(pt, ln2_w + l * EMB, ln2_b + l * EMB, ph);
        gemm_nt<<<gemm_grid(M, 4 * EMB), 256>>>(ph, fc1_w + (size_t)l * 4 * EMB * EMB,
                                                fc1_b + l * 4 * EMB, nullptr, pmlp,
                                                M, 4 * EMB, EMB, 1);
        gemm_nt<<<gemm_grid(M, EMB), 256>>>(pmlp, fc2_w + (size_t)l * EMB * 4 * EMB,
                                            fc2_b + l * EMB, pt, pt, M, EMB, 4 * EMB, 0);
        float* fdst = nullptr;
        if (l == 3) fdst = pf0;
        else if (l == 5) fdst = pf1;
        else if (l == 7) fdst = pf2;
        else if (l == 11) fdst = pf3;
        if (fdst) copy_kernel<<<(TOKELEMS + 255) / 256, 256>>>(pt, fdst, TOKELEMS);
    }

    // ---- o3: layer-7 map ----
    to_map_kernel<<<(BATCH * 768 * 1024 + 255) / 256, 256>>>(pf2, out3);
    // ---- o4: maxpool of layer-11 map ----
    maxpool_kernel<<<(BATCH * 768 * 256 + 255) / 256, 256>>>(pf3, out4);

    // ---- fpn1 stage 1: deconv d1 on layer-3 map (input = feat rows, BHWC) ----
    repack_w_kernel<<<(3072 * 768 + 255) / 256, 256>>>(d1_w, pwp);
    for (int b = 0; b < BATCH; b++)
        gemm_nt<<<gemm_grid(1024, 3072), 256>>>(pf0 + ((size_t)b * NT + 1) * EMB, pwp,
                                                nullptr, nullptr,
                                                ptmp + (size_t)b * 1024 * 3072,
                                                1024, 3072, EMB, 0);
    scatter_bhwc_kernel<<<(BATCH * 1024 * 3072 + 255) / 256, 256>>>(ptmp, d1_b, py, 32);
    bn_gelu_kernel<<<(BATCH * 64 * 64 * 768 + 255) / 256, 256>>>(py, bn_w, bn_b, bn_mean, bn_var);

    // ---- fpn1 stage 2: deconv d2 -> o1 [B,768,128,128] ----
    repack_w_kernel<<<(3072 * 768 + 255) / 256, 256>>>(d2_w, pwp);
    for (int b = 0; b < BATCH; b++)
        gemm_nt<<<gemm_grid(4096, 3072), 256>>>(py + (size_t)b * 64 * 64 * 768, pwp,
                                                nullptr, nullptr,
                                                ptmp + (size_t)b * 4096 * 3072,
                                                4096, 3072, EMB, 0);
    scatter_bchw_kernel<<<(BATCH * 4096 * 3072 + 255) / 256, 256>>>(ptmp, d2_b, out1, 64);

    // ---- o2: deconv f2_w on layer-5 map -> [B,768,64,64] ----
    repack_w_kernel<<<(3072 * 768 + 255) / 256, 256>>>(f2w, pwp);
    for (int b = 0; b < BATCH; b++)
        gemm_nt<<<gemm_grid(1024, 3072), 256>>>(pf1 + ((size_t)b * NT + 1) * EMB, pwp,
                                                nullptr, nullptr,
                                                ptmp + (size_t)b * 1024 * 3072,
                                                1024, 3072, EMB, 0);
    scatter_bchw_kernel<<<(BATCH * 1024 * 3072 + 255) / 256, 256>>>(ptmp, f2b, out2, 32);

    (void)in_sizes; (void)n_in; (void)out_size;
}

// round 3
// speedup vs baseline: 1.8621x; 1.8621x over previous
#include <cuda_runtime.h>
#include <cuda_bf16.h>
#include <math.h>
#include <stdint.h>

#define NT    1025
#define EMB   768
#define BATCH 2
#define HEADS 12
#define NREL  3972

// ------------------------- device scratch (no allocs allowed) ---------------
__device__ float g_t[BATCH * NT * EMB];
__device__ float g_h[BATCH * NT * EMB];
__device__ float g_qkv[BATCH * NT * 3 * EMB];
__device__ float g_attn[(size_t)BATCH * HEADS * NT * NT];
__device__ float g_o[BATCH * NT * EMB];
__device__ float g_mlp[BATCH * NT * 4 * EMB];
__device__ float g_patch[BATCH * 1024 * EMB];
__device__ float g_tok[BATCH * 1024 * EMB];
__device__ float g_feat0[BATCH * NT * EMB];
__device__ float g_feat1[BATCH * NT * EMB];
__device__ float g_feat2[BATCH * NT * EMB];
__device__ float g_feat3[BATCH * NT * EMB];
__device__ float g_y[BATCH * 64 * 64 * EMB];
__device__ float g_tmp[(size_t)BATCH * 4096 * 3072];
__device__ float g_wpack[3072 * 768];
__device__ float g_qkvbias[3 * EMB];
// bf16 packed operand buffers (split hi/lo, 3 sections along K)
__device__ __nv_bfloat16 g_pa[80294400];   // A operands (max: P pack 24*1025*3264)
__device__ __nv_bfloat16 g_pb[7500000];    // B operands (max: fc weights 7.08M)

__device__ __forceinline__ float gelu_exact(float x) {
    return 0.5f * x * (1.0f + erff(x * 0.70710678118654752f));
}

__device__ __forceinline__ uint32_t smem_u32(const void* p) {
    uint32_t a;
    asm("{ .reg .u64 t; cvta.to.shared.u64 t, %1; cvt.u32.u64 %0, t; }" : "=r"(a) : "l"(p));
    return a;
}

#define LDSM_X4(r0, r1, r2, r3, addr) \
    asm volatile("ldmatrix.sync.aligned.m8n8.x4.shared.b16 {%0,%1,%2,%3}, [%4];" \
                 : "=r"(r0), "=r"(r1), "=r"(r2), "=r"(r3) : "r"(addr))

#define MMA16816(d, a0, a1, a2, a3, b0, b1) \
    asm volatile("mma.sync.aligned.m16n8k16.row.col.f32.bf16.bf16.f32 " \
                 "{%0,%1,%2,%3}, {%4,%5,%6,%7}, {%8,%9}, {%0,%1,%2,%3};" \
                 : "+f"((d)[0]), "+f"((d)[1]), "+f"((d)[2]), "+f"((d)[3]) \
                 : "r"(a0), "r"(a1), "r"(a2), "r"(a3), "r"(b0), "r"(b1))

// ========================= split-bf16 pack kernels ==========================
// A sections: [hi | lo | hi]   B sections: [hi | hi | lo]
// sum of products = hi*hi + lo*hi + hi*lo  (~2^-18 relative error)
__global__ void packA_kernel(const float* __restrict__ in, __nv_bfloat16* __restrict__ out,
                             int M, int K, int Kp, size_t irs, size_t ics,
                             size_t ibs0, size_t ibs1, int nh, size_t obs, float scale) {
    int idx = blockIdx.x * 256 + threadIdx.x;
    int z = blockIdx.y;
    if (idx >= M * Kp) return;
    int k = idx % Kp, m = idx / Kp;
    const float* src = in + (size_t)(z / nh) * ibs0 + (size_t)(z % nh) * ibs1;
    float v = (k < K) ? src[(size_t)m * irs + (size_t)k * ics] * scale : 0.f;
    __nv_bfloat16 hi = __float2bfloat16(v);
    __nv_bfloat16 lo = __float2bfloat16(v - __bfloat162float(hi));
    __nv_bfloat16* o = out + (size_t)z * obs + (size_t)m * (3 * (size_t)Kp);
    o[k] = hi; o[Kp + k] = lo; o[2 * Kp + k] = hi;
}
__global__ void packB_kernel(const float* __restrict__ in, __nv_bfloat16* __restrict__ out,
                             int M, int K, int Kp, size_t irs, size_t ics,
                             size_t ibs0, size_t ibs1, int nh, size_t obs, float scale) {
    int idx = blockIdx.x * 256 + threadIdx.x;
    int z = blockIdx.y;
    if (idx >= M * Kp) return;
    int k = idx % Kp, m = idx / Kp;
    const float* src = in + (size_t)(z / nh) * ibs0 + (size_t)(z % nh) * ibs1;
    float v = (k < K) ? src[(size_t)m * irs + (size_t)k * ics] * scale : 0.f;
    __nv_bfloat16 hi = __float2bfloat16(v);
    __nv_bfloat16 lo = __float2bfloat16(v - __bfloat162float(hi));
    __nv_bfloat16* o = out + (size_t)z * obs + (size_t)m * (3 * (size_t)Kp);
    o[k] = hi; o[Kp + k] = hi; o[2 * Kp + k] = lo;
}

// ========================= HMMA GEMM (mma.sync bf16) ========================
// C[z][m][n] = sum_k A'[z][m][k] * B'[z][n][k]  (both K-major bf16, fp32 acc)
// Block tile 128 x BN, 8 warps (2x4), warp tile 64 x BN/4, BK=32.
template <int BN>
__global__ void __launch_bounds__(256) hgemm(
    const __nv_bfloat16* __restrict__ A, const __nv_bfloat16* __restrict__ B,
    float* __restrict__ C, const float* __restrict__ bias, const float* __restrict__ resid,
    int M, int Nreal, int Ktot, size_t lda, size_t ldb, size_t Abs, size_t Bbs,
    size_t ldc, size_t cs0, size_t cs1, int nh, int do_gelu,
    const float* __restrict__ relt, const int* __restrict__ relidx) {
    constexpr int WTN = BN / 4;        // warp n extent (32 or 16)
    constexpr int NT8 = WTN / 8;       // n8 tiles per warp (4 or 2)
    constexpr int NB4 = BN / 64;       // B uint4 loads per thread (2 or 1)
    __shared__ __nv_bfloat16 sA[128][40];
    __shared__ __nv_bfloat16 sB[BN][40];

    int tid = threadIdx.x;
    int wid = tid >> 5, lane = tid & 31;
    int warp_m = wid >> 2, warp_n = wid & 3;
    int m0 = blockIdx.y * 128, n0 = blockIdx.x * BN;
    int z = blockIdx.z;

    const __nv_bfloat16* Az = A + (size_t)z * Abs;
    const __nv_bfloat16* Bz = B + (size_t)z * Bbs;

    float acc[4][NT8][4];
#pragma unroll
    for (int i = 0; i < 4; i++)
#pragma unroll
        for (int j = 0; j < NT8; j++)
#pragma unroll
            for (int e = 0; e < 4; e++) acc[i][j][e] = 0.f;

    const uint4 zero4 = make_uint4(0, 0, 0, 0);
    uint4 ra[2], rb[NB4];
    int nk = Ktot >> 5;

    // prefetch chunk 0
    {
#pragma unroll
        for (int i = 0; i < 2; i++) {
            int idx = tid + i * 256, row = idx >> 2, cg = idx & 3;
            ra[i] = (m0 + row < M) ? *(const uint4*)(Az + (size_t)(m0 + row) * lda + cg * 8) : zero4;
        }
#pragma unroll
        for (int i = 0; i < NB4; i++) {
            int idx = tid + i * 256, row = idx >> 2, cg = idx & 3;
            rb[i] = (n0 + row < Nreal) ? *(const uint4*)(Bz + (size_t)(n0 + row) * ldb + cg * 8) : zero4;
        }
    }

    for (int c = 0; c < nk; c++) {
        __syncthreads();
#pragma unroll
        for (int i = 0; i < 2; i++) {
            int idx = tid + i * 256, row = idx >> 2, cg = idx & 3;
            *(uint4*)&sA[row][cg * 8] = ra[i];
        }
#pragma unroll
        for (int i = 0; i < NB4; i++) {
            int idx = tid + i * 256, row = idx >> 2, cg = idx & 3;
            *(uint4*)&sB[row][cg * 8] = rb[i];
        }
        __syncthreads();
        if (c + 1 < nk) {
            int koff = (c + 1) * 32;
#pragma unroll
            for (int i = 0; i < 2; i++) {
                int idx = tid + i * 256, row = idx >> 2, cg = idx & 3;
                ra[i] = (m0 + row < M) ? *(const uint4*)(Az + (size_t)(m0 + row) * lda + koff + cg * 8) : zero4;
            }
#pragma unroll
            for (int i = 0; i < NB4; i++) {
                int idx = tid + i * 256, row = idx >> 2, cg = idx & 3;
                rb[i] = (n0 + row < Nreal) ? *(const uint4*)(Bz + (size_t)(n0 + row) * ldb + koff + cg * 8) : zero4;
            }
        }
#pragma unroll
        for (int kk = 0; kk < 2; kk++) {
            uint32_t af[4][4];
#pragma unroll
            for (int mt = 0; mt < 4; mt++) {
                uint32_t addr = smem_u32(&sA[warp_m * 64 + mt * 16 + (lane & 15)]
                                           [kk * 16 + (lane >> 4) * 8]);
                LDSM_X4(af[mt][0], af[mt][1], af[mt][2], af[mt][3], addr);
            }
            uint32_t bf[NT8][2];
#pragma unroll
            for (int p = 0; p < NT8 / 2; p++) {
                uint32_t addr = smem_u32(&sB[warp_n * WTN + p * 16 + ((lane >> 4) << 3) + (lane & 7)]
                                           [kk * 16 + ((lane >> 3) & 1) * 8]);
                LDSM_X4(bf[2 * p][0], bf[2 * p][1], bf[2 * p + 1][0], bf[2 * p + 1][1], addr);
            }
#pragma unroll
            for (int mt = 0; mt < 4; mt++)
#pragma unroll
                for (int nt = 0; nt < NT8; nt++)
                    MMA16816(acc[mt][nt], af[mt][0], af[mt][1], af[mt][2], af[mt][3],
                             bf[nt][0], bf[nt][1]);
        }
    }

    // epilogue
    int h = z % HEADS;
    size_t cbase = (size_t)(z / nh) * cs0 + (size_t)(z % nh) * cs1;
    int mrow = lane >> 2, ncol = (lane & 3) * 2;
#pragma unroll
    for (int mt = 0; mt < 4; mt++) {
#pragma unroll
        for (int half = 0; half < 2; half++) {
            int row = m0 + warp_m * 64 + mt * 16 + mrow + half * 8;
            if (row >= M) continue;
#pragma unroll
            for (int nt = 0; nt < NT8; nt++) {
#pragma unroll
                for (int e = 0; e < 2; e++) {
                    int col = n0 + warp_n * WTN + nt * 8 + ncol + e;
                    if (col >= Nreal) continue;
                    float v = acc[mt][nt][half * 2 + e];
                    if (bias) v += bias[col];
                    if (relidx) v += relt[(size_t)relidx[(size_t)row * NT + col] * HEADS + h];
                    size_t off = cbase + (size_t)row * ldc + col;
                    if (resid) v += resid[off];
                    if (do_gelu) v = gelu_exact(v);
                    C[off] = v;
                }
            }
        }
    }
}

// ------------------------- patchify: x[B,3,512,512] -> A[B*1024, 768] -------
__global__ void patchify_kernel(const float* __restrict__ x, float* __restrict__ A) {
    int idx = blockIdx.x * 256 + threadIdx.x;
    if (idx >= BATCH * 1024 * EMB) return;
    int col = idx % EMB;
    int m = idx / EMB;
    int b = m / 1024, g = m % 1024;
    int gh = g / 32, gw = g % 32;
    int c = col / 256, rem = col % 256;
    int i = rem / 16, j = rem % 16;
    A[idx] = x[(((size_t)(b * 3 + c) * 512) + gh * 16 + i) * 512 + gw * 16 + j];
}

__global__ void assemble_kernel(const float* __restrict__ tok, const float* __restrict__ cls,
                                const float* __restrict__ pos, float* __restrict__ t) {
    int idx = blockIdx.x * 256 + threadIdx.x;
    if (idx >= BATCH * NT * EMB) return;
    int d = idx % EMB;
    int n = (idx / EMB) % NT;
    int b = idx / (EMB * NT);
    float v = (n == 0) ? cls[d] : tok[((size_t)b * 1024 + (n - 1)) * EMB + d];
    t[idx] = v + pos[n * EMB + d];
}

// ------------------------- LayerNorm over last dim 768 ----------------------
__global__ void ln_kernel(const float* __restrict__ x, const float* __restrict__ w,
                          const float* __restrict__ b, float* __restrict__ out) {
    int r = blockIdx.x;
    const float* xr = x + (size_t)r * EMB;
    __shared__ float red[256];
    int tid = threadIdx.x;
    float s = 0.f;
    for (int i = tid; i < EMB; i += 256) s += xr[i];
    red[tid] = s; __syncthreads();
    for (int st = 128; st > 0; st >>= 1) { if (tid < st) red[tid] += red[tid + st]; __syncthreads(); }
    float mean = red[0] * (1.0f / EMB);
    __syncthreads();
    float s2 = 0.f;
    for (int i = tid; i < EMB; i += 256) { float d = xr[i] - mean; s2 += d * d; }
    red[tid] = s2; __syncthreads();
    for (int st = 128; st > 0; st >>= 1) { if (tid < st) red[tid] += red[tid + st]; __syncthreads(); }
    float inv = rsqrtf(red[0] * (1.0f / EMB) + 1e-6f);
    for (int i = tid; i < EMB; i += 256)
        out[(size_t)r * EMB + i] = (xr[i] - mean) * inv * w[i] + b[i];
}

__global__ void biaspack_kernel(const float* __restrict__ qb, const float* __restrict__ vb,
                                float* __restrict__ out) {
    int i = blockIdx.x * 256 + threadIdx.x;
    if (i >= 3 * EMB) return;
    out[i] = (i < EMB) ? qb[i] : ((i < 2 * EMB) ? 0.f : vb[i - 2 * EMB]);
}

// ------------------------- softmax per row (length 1025) --------------------
__global__ void softmax_kernel(float* __restrict__ attn) {
    size_t row = blockIdx.x;
    float* p = attn + row * NT;
    __shared__ float red[256];
    int tid = threadIdx.x;
    float mx = -1e30f;
    for (int i = tid; i < NT; i += 256) mx = fmaxf(mx, p[i]);
    red[tid] = mx; __syncthreads();
    for (int st = 128; st > 0; st >>= 1) { if (tid < st) red[tid] = fmaxf(red[tid], red[tid + st]); __syncthreads(); }
    mx = red[0];
    __syncthreads();
    float s = 0.f;
    for (int i = tid; i < NT; i += 256) { float e = __expf(p[i] - mx); p[i] = e; s += e; }
    red[tid] = s; __syncthreads();
    for (int st = 128; st > 0; st >>= 1) { if (tid < st) red[tid] += red[tid + st]; __syncthreads(); }
    float inv = 1.0f / red[0];
    for (int i = tid; i < NT; i += 256) p[i] *= inv;
}

__global__ void copy_kernel(const float* __restrict__ src, float* __restrict__ dst, int n) {
    int i = blockIdx.x * 256 + threadIdx.x;
    if (i < n) dst[i] = src[i];
}

// repack deconv weight [Cin=768, Cout=768, 2, 2] -> wpack[(ij*768+d)][c]
__global__ void repack_w_kernel(const float* __restrict__ w, float* __restrict__ wp) {
    int idx = blockIdx.x * 256 + threadIdx.x;
    if (idx >= 3072 * 768) return;
    int c = idx % 768, n = idx / 768;
    int ij = n / 768, d = n % 768;
    wp[idx] = w[(size_t)c * 3072 + d * 4 + ij];
}

__global__ void scatter_bhwc_kernel(const float* __restrict__ tmp, const float* __restrict__ bias,
                                    float* __restrict__ y, int HW) {
    int total = BATCH * HW * HW * 4 * 768;
    int idx = blockIdx.x * 256 + threadIdx.x;
    if (idx >= total) return;
    int d = idx % 768;
    int ij = (idx / 768) % 4;
    int p = (idx / 3072) % (HW * HW);
    int b = idx / (3072 * HW * HW);
    int h = p / HW, w = p % HW, i = ij / 2, j = ij % 2;
    int W2 = 2 * HW;
    y[(((size_t)b * W2 + 2 * h + i) * W2 + (2 * w + j)) * 768 + d] = tmp[idx] + bias[d];
}

__global__ void scatter_bchw_kernel(const float* __restrict__ tmp, const float* __restrict__ bias,
                                    float* __restrict__ out, int HW) {
    int total = BATCH * HW * HW * 4 * 768;
    int idx = blockIdx.x * 256 + threadIdx.x;
    if (idx >= total) return;
    int d = idx % 768;
    int ij = (idx / 768) % 4;
    int p = (idx / 3072) % (HW * HW);
    int b = idx / (3072 * HW * HW);
    int h = p / HW, w = p % HW, i = ij / 2, j = ij % 2;
    int W2 = 2 * HW;
    out[(((size_t)b * 768 + d) * W2 + 2 * h + i) * W2 + (2 * w + j)] = tmp[idx] + bias[d];
}

__global__ void bn_gelu_kernel(float* __restrict__ y, const float* __restrict__ w,
                               const float* __restrict__ b, const float* __restrict__ mean,
                               const float* __restrict__ var) {
    int idx = blockIdx.x * 256 + threadIdx.x;
    if (idx >= BATCH * 64 * 64 * 768) return;
    int c = idx % 768;
    float v = y[idx];
    v = (v - mean[c]) * rsqrtf(var[c] + 1e-5f) * w[c] + b[c];
    y[idx] = gelu_exact(v);
}

__global__ void to_map_kernel(const float* __restrict__ feat, float* __restrict__ out) {
    int idx = blockIdx.x * 256 + threadIdx.x;
    if (idx >= BATCH * 768 * 32 * 32) return;
    int xw = idx % 32;
    int yh = (idx / 32) % 32;
    int c = (idx / 1024) % 768;
    int b = idx / (1024 * 768);
    out[idx] = feat[((size_t)b * NT + 1 + yh * 32 + xw) * EMB + c];
}

__global__ void maxpool_kernel(const float* __restrict__ feat, float* __restrict__ out) {
    int idx = blockIdx.x * 256 + threadIdx.x;
    if (idx >= BATCH * 768 * 16 * 16) return;
    int xw = idx % 16;
    int yh = (idx / 16) % 16;
    int c = (idx / 256) % 768;
    int b = idx / (256 * 768);
    float m = -1e30f;
#pragma unroll
    for (int i = 0; i < 2; i++)
#pragma unroll
        for (int j = 0; j < 2; j++) {
            int Y = 2 * yh + i, X = 2 * xw + j;
            m = fmaxf(m, feat[((size_t)b * NT + 1 + Y * 32 + X) * EMB + c]);
        }
    out[idx] = m;
}

// ------------------------- host helpers -------------------------------------
static void packA(const float* in, __nv_bfloat16* out, int M, int K, int Kp,
                  size_t irs, size_t ics, size_t ibs0, size_t ibs1, int nh,
                  size_t obs, float scale, int nz) {
    dim3 g((M * Kp + 255) / 256, nz);
    packA_kernel<<<g, 256>>>(in, out, M, K, Kp, irs, ics, ibs0, ibs1, nh, obs, scale);
}
static void packB(const float* in, __nv_bfloat16* out, int M, int K, int Kp,
                  size_t irs, size_t ics, size_t ibs0, size_t ibs1, int nh,
                  size_t obs, int nz) {
    dim3 g((M * Kp + 255) / 256, nz);
    packB_kernel<<<g, 256>>>(in, out, M, K, Kp, irs, ics, ibs0, ibs1, nh, obs, 1.0f);
}
static void gemm128(const __nv_bfloat16* A, const __nv_bfloat16* B, float* C,
                    const float* bias, const float* resid, int M, int N, int Ktot,
                    size_t lda, size_t ldb, size_t Abs, size_t Bbs, size_t ldc,
                    size_t cs0, size_t cs1, int nh, int gelu,
                    const float* relt, const int* relidx, int nz) {
    dim3 g((N + 127) / 128, (M + 127) / 128, nz);
    hgemm<128><<<g, 256>>>(A, B, C, bias, resid, M, N, Ktot, lda, ldb, Abs, Bbs,
                           ldc, cs0, cs1, nh, gelu, relt, relidx);
}
static void gemm64(const __nv_bfloat16* A, const __nv_bfloat16* B, float* C,
                   int M, int N, int Ktot, size_t lda, size_t ldb, size_t Abs, size_t Bbs,
                   size_t ldc, size_t cs0, size_t cs1, int nh, int nz) {
    dim3 g((N + 63) / 64, (M + 127) / 128, nz);
    hgemm<64><<<g, 256>>>(A, B, C, nullptr, nullptr, M, N, Ktot, lda, ldb, Abs, Bbs,
                          ldc, cs0, cs1, nh, 0, nullptr, nullptr);
}

extern "C" void kernel_launch(void* const* d_in, const int* in_sizes, int n_in,
                              void* d_out, int out_size) {
    const float* x         = (const float*)d_in[0];
    const float* patch_w   = (const float*)d_in[1];
    const float* patch_b   = (const float*)d_in[2];
    const float* cls_token = (const float*)d_in[3];
    const float* pos_embed = (const float*)d_in[4];
    const float* ln1_w     = (const float*)d_in[5];
    const float* ln1_b     = (const float*)d_in[6];
    const float* qkv_w     = (const float*)d_in[7];
    const float* q_bias    = (const float*)d_in[8];
    const float* v_bias    = (const float*)d_in[9];
    const float* rel_tab   = (const float*)d_in[10];
    const float* proj_w    = (const float*)d_in[11];
    const float* proj_b    = (const float*)d_in[12];
    const float* ln2_w     = (const float*)d_in[13];
    const float* ln2_b     = (const float*)d_in[14];
    const float* fc1_w     = (const float*)d_in[15];
    const float* fc1_b     = (const float*)d_in[16];
    const float* fc2_w     = (const float*)d_in[17];
    const float* fc2_b     = (const float*)d_in[18];
    const float* d1_w      = (const float*)d_in[19];
    const float* d1_b      = (const float*)d_in[20];
    const float* bn_w      = (const float*)d_in[21];
    const float* bn_b      = (const float*)d_in[22];
    const float* bn_mean   = (const float*)d_in[23];
    const float* bn_var    = (const float*)d_in[24];
    const float* d2_w      = (const float*)d_in[25];
    const float* d2_b      = (const float*)d_in[26];
    const float* f2w       = (const float*)d_in[27];
    const float* f2b       = (const float*)d_in[28];
    const int*   rel_idx   = (const int*)d_in[29];

    float* out = (float*)d_out;
    float* out1 = out;
    float* out2 = out1 + (size_t)BATCH * 768 * 128 * 128;
    float* out3 = out2 + (size_t)BATCH * 768 * 64 * 64;
    float* out4 = out3 + (size_t)BATCH * 768 * 32 * 32;

    static float *pt = nullptr, *ph, *pqkv, *pattn, *po, *pmlp, *ppatch, *ptok;
    static float *pf0, *pf1, *pf2, *pf3, *py, *ptmp, *pwp, *pqb;
    static __nv_bfloat16 *pa, *pb;
    if (!pt) {
        cudaGetSymbolAddress((void**)&pt, g_t);
        cudaGetSymbolAddress((void**)&ph, g_h);
        cudaGetSymbolAddress((void**)&pqkv, g_qkv);
        cudaGetSymbolAddress((void**)&pattn, g_attn);
        cudaGetSymbolAddress((void**)&po, g_o);
        cudaGetSymbolAddress((void**)&pmlp, g_mlp);
        cudaGetSymbolAddress((void**)&ppatch, g_patch);
        cudaGetSymbolAddress((void**)&ptok, g_tok);
        cudaGetSymbolAddress((void**)&pf0, g_feat0);
        cudaGetSymbolAddress((void**)&pf1, g_feat1);
        cudaGetSymbolAddress((void**)&pf2, g_feat2);
        cudaGetSymbolAddress((void**)&pf3, g_feat3);
        cudaGetSymbolAddress((void**)&py, g_y);
        cudaGetSymbolAddress((void**)&ptmp, g_tmp);
        cudaGetSymbolAddress((void**)&pwp, g_wpack);
        cudaGetSymbolAddress((void**)&pqb, g_qkvbias);
        cudaGetSymbolAddress((void**)&pa, g_pa);
        cudaGetSymbolAddress((void**)&pb, g_pb);
    }

    const int TOKELEMS = BATCH * NT * EMB;
    const int M = BATCH * NT;  // 2050

    // ---- patch embed (tensor-core GEMM) ----
    patchify_kernel<<<(BATCH * 1024 * EMB + 255) / 256, 256>>>(x, ppatch);
    packA(ppatch, pa, 2048, 768, 768, 768, 1, 0, 0, 1, 0, 1.0f, 1);
    packB(patch_w, pb, 768, 768, 768, 768, 1, 0, 0, 1, 0, 1);
    gemm128(pa, pb, ptok, patch_b, nullptr, 2048, 768, 2304, 2304, 2304, 0, 0,
            768, 0, 0, 1, 0, nullptr, nullptr, 1);
    assemble_kernel<<<(TOKELEMS + 255) / 256, 256>>>(ptok, cls_token, pos_embed, pt);

    // ---- transformer layers ----
    for (int l = 0; l < 12; l++) {
        // LN1 + QKV
        ln_kernel<<<M, 256>>>(pt, ln1_w + l * EMB, ln1_b + l * EMB, ph);
        biaspack_kernel<<<(3 * EMB + 255) / 256, 256>>>(q_bias + l * EMB, v_bias + l * EMB, pqb);
        packA(ph, pa, M, 768, 768, 768, 1, 0, 0, 1, 0, 1.0f, 1);
        packB(qkv_w + (size_t)l * 2304 * 768, pb, 2304, 768, 768, 768, 1, 0, 0, 1, 0, 1);
        gemm128(pa, pb, pqkv, pqb, nullptr, M, 2304, 2304, 2304, 2304, 0, 0,
                2304, 0, 0, 1, 0, nullptr, nullptr, 1);
        // QK^T (scale folded into Q pack) + rel-bias epilogue
        packA(pqkv, pa, NT, 64, 64, 2304, 1, (size_t)NT * 2304, 64, HEADS,
              (size_t)NT * 192, 0.125f, BATCH * HEADS);
        packB(pqkv + 768, pb, NT, 64, 64, 2304, 1, (size_t)NT * 2304, 64, HEADS,
              (size_t)NT * 192, BATCH * HEADS);
        gemm128(pa, pb, pattn, nullptr, nullptr, NT, NT, 192, 192, 192,
                (size_t)NT * 192, (size_t)NT * 192, NT, (size_t)NT * NT, 0, 1, 0,
                rel_tab + (size_t)l * NREL * HEADS, rel_idx, BATCH * HEADS);
        softmax_kernel<<<BATCH * HEADS * NT, 256>>>(pattn);
        // AV
        packA(pattn, pa, NT, NT, 1088, NT, 1, (size_t)NT * NT, 0, 1,
              (size_t)NT * 3264, 1.0f, BATCH * HEADS);
        packB(pqkv + 1536, pb, 64, NT, 1088, 1, 2304, (size_t)NT * 2304, 64, HEADS,
              (size_t)64 * 3264, BATCH * HEADS);
        gemm64(pa, pb, po, NT, 64, 3264, 3264, 3264, (size_t)NT * 3264, (size_t)64 * 3264,
               768, (size_t)NT * 768, 64, HEADS, BATCH * HEADS);
        // proj (+residual)
        packA(po, pa, M, 768, 768, 768, 1, 0, 0, 1, 0, 1.0f, 1);
        packB(proj_w + (size_t)l * 768 * 768, pb, 768, 768, 768, 768, 1, 0, 0, 1, 0, 1);
        gemm128(pa, pb, pt, proj_b + l * EMB, pt, M, 768, 2304, 2304, 2304, 0, 0,
                768, 0, 0, 1, 0, nullptr, nullptr, 1);
        // MLP
        ln_kernel<<<M, 256>>>(pt, ln2_w + l * EMB, ln2_b + l * EMB, ph);
        packA(ph, pa, M, 768, 768, 768, 1, 0, 0, 1, 0, 1.0f, 1);
        packB(fc1_w + (size_t)l * 3072 * 768, pb, 3072, 768, 768, 768, 1, 0, 0, 1, 0, 1);
        gemm128(pa, pb, pmlp, fc1_b + l * 4 * EMB, nullptr, M, 3072, 2304, 2304, 2304, 0, 0,
                3072, 0, 0, 1, 1, nullptr, nullptr, 1);
        packA(pmlp, pa, M, 3072, 3072, 3072, 1, 0, 0, 1, 0, 1.0f, 1);
        packB(fc2_w + (size_t)l * 768 * 3072, pb, 768, 3072, 3072, 3072, 1, 0, 0, 1, 0, 1);
        gemm128(pa, pb, pt, fc2_b + l * EMB, pt, M, 768, 9216, 9216, 9216, 0, 0,
                768, 0, 0, 1, 0, nullptr, nullptr, 1);
        float* fdst = nullptr;
        if (l == 3) fdst = pf0;
        else if (l == 5) fdst = pf1;
        else if (l == 7) fdst = pf2;
        else if (l == 11) fdst = pf3;
        if (fdst) copy_kernel<<<(TOKELEMS + 255) / 256, 256>>>(pt, fdst, TOKELEMS);
    }

    // ---- o3 / o4 ----
    to_map_kernel<<<(BATCH * 768 * 1024 + 255) / 256, 256>>>(pf2, out3);
    maxpool_kernel<<<(BATCH * 768 * 256 + 255) / 256, 256>>>(pf3, out4);

    // ---- fpn1 stage 1: deconv d1 on layer-3 map ----
    repack_w_kernel<<<(3072 * 768 + 255) / 256, 256>>>(d1_w, pwp);
    packB(pwp, pb, 3072, 768, 768, 768, 1, 0, 0, 1, 0, 1);
    packA(pf0 + 768, pa, 1024, 768, 768, 768, 1, (size_t)NT * 768, 0, 1,
          (size_t)1024 * 2304, 1.0f, BATCH);
    gemm128(pa, pb, ptmp, nullptr, nullptr, 1024, 3072, 2304, 2304, 2304,
            (size_t)1024 * 2304, 0, 3072, (size_t)1024 * 3072, 0, 1, 0,
            nullptr, nullptr, BATCH);
    scatter_bhwc_kernel<<<(BATCH * 1024 * 3072 + 255) / 256, 256>>>(ptmp, d1_b, py, 32);
    bn_gelu_kernel<<<(BATCH * 64 * 64 * 768 + 255) / 256, 256>>>(py, bn_w, bn_b, bn_mean, bn_var);

    // ---- fpn1 stage 2: deconv d2 -> o1 ----
    repack_w_kernel<<<(3072 * 768 + 255) / 256, 256>>>(d2_w, pwp);
    packB(pwp, pb, 3072, 768, 768, 768, 1, 0, 0, 1, 0, 1);
    packA(py, pa, 4096, 768, 768, 768, 1, (size_t)4096 * 768, 0, 1,
          (size_t)4096 * 2304, 1.0f, BATCH);
    gemm128(pa, pb, ptmp, nullptr, nullptr, 4096, 3072, 2304, 2304, 2304,
            (size_t)4096 * 2304, 0, 3072, (size_t)4096 * 3072, 0, 1, 0,
            nullptr, nullptr, BATCH);
    scatter_bchw_kernel<<<(BATCH * 4096 * 3072 + 255) / 256, 256>>>(ptmp, d2_b, out1, 64);

    // ---- o2: deconv f2_w on layer-5 map ----
    repack_w_kernel<<<(3072 * 768 + 255) / 256, 256>>>(f2w, pwp);
    packB(pwp, pb, 3072, 768, 768, 768, 1, 0, 0, 1, 0, 1);
    packA(pf1 + 768, pa, 1024, 768, 768, 768, 1, (size_t)NT * 768, 0, 1,
          (size_t)1024 * 2304, 1.0f, BATCH);
    gemm128(pa, pb, ptmp, nullptr, nullptr, 1024, 3072, 2304, 2304, 2304,
            (size_t)1024 * 2304, 0, 3072, (size_t)1024 * 3072, 0, 1, 0,
            nullptr, nullptr, BATCH);
    scatter_bchw_kernel<<<(BATCH * 1024 * 3072 + 255) / 256, 256>>>(ptmp, f2b, out2, 32);

    (void)in_sizes; (void)n_in; (void)out_size;
}

// round 4
// speedup vs baseline: 2.1414x; 1.1500x over previous
#include <cuda_runtime.h>
#include <cuda_bf16.h>
#include <math.h>
#include <stdint.h>

#define NT    1025
#define EMB   768
#define BATCH 2
#define HEADS 12
#define NREL  3972

// ------------------------- device scratch (no allocs allowed) ---------------
__device__ float g_t[BATCH * NT * EMB];
__device__ float g_h[BATCH * NT * EMB];
__device__ float g_qkv[BATCH * NT * 3 * EMB];
__device__ float g_attn[(size_t)BATCH * HEADS * NT * NT];
__device__ float g_o[BATCH * NT * EMB];
__device__ float g_mlp[BATCH * NT * 4 * EMB];
__device__ float g_patch[BATCH * 1024 * EMB];
__device__ float g_tok[BATCH * 1024 * EMB];
__device__ float g_feat0[BATCH * NT * EMB];
__device__ float g_feat1[BATCH * NT * EMB];
__device__ float g_feat2[BATCH * NT * EMB];
__device__ float g_feat3[BATCH * NT * EMB];
__device__ float g_y[BATCH * 64 * 64 * EMB];
__device__ float g_tmp[(size_t)BATCH * 4096 * 3072];
__device__ float g_wpack[3072 * 768];
__device__ float g_qkvbias[3 * EMB];
// bf16 packed operand buffers (split hi/lo, 3 sections along K)
__device__ __nv_bfloat16 g_pa[80294400];   // A operands (max: P pack 24*1025*3264)
__device__ __nv_bfloat16 g_pb[7500000];    // B operands (max: fc weights 7.08M)

__device__ __forceinline__ float gelu_exact(float x) {
    return 0.5f * x * (1.0f + erff(x * 0.70710678118654752f));
}

__device__ __forceinline__ uint32_t smem_u32(const void* p) {
    uint32_t a;
    asm("{ .reg .u64 t; cvta.to.shared.u64 t, %1; cvt.u32.u64 %0, t; }" : "=r"(a) : "l"(p));
    return a;
}

#define LDSM_X4(r0, r1, r2, r3, addr) \
    asm volatile("ldmatrix.sync.aligned.m8n8.x4.shared.b16 {%0,%1,%2,%3}, [%4];" \
                 : "=r"(r0), "=r"(r1), "=r"(r2), "=r"(r3) : "r"(addr))

#define MMA16816(d, a0, a1, a2, a3, b0, b1) \
    asm volatile("mma.sync.aligned.m16n8k16.row.col.f32.bf16.bf16.f32 " \
                 "{%0,%1,%2,%3}, {%4,%5,%6,%7}, {%8,%9}, {%0,%1,%2,%3};" \
                 : "+f"((d)[0]), "+f"((d)[1]), "+f"((d)[2]), "+f"((d)[3]) \
                 : "r"(a0), "r"(a1), "r"(a2), "r"(a3), "r"(b0), "r"(b1))

#define CP_ASYNC16(dst, src, sz) \
    asm volatile("cp.async.cg.shared.global [%0], [%1], 16, %2;" \
                 :: "r"(dst), "l"(src), "r"(sz))

// ========================= split-bf16 pack kernels ==========================
// A sections: [hi | lo | hi]   B sections: [hi | hi | lo]
// sum of products = hi*hi + lo*hi + hi*lo  (~2^-18 relative error)
__global__ void packA_kernel(const float* __restrict__ in, __nv_bfloat16* __restrict__ out,
                             int M, int K, int Kp, size_t irs, size_t ics,
                             size_t ibs0, size_t ibs1, int nh, size_t obs, float scale) {
    int idx = blockIdx.x * 256 + threadIdx.x;
    int z = blockIdx.y;
    if (idx >= M * Kp) return;
    int k = idx % Kp, m = idx / Kp;
    const float* src = in + (size_t)(z / nh) * ibs0 + (size_t)(z % nh) * ibs1;
    float v = (k < K) ? src[(size_t)m * irs + (size_t)k * ics] * scale : 0.f;
    __nv_bfloat16 hi = __float2bfloat16(v);
    __nv_bfloat16 lo = __float2bfloat16(v - __bfloat162float(hi));
    __nv_bfloat16* o = out + (size_t)z * obs + (size_t)m * (3 * (size_t)Kp);
    o[k] = hi; o[Kp + k] = lo; o[2 * Kp + k] = hi;
}
__global__ void packB_kernel(const float* __restrict__ in, __nv_bfloat16* __restrict__ out,
                             int M, int K, int Kp, size_t irs, size_t ics,
                             size_t ibs0, size_t ibs1, int nh, size_t obs, float scale) {
    int idx = blockIdx.x * 256 + threadIdx.x;
    int z = blockIdx.y;
    if (idx >= M * Kp) return;
    int k = idx % Kp, m = idx / Kp;
    const float* src = in + (size_t)(z / nh) * ibs0 + (size_t)(z % nh) * ibs1;
    float v = (k < K) ? src[(size_t)m * irs + (size_t)k * ics] * scale : 0.f;
    __nv_bfloat16 hi = __float2bfloat16(v);
    __nv_bfloat16 lo = __float2bfloat16(v - __bfloat162float(hi));
    __nv_bfloat16* o = out + (size_t)z * obs + (size_t)m * (3 * (size_t)Kp);
    o[k] = hi; o[Kp + k] = hi; o[2 * Kp + k] = lo;
}

// ========================= HMMA GEMM (mma.sync bf16) ========================
// C[z][m][n] = sum_k A'[z][m][k] * B'[z][n][k]  (both K-major bf16, fp32 acc)
// Block tile 128 x BN, 8 warps (2x4), warp tile 64 x BN/4, BK=32.
// cp.async double-buffered smem pipeline.
template <int BN>
__global__ void __launch_bounds__(256, 2) hgemm(
    const __nv_bfloat16* __restrict__ A, const __nv_bfloat16* __restrict__ B,
    float* __restrict__ C, const float* __restrict__ bias, const float* __restrict__ resid,
    int M, int Nreal, int Ktot, size_t lda, size_t ldb, size_t Abs, size_t Bbs,
    size_t ldc, size_t cs0, size_t cs1, int nh, int do_gelu,
    const float* __restrict__ relt, const int* __restrict__ relidx) {
    constexpr int WTN = BN / 4;        // warp n extent (32 or 16)
    constexpr int NT8 = WTN / 8;       // n8 tiles per warp (4 or 2)
    constexpr int NB4 = BN / 64;       // B uint4 loads per thread (2 or 1)
    __shared__ __nv_bfloat16 sA[2][128][40];
    __shared__ __nv_bfloat16 sB[2][BN][40];

    int tid = threadIdx.x;
    int wid = tid >> 5, lane = tid & 31;
    int warp_m = wid >> 2, warp_n = wid & 3;
    int m0 = blockIdx.y * 128, n0 = blockIdx.x * BN;
    int z = blockIdx.z;

    const __nv_bfloat16* Az = A + (size_t)z * Abs;
    const __nv_bfloat16* Bz = B + (size_t)z * Bbs;

    float acc[4][NT8][4];
#pragma unroll
    for (int i = 0; i < 4; i++)
#pragma unroll
        for (int j = 0; j < NT8; j++)
#pragma unroll
            for (int e = 0; e < 4; e++) acc[i][j][e] = 0.f;

    int nk = Ktot >> 5;
    int arow = tid >> 2, acg = tid & 3;     // 64 rows per 256/4... (row = idx>>2)

    // async-load one 32-K chunk into buffer `buf`
    auto load_chunk = [&](int c, int buf) {
#pragma unroll
        for (int i = 0; i < 2; i++) {
            int idx = tid + i * 256, row = idx >> 2, cg = idx & 3;
            uint32_t dst = smem_u32(&sA[buf][row][cg * 8]);
            const __nv_bfloat16* src = Az + (size_t)(m0 + row) * lda + c * 32 + cg * 8;
            CP_ASYNC16(dst, src, (m0 + row < M) ? 16 : 0);
        }
#pragma unroll
        for (int i = 0; i < NB4; i++) {
            int idx = tid + i * 256, row = idx >> 2, cg = idx & 3;
            uint32_t dst = smem_u32(&sB[buf][row][cg * 8]);
            const __nv_bfloat16* src = Bz + (size_t)(n0 + row) * ldb + c * 32 + cg * 8;
            CP_ASYNC16(dst, src, (n0 + row < Nreal) ? 16 : 0);
        }
        asm volatile("cp.async.commit_group;");
    };

    load_chunk(0, 0);

    for (int c = 0; c < nk; c++) {
        int buf = c & 1;
        if (c + 1 < nk) {
            load_chunk(c + 1, buf ^ 1);
            asm volatile("cp.async.wait_group 1;");
        } else {
            asm volatile("cp.async.wait_group 0;");
        }
        __syncthreads();
#pragma unroll
        for (int kk = 0; kk < 2; kk++) {
            uint32_t af[4][4];
#pragma unroll
            for (int mt = 0; mt < 4; mt++) {
                uint32_t addr = smem_u32(&sA[buf][warp_m * 64 + mt * 16 + (lane & 15)]
                                           [kk * 16 + (lane >> 4) * 8]);
                LDSM_X4(af[mt][0], af[mt][1], af[mt][2], af[mt][3], addr);
            }
            uint32_t bf[NT8][2];
#pragma unroll
            for (int p = 0; p < NT8 / 2; p++) {
                uint32_t addr = smem_u32(&sB[buf][warp_n * WTN + p * 16 + ((lane >> 4) << 3) + (lane & 7)]
                                           [kk * 16 + ((lane >> 3) & 1) * 8]);
                LDSM_X4(bf[2 * p][0], bf[2 * p][1], bf[2 * p + 1][0], bf[2 * p + 1][1], addr);
            }
#pragma unroll
            for (int mt = 0; mt < 4; mt++)
#pragma unroll
                for (int nt = 0; nt < NT8; nt++)
                    MMA16816(acc[mt][nt], af[mt][0], af[mt][1], af[mt][2], af[mt][3],
                             bf[nt][0], bf[nt][1]);
        }
        __syncthreads();
    }
    (void)arow; (void)acg;

    // epilogue
    int h = z % HEADS;
    size_t cbase = (size_t)(z / nh) * cs0 + (size_t)(z % nh) * cs1;
    int mrow = lane >> 2, ncol = (lane & 3) * 2;
#pragma unroll
    for (int mt = 0; mt < 4; mt++) {
#pragma unroll
        for (int half = 0; half < 2; half++) {
            int row = m0 + warp_m * 64 + mt * 16 + mrow + half * 8;
            if (row >= M) continue;
#pragma unroll
            for (int nt = 0; nt < NT8; nt++) {
#pragma unroll
                for (int e = 0; e < 2; e++) {
                    int col = n0 + warp_n * WTN + nt * 8 + ncol + e;
                    if (col >= Nreal) continue;
                    float v = acc[mt][nt][half * 2 + e];
                    if (bias) v += bias[col];
                    if (relidx) v += relt[(size_t)relidx[(size_t)row * NT + col] * HEADS + h];
                    size_t off = cbase + (size_t)row * ldc + col;
                    if (resid) v += resid[off];
                    if (do_gelu) v = gelu_exact(v);
                    C[off] = v;
                }
            }
        }
    }
}

// ------------------------- patchify: x[B,3,512,512] -> A[B*1024, 768] -------
__global__ void patchify_kernel(const float* __restrict__ x, float* __restrict__ A) {
    int idx = blockIdx.x * 256 + threadIdx.x;
    if (idx >= BATCH * 1024 * EMB) return;
    int col = idx % EMB;
    int m = idx / EMB;
    int b = m / 1024, g = m % 1024;
    int gh = g / 32, gw = g % 32;
    int c = col / 256, rem = col % 256;
    int i = rem / 16, j = rem % 16;
    A[idx] = x[(((size_t)(b * 3 + c) * 512) + gh * 16 + i) * 512 + gw * 16 + j];
}

__global__ void assemble_kernel(const float* __restrict__ tok, const float* __restrict__ cls,
                                const float* __restrict__ pos, float* __restrict__ t) {
    int idx = blockIdx.x * 256 + threadIdx.x;
    if (idx >= BATCH * NT * EMB) return;
    int d = idx % EMB;
    int n = (idx / EMB) % NT;
    int b = idx / (EMB * NT);
    float v = (n == 0) ? cls[d] : tok[((size_t)b * 1024 + (n - 1)) * EMB + d];
    t[idx] = v + pos[n * EMB + d];
}

// ------------------------- LayerNorm over last dim 768 ----------------------
__global__ void ln_kernel(const float* __restrict__ x, const float* __restrict__ w,
                          const float* __restrict__ b, float* __restrict__ out) {
    int r = blockIdx.x;
    const float* xr = x + (size_t)r * EMB;
    __shared__ float red[256];
    int tid = threadIdx.x;
    float s = 0.f;
    for (int i = tid; i < EMB; i += 256) s += xr[i];
    red[tid] = s; __syncthreads();
    for (int st = 128; st > 0; st >>= 1) { if (tid < st) red[tid] += red[tid + st]; __syncthreads(); }
    float mean = red[0] * (1.0f / EMB);
    __syncthreads();
    float s2 = 0.f;
    for (int i = tid; i < EMB; i += 256) { float d = xr[i] - mean; s2 += d * d; }
    red[tid] = s2; __syncthreads();
    for (int st = 128; st > 0; st >>= 1) { if (tid < st) red[tid] += red[tid + st]; __syncthreads(); }
    float inv = rsqrtf(red[0] * (1.0f / EMB) + 1e-6f);
    for (int i = tid; i < EMB; i += 256)
        out[(size_t)r * EMB + i] = (xr[i] - mean) * inv * w[i] + b[i];
}

__global__ void biaspack_kernel(const float* __restrict__ qb, const float* __restrict__ vb,
                                float* __restrict__ out) {
    int i = blockIdx.x * 256 + threadIdx.x;
    if (i >= 3 * EMB) return;
    out[i] = (i < EMB) ? qb[i] : ((i < 2 * EMB) ? 0.f : vb[i - 2 * EMB]);
}

// ------------- fused softmax + split-bf16 P pack (per row, len 1025) --------
// writes packed P directly in AV-A layout: sections [hi | lo | hi] of width 1088
__global__ void softmax_pack_kernel(const float* __restrict__ attn,
                                    __nv_bfloat16* __restrict__ out) {
    size_t row = blockIdx.x;          // z*NT + m
    const float* p = attn + row * NT;
    size_t z = row / NT, m = row % NT;
    __nv_bfloat16* o = out + z * ((size_t)NT * 3264) + m * 3264;
    __shared__ float red[256];
    int tid = threadIdx.x;
    float mx = -1e30f;
    for (int i = tid; i < NT; i += 256) mx = fmaxf(mx, p[i]);
    red[tid] = mx; __syncthreads();
    for (int st = 128; st > 0; st >>= 1) { if (tid < st) red[tid] = fmaxf(red[tid], red[tid + st]); __syncthreads(); }
    mx = red[0];
    __syncthreads();
    float s = 0.f;
    for (int i = tid; i < NT; i += 256) s += __expf(p[i] - mx);
    red[tid] = s; __syncthreads();
    for (int st = 128; st > 0; st >>= 1) { if (tid < st) red[tid] += red[tid + st]; __syncthreads(); }
    float inv = 1.0f / red[0];
    for (int i = tid; i < 1088; i += 256) {
        float e = (i < NT) ? __expf(p[i] - mx) * inv : 0.f;
        __nv_bfloat16 hi = __float2bfloat16(e);
        __nv_bfloat16 lo = __float2bfloat16(e - __bfloat162float(hi));
        o[i] = hi; o[1088 + i] = lo; o[2176 + i] = hi;
    }
}

__global__ void copy_kernel(const float* __restrict__ src, float* __restrict__ dst, int n) {
    int i = blockIdx.x * 256 + threadIdx.x;
    if (i < n) dst[i] = src[i];
}

// repack deconv weight [Cin=768, Cout=768, 2, 2] -> wpack[(ij*768+d)][c]
__global__ void repack_w_kernel(const float* __restrict__ w, float* __restrict__ wp) {
    int idx = blockIdx.x * 256 + threadIdx.x;
    if (idx >= 3072 * 768) return;
    int c = idx % 768, n = idx / 768;
    int ij = n / 768, d = n % 768;
    wp[idx] = w[(size_t)c * 3072 + d * 4 + ij];
}

__global__ void scatter_bhwc_kernel(const float* __restrict__ tmp, const float* __restrict__ bias,
                                    float* __restrict__ y, int HW) {
    int total = BATCH * HW * HW * 4 * 768;
    int idx = blockIdx.x * 256 + threadIdx.x;
    if (idx >= total) return;
    int d = idx % 768;
    int ij = (idx / 768) % 4;
    int p = (idx / 3072) % (HW * HW);
    int b = idx / (3072 * HW * HW);
    int h = p / HW, w = p % HW, i = ij / 2, j = ij % 2;
    int W2 = 2 * HW;
    y[(((size_t)b * W2 + 2 * h + i) * W2 + (2 * w + j)) * 768 + d] = tmp[idx] + bias[d];
}

__global__ void scatter_bchw_kernel(const float* __restrict__ tmp, const float* __restrict__ bias,
                                    float* __restrict__ out, int HW) {
    int total = BATCH * HW * HW * 4 * 768;
    int idx = blockIdx.x * 256 + threadIdx.x;
    if (idx >= total) return;
    int d = idx % 768;
    int ij = (idx / 768) % 4;
    int p = (idx / 3072) % (HW * HW);
    int b = idx / (3072 * HW * HW);
    int h = p / HW, w = p % HW, i = ij / 2, j = ij % 2;
    int W2 = 2 * HW;
    out[(((size_t)b * 768 + d) * W2 + 2 * h + i) * W2 + (2 * w + j)] = tmp[idx] + bias[d];
}

__global__ void bn_gelu_kernel(float* __restrict__ y, const float* __restrict__ w,
                               const float* __restrict__ b, const float* __restrict__ mean,
                               const float* __restrict__ var) {
    int idx = blockIdx.x * 256 + threadIdx.x;
    if (idx >= BATCH * 64 * 64 * 768) return;
    int c = idx % 768;
    float v = y[idx];
    v = (v - mean[c]) * rsqrtf(var[c] + 1e-5f) * w[c] + b[c];
    y[idx] = gelu_exact(v);
}

__global__ void to_map_kernel(const float* __restrict__ feat, float* __restrict__ out) {
    int idx = blockIdx.x * 256 + threadIdx.x;
    if (idx >= BATCH * 768 * 32 * 32) return;
    int xw = idx % 32;
    int yh = (idx / 32) % 32;
    int c = (idx / 1024) % 768;
    int b = idx / (1024 * 768);
    out[idx] = feat[((size_t)b * NT + 1 + yh * 32 + xw) * EMB + c];
}

__global__ void maxpool_kernel(const float* __restrict__ feat, float* __restrict__ out) {
    int idx = blockIdx.x * 256 + threadIdx.x;
    if (idx >= BATCH * 768 * 16 * 16) return;
    int xw = idx % 16;
    int yh = (idx / 16) % 16;
    int c = (idx / 256) % 768;
    int b = idx / (256 * 768);
    float m = -1e30f;
#pragma unroll
    for (int i = 0; i < 2; i++)
#pragma unroll
        for (int j = 0; j < 2; j++) {
            int Y = 2 * yh + i, X = 2 * xw + j;
            m = fmaxf(m, feat[((size_t)b * NT + 1 + Y * 32 + X) * EMB + c]);
        }
    out[idx] = m;
}

// ------------------------- host helpers -------------------------------------
static void packA(const float* in, __nv_bfloat16* out, int M, int K, int Kp,
                  size_t irs, size_t ics, size_t ibs0, size_t ibs1, int nh,
                  size_t obs, float scale, int nz) {
    dim3 g((M * Kp + 255) / 256, nz);
    packA_kernel<<<g, 256>>>(in, out, M, K, Kp, irs, ics, ibs0, ibs1, nh, obs, scale);
}
static void packB(const float* in, __nv_bfloat16* out, int M, int K, int Kp,
                  size_t irs, size_t ics, size_t ibs0, size_t ibs1, int nh,
                  size_t obs, int nz) {
    dim3 g((M * Kp + 255) / 256, nz);
    packB_kernel<<<g, 256>>>(in, out, M, K, Kp, irs, ics, ibs0, ibs1, nh, obs, 1.0f);
}
// BN selected for grid occupancy: use 64-wide tiles when 128-wide grid < 148 CTAs
static void gemm_tc(const __nv_bfloat16* A, const __nv_bfloat16* B, float* C,
                    const float* bias, const float* resid, int M, int N, int Ktot,
                    size_t lda, size_t ldb, size_t Abs, size_t Bbs, size_t ldc,
                    size_t cs0, size_t cs1, int nh, int gelu,
                    const float* relt, const int* relidx, int nz) {
    int gm = (M + 127) / 128;
    int g128 = ((N + 127) / 128) * gm * nz;
    if (N % 64 == 0 && (N % 128 != 0 || g128 < 148)) {
        dim3 g(N / 64, gm, nz);
        hgemm<64><<<g, 256>>>(A, B, C, bias, resid, M, N, Ktot, lda, ldb, Abs, Bbs,
                              ldc, cs0, cs1, nh, gelu, relt, relidx);
    } else {
        dim3 g((N + 127) / 128, gm, nz);
        hgemm<128><<<g, 256>>>(A, B, C, bias, resid, M, N, Ktot, lda, ldb, Abs, Bbs,
                               ldc, cs0, cs1, nh, gelu, relt, relidx);
    }
}

extern "C" void kernel_launch(void* const* d_in, const int* in_sizes, int n_in,
                              void* d_out, int out_size) {
    const float* x         = (const float*)d_in[0];
    const float* patch_w   = (const float*)d_in[1];
    const float* patch_b   = (const float*)d_in[2];
    const float* cls_token = (const float*)d_in[3];
    const float* pos_embed = (const float*)d_in[4];
    const float* ln1_w     = (const float*)d_in[5];
    const float* ln1_b     = (const float*)d_in[6];
    const float* qkv_w     = (const float*)d_in[7];
    const float* q_bias    = (const float*)d_in[8];
    const float* v_bias    = (const float*)d_in[9];
    const float* rel_tab   = (const float*)d_in[10];
    const float* proj_w    = (const float*)d_in[11];
    const float* proj_b    = (const float*)d_in[12];
    const float* ln2_w     = (const float*)d_in[13];
    const float* ln2_b     = (const float*)d_in[14];
    const float* fc1_w     = (const float*)d_in[15];
    const float* fc1_b     = (const float*)d_in[16];
    const float* fc2_w     = (const float*)d_in[17];
    const float* fc2_b     = (const float*)d_in[18];
    const float* d1_w      = (const float*)d_in[19];
    const float* d1_b      = (const float*)d_in[20];
    const float* bn_w      = (const float*)d_in[21];
    const float* bn_b      = (const float*)d_in[22];
    const float* bn_mean   = (const float*)d_in[23];
    const float* bn_var    = (const float*)d_in[24];
    const float* d2_w      = (const float*)d_in[25];
    const float* d2_b      = (const float*)d_in[26];
    const float* f2w       = (const float*)d_in[27];
    const float* f2b       = (const float*)d_in[28];
    const int*   rel_idx   = (const int*)d_in[29];

    float* out = (float*)d_out;
    float* out1 = out;
    float* out2 = out1 + (size_t)BATCH * 768 * 128 * 128;
    float* out3 = out2 + (size_t)BATCH * 768 * 64 * 64;
    float* out4 = out3 + (size_t)BATCH * 768 * 32 * 32;

    static float *pt = nullptr, *ph, *pqkv, *pattn, *po, *pmlp, *ppatch, *ptok;
    static float *pf0, *pf1, *pf2, *pf3, *py, *ptmp, *pwp, *pqb;
    static __nv_bfloat16 *pa, *pb;
    if (!pt) {
        cudaGetSymbolAddress((void**)&pt, g_t);
        cudaGetSymbolAddress((void**)&ph, g_h);
        cudaGetSymbolAddress((void**)&pqkv, g_qkv);
        cudaGetSymbolAddress((void**)&pattn, g_attn);
        cudaGetSymbolAddress((void**)&po, g_o);
        cudaGetSymbolAddress((void**)&pmlp, g_mlp);
        cudaGetSymbolAddress((void**)&ppatch, g_patch);
        cudaGetSymbolAddress((void**)&ptok, g_tok);
        cudaGetSymbolAddress((void**)&pf0, g_feat0);
        cudaGetSymbolAddress((void**)&pf1, g_feat1);
        cudaGetSymbolAddress((void**)&pf2, g_feat2);
        cudaGetSymbolAddress((void**)&pf3, g_feat3);
        cudaGetSymbolAddress((void**)&py, g_y);
        cudaGetSymbolAddress((void**)&ptmp, g_tmp);
        cudaGetSymbolAddress((void**)&pwp, g_wpack);
        cudaGetSymbolAddress((void**)&pqb, g_qkvbias);
        cudaGetSymbolAddress((void**)&pa, g_pa);
        cudaGetSymbolAddress((void**)&pb, g_pb);
    }

    const int TOKELEMS = BATCH * NT * EMB;
    const int M = BATCH * NT;  // 2050

    // ---- patch embed (tensor-core GEMM) ----
    patchify_kernel<<<(BATCH * 1024 * EMB + 255) / 256, 256>>>(x, ppatch);
    packA(ppatch, pa, 2048, 768, 768, 768, 1, 0, 0, 1, 0, 1.0f, 1);
    packB(patch_w, pb, 768, 768, 768, 768, 1, 0, 0, 1, 0, 1);
    gemm_tc(pa, pb, ptok, patch_b, nullptr, 2048, 768, 2304, 2304, 2304, 0, 0,
            768, 0, 0, 1, 0, nullptr, nullptr, 1);
    assemble_kernel<<<(TOKELEMS + 255) / 256, 256>>>(ptok, cls_token, pos_embed, pt);

    // ---- transformer layers ----
    for (int l = 0; l < 12; l++) {
        // LN1 + QKV
        ln_kernel<<<M, 256>>>(pt, ln1_w + l * EMB, ln1_b + l * EMB, ph);
        biaspack_kernel<<<(3 * EMB + 255) / 256, 256>>>(q_bias + l * EMB, v_bias + l * EMB, pqb);
        packA(ph, pa, M, 768, 768, 768, 1, 0, 0, 1, 0, 1.0f, 1);
        packB(qkv_w + (size_t)l * 2304 * 768, pb, 2304, 768, 768, 768, 1, 0, 0, 1, 0, 1);
        gemm_tc(pa, pb, pqkv, pqb, nullptr, M, 2304, 2304, 2304, 2304, 0, 0,
                2304, 0, 0, 1, 0, nullptr, nullptr, 1);
        // QK^T (scale folded into Q pack) + rel-bias epilogue
        packA(pqkv, pa, NT, 64, 64, 2304, 1, (size_t)NT * 2304, 64, HEADS,
              (size_t)NT * 192, 0.125f, BATCH * HEADS);
        packB(pqkv + 768, pb, NT, 64, 64, 2304, 1, (size_t)NT * 2304, 64, HEADS,
              (size_t)NT * 192, BATCH * HEADS);
        gemm_tc(pa, pb, pattn, nullptr, nullptr, NT, NT, 192, 192, 192,
                (size_t)NT * 192, (size_t)NT * 192, NT, (size_t)NT * NT, 0, 1, 0,
                rel_tab + (size_t)l * NREL * HEADS, rel_idx, BATCH * HEADS);
        // fused softmax + split-pack P directly into AV A-operand layout
        softmax_pack_kernel<<<BATCH * HEADS * NT, 256>>>(pattn, pa);
        // AV
        packB(pqkv + 1536, pb, 64, NT, 1088, 1, 2304, (size_t)NT * 2304, 64, HEADS,
              (size_t)64 * 3264, BATCH * HEADS);
        gemm_tc(pa, pb, po, nullptr, nullptr, NT, 64, 3264, 3264, 3264,
                (size_t)NT * 3264, (size_t)64 * 3264,
                768, (size_t)NT * 768, 64, HEADS, 0, nullptr, nullptr, BATCH * HEADS);
        // proj (+residual)
        packA(po, pa, M, 768, 768, 768, 1, 0, 0, 1, 0, 1.0f, 1);
        packB(proj_w + (size_t)l * 768 * 768, pb, 768, 768, 768, 768, 1, 0, 0, 1, 0, 1);
        gemm_tc(pa, pb, pt, proj_b + l * EMB, pt, M, 768, 2304, 2304, 2304, 0, 0,
                768, 0, 0, 1, 0, nullptr, nullptr, 1);
        // MLP
        ln_kernel<<<M, 256>>>(pt, ln2_w + l * EMB, ln2_b + l * EMB, ph);
        packA(ph, pa, M, 768, 768, 768, 1, 0, 0, 1, 0, 1.0f, 1);
        packB(fc1_w + (size_t)l * 3072 * 768, pb, 3072, 768, 768, 768, 1, 0, 0, 1, 0, 1);
        gemm_tc(pa, pb, pmlp, fc1_b + l * 4 * EMB, nullptr, M, 3072, 2304, 2304, 2304, 0, 0,
                3072, 0, 0, 1, 1, nullptr, nullptr, 1);
        packA(pmlp, pa, M, 3072, 3072, 3072, 1, 0, 0, 1, 0, 1.0f, 1);
        packB(fc2_w + (size_t)l * 768 * 3072, pb, 768, 3072, 3072, 3072, 1, 0, 0, 1, 0, 1);
        gemm_tc(pa, pb, pt, fc2_b + l * EMB, pt, M, 768, 9216, 9216, 9216, 0, 0,
                768, 0, 0, 1, 0, nullptr, nullptr, 1);
        float* fdst = nullptr;
        if (l == 3) fdst = pf0;
        else if (l == 5) fdst = pf1;
        else if (l == 7) fdst = pf2;
        else if (l == 11) fdst = pf3;
        if (fdst) copy_kernel<<<(TOKELEMS + 255) / 256, 256>>>(pt, fdst, TOKELEMS);
    }

    // ---- o3 / o4 ----
    to_map_kernel<<<(BATCH * 768 * 1024 + 255) / 256, 256>>>(pf2, out3);
    maxpool_kernel<<<(BATCH * 768 * 256 + 255) / 256, 256>>>(pf3, out4);

    // ---- fpn1 stage 1: deconv d1 on layer-3 map ----
    repack_w_kernel<<<(3072 * 768 + 255) / 256, 256>>>(d1_w, pwp);
    packB(pwp, pb, 3072, 768, 768, 768, 1, 0, 0, 1, 0, 1);
    packA(pf0 + 768, pa, 1024, 768, 768, 768, 1, (size_t)NT * 768, 0, 1,
          (size_t)1024 * 2304, 1.0f, BATCH);
    gemm_tc(pa, pb, ptmp, nullptr, nullptr, 1024, 3072, 2304, 2304, 2304,
            (size_t)1024 * 2304, 0, 3072, (size_t)1024 * 3072, 0, 1, 0,
            nullptr, nullptr, BATCH);
    scatter_bhwc_kernel<<<(BATCH * 1024 * 3072 + 255) / 256, 256>>>(ptmp, d1_b, py, 32);
    bn_gelu_kernel<<<(BATCH * 64 * 64 * 768 + 255) / 256, 256>>>(py, bn_w, bn_b, bn_mean, bn_var);

    // ---- fpn1 stage 2: deconv d2 -> o1 ----
    repack_w_kernel<<<(3072 * 768 + 255) / 256, 256>>>(d2_w, pwp);
    packB(pwp, pb, 3072, 768, 768, 768, 1, 0, 0, 1, 0, 1);
    packA(py, pa, 4096, 768, 768, 768, 1, (size_t)4096 * 768, 0, 1,
          (size_t)4096 * 2304, 1.0f, BATCH);
    gemm_tc(pa, pb, ptmp, nullptr, nullptr, 4096, 3072, 2304, 2304, 2304,
            (size_t)4096 * 2304, 0, 3072, (size_t)4096 * 3072, 0, 1, 0,
            nullptr, nullptr, BATCH);
    scatter_bchw_kernel<<<(BATCH * 4096 * 3072 + 255) / 256, 256>>>(ptmp, d2_b, out1, 64);

    // ---- o2: deconv f2_w on layer-5 map ----
    repack_w_kernel<<<(3072 * 768 + 255) / 256, 256>>>(f2w, pwp);
    packB(pwp, pb, 3072, 768, 768, 768, 1, 0, 0, 1, 0, 1);
    packA(pf1 + 768, pa, 1024, 768, 768, 768, 1, (size_t)NT * 768, 0, 1,
          (size_t)1024 * 2304, 1.0f, BATCH);
    gemm_tc(pa, pb, ptmp, nullptr, nullptr, 1024, 3072, 2304, 2304, 2304,
            (size_t)1024 * 2304, 0, 3072, (size_t)1024 * 3072, 0, 1, 0,
            nullptr, nullptr, BATCH);
    scatter_bchw_kernel<<<(BATCH * 1024 * 3072 + 255) / 256, 256>>>(ptmp, f2b, out2, 32);

    (void)in_sizes; (void)n_in; (void)out_size;
}

// round 5
// speedup vs baseline: 2.3832x; 1.1129x over previous
#include <cuda_runtime.h>
#include <cuda_bf16.h>
#include <math.h>
#include <stdint.h>

#define NT    1025
#define EMB   768
#define BATCH 2
#define HEADS 12
#define NREL  3972

// ------------------------- device scratch (no allocs allowed) ---------------
__device__ float g_t[BATCH * NT * EMB];
__device__ float g_h[BATCH * NT * EMB];
__device__ float g_qkv[BATCH * NT * 3 * EMB];
__device__ float g_o[BATCH * NT * EMB];
__device__ float g_mlp[BATCH * NT * 4 * EMB];
__device__ float g_patch[BATCH * 1024 * EMB];
__device__ float g_tok[BATCH * 1024 * EMB];
__device__ float g_feat0[BATCH * NT * EMB];
__device__ float g_feat1[BATCH * NT * EMB];
__device__ float g_feat2[BATCH * NT * EMB];
__device__ float g_feat3[BATCH * NT * EMB];
__device__ float g_y[BATCH * 64 * 64 * EMB];
__device__ float g_tmp[(size_t)BATCH * 4096 * 3072];
__device__ float g_wpack[3072 * 768];
__device__ float g_qkvbias[3 * EMB];
// bf16 packed operand buffers (split hi/lo, 3 sections along K)
__device__ __nv_bfloat16 g_pa[20000000];
__device__ __nv_bfloat16 g_pb[7500000];

__device__ __forceinline__ float gelu_exact(float x) {
    return 0.5f * x * (1.0f + erff(x * 0.70710678118654752f));
}

__device__ __forceinline__ uint32_t smem_u32(const void* p) {
    uint32_t a;
    asm("{ .reg .u64 t; cvta.to.shared.u64 t, %1; cvt.u32.u64 %0, t; }" : "=r"(a) : "l"(p));
    return a;
}

#define LDSM_X4(r0, r1, r2, r3, addr) \
    asm volatile("ldmatrix.sync.aligned.m8n8.x4.shared.b16 {%0,%1,%2,%3}, [%4];" \
                 : "=r"(r0), "=r"(r1), "=r"(r2), "=r"(r3) : "r"(addr))

#define MMA16816(d, a0, a1, a2, a3, b0, b1) \
    asm volatile("mma.sync.aligned.m16n8k16.row.col.f32.bf16.bf16.f32 " \
                 "{%0,%1,%2,%3}, {%4,%5,%6,%7}, {%8,%9}, {%0,%1,%2,%3};" \
                 : "+f"((d)[0]), "+f"((d)[1]), "+f"((d)[2]), "+f"((d)[3]) \
                 : "r"(a0), "r"(a1), "r"(a2), "r"(a3), "r"(b0), "r"(b1))

#define CP_ASYNC16(dst, src, sz) \
    asm volatile("cp.async.cg.shared.global [%0], [%1], 16, %2;" \
                 :: "r"(dst), "l"(src), "r"(sz))

__device__ __forceinline__ uint32_t pack_bf16(float x, float y) {
    __nv_bfloat162 t = __floats2bfloat162_rn(x, y);
    return *(uint32_t*)&t;
}

// ========================= split-bf16 pack kernels ==========================
__global__ void packA_kernel(const float* __restrict__ in, __nv_bfloat16* __restrict__ out,
                             int M, int K, int Kp, size_t irs, size_t ics,
                             size_t ibs0, size_t ibs1, int nh, size_t obs, float scale) {
    int idx = blockIdx.x * 256 + threadIdx.x;
    int z = blockIdx.y;
    if (idx >= M * Kp) return;
    int k = idx % Kp, m = idx / Kp;
    const float* src = in + (size_t)(z / nh) * ibs0 + (size_t)(z % nh) * ibs1;
    float v = (k < K) ? src[(size_t)m * irs + (size_t)k * ics] * scale : 0.f;
    __nv_bfloat16 hi = __float2bfloat16(v);
    __nv_bfloat16 lo = __float2bfloat16(v - __bfloat162float(hi));
    __nv_bfloat16* o = out + (size_t)z * obs + (size_t)m * (3 * (size_t)Kp);
    o[k] = hi; o[Kp + k] = lo; o[2 * Kp + k] = hi;
}
__global__ void packB_kernel(const float* __restrict__ in, __nv_bfloat16* __restrict__ out,
                             int M, int K, int Kp, size_t irs, size_t ics,
                             size_t ibs0, size_t ibs1, int nh, size_t obs, float scale) {
    int idx = blockIdx.x * 256 + threadIdx.x;
    int z = blockIdx.y;
    if (idx >= M * Kp) return;
    int k = idx % Kp, m = idx / Kp;
    const float* src = in + (size_t)(z / nh) * ibs0 + (size_t)(z % nh) * ibs1;
    float v = (k < K) ? src[(size_t)m * irs + (size_t)k * ics] * scale : 0.f;
    __nv_bfloat16 hi = __float2bfloat16(v);
    __nv_bfloat16 lo = __float2bfloat16(v - __bfloat162float(hi));
    __nv_bfloat16* o = out + (size_t)z * obs + (size_t)m * (3 * (size_t)Kp);
    o[k] = hi; o[Kp + k] = hi; o[2 * Kp + k] = lo;
}

// ========================= HMMA GEMM (mma.sync bf16) ========================
template <int BN>
__global__ void __launch_bounds__(256, 2) hgemm(
    const __nv_bfloat16* __restrict__ A, const __nv_bfloat16* __restrict__ B,
    float* __restrict__ C, const float* __restrict__ bias, const float* __restrict__ resid,
    int M, int Nreal, int Ktot, size_t lda, size_t ldb, size_t Abs, size_t Bbs,
    size_t ldc, size_t cs0, size_t cs1, int nh, int do_gelu) {
    constexpr int WTN = BN / 4;
    constexpr int NT8 = WTN / 8;
    constexpr int NB4 = BN / 64;
    __shared__ __nv_bfloat16 sA[2][128][40];
    __shared__ __nv_bfloat16 sB[2][BN][40];

    int tid = threadIdx.x;
    int wid = tid >> 5, lane = tid & 31;
    int warp_m = wid >> 2, warp_n = wid & 3;
    int m0 = blockIdx.y * 128, n0 = blockIdx.x * BN;
    int z = blockIdx.z;

    const __nv_bfloat16* Az = A + (size_t)z * Abs;
    const __nv_bfloat16* Bz = B + (size_t)z * Bbs;

    float acc[4][NT8][4];
#pragma unroll
    for (int i = 0; i < 4; i++)
#pragma unroll
        for (int j = 0; j < NT8; j++)
#pragma unroll
            for (int e = 0; e < 4; e++) acc[i][j][e] = 0.f;

    int nk = Ktot >> 5;

    auto load_chunk = [&](int c, int buf) {
#pragma unroll
        for (int i = 0; i < 2; i++) {
            int idx = tid + i * 256, row = idx >> 2, cg = idx & 3;
            uint32_t dst = smem_u32(&sA[buf][row][cg * 8]);
            const __nv_bfloat16* src = Az + (size_t)(m0 + row) * lda + c * 32 + cg * 8;
            CP_ASYNC16(dst, src, (m0 + row < M) ? 16 : 0);
        }
#pragma unroll
        for (int i = 0; i < NB4; i++) {
            int idx = tid + i * 256, row = idx >> 2, cg = idx & 3;
            uint32_t dst = smem_u32(&sB[buf][row][cg * 8]);
            const __nv_bfloat16* src = Bz + (size_t)(n0 + row) * ldb + c * 32 + cg * 8;
            CP_ASYNC16(dst, src, (n0 + row < Nreal) ? 16 : 0);
        }
        asm volatile("cp.async.commit_group;");
    };

    load_chunk(0, 0);

    for (int c = 0; c < nk; c++) {
        int buf = c & 1;
        if (c + 1 < nk) {
            load_chunk(c + 1, buf ^ 1);
            asm volatile("cp.async.wait_group 1;");
        } else {
            asm volatile("cp.async.wait_group 0;");
        }
        __syncthreads();
#pragma unroll
        for (int kk = 0; kk < 2; kk++) {
            uint32_t af[4][4];
#pragma unroll
            for (int mt = 0; mt < 4; mt++) {
                uint32_t addr = smem_u32(&sA[buf][warp_m * 64 + mt * 16 + (lane & 15)]
                                           [kk * 16 + (lane >> 4) * 8]);
                LDSM_X4(af[mt][0], af[mt][1], af[mt][2], af[mt][3], addr);
            }
            uint32_t bf[NT8][2];
#pragma unroll
            for (int p = 0; p < NT8 / 2; p++) {
                uint32_t addr = smem_u32(&sB[buf][warp_n * WTN + p * 16 + ((lane >> 4) << 3) + (lane & 7)]
                                           [kk * 16 + ((lane >> 3) & 1) * 8]);
                LDSM_X4(bf[2 * p][0], bf[2 * p][1], bf[2 * p + 1][0], bf[2 * p + 1][1], addr);
            }
#pragma unroll
            for (int mt = 0; mt < 4; mt++)
#pragma unroll
                for (int nt = 0; nt < NT8; nt++)
                    MMA16816(acc[mt][nt], af[mt][0], af[mt][1], af[mt][2], af[mt][3],
                             bf[nt][0], bf[nt][1]);
        }
        __syncthreads();
    }

    size_t cbase = (size_t)(z / nh) * cs0 + (size_t)(z % nh) * cs1;
    int mrow = lane >> 2, ncol = (lane & 3) * 2;
#pragma unroll
    for (int mt = 0; mt < 4; mt++) {
#pragma unroll
        for (int half = 0; half < 2; half++) {
            int row = m0 + warp_m * 64 + mt * 16 + mrow + half * 8;
            if (row >= M) continue;
#pragma unroll
            for (int nt = 0; nt < NT8; nt++) {
#pragma unroll
                for (int e = 0; e < 2; e++) {
                    int col = n0 + warp_n * WTN + nt * 8 + ncol + e;
                    if (col >= Nreal) continue;
                    float v = acc[mt][nt][half * 2 + e];
                    if (bias) v += bias[col];
                    size_t off = cbase + (size_t)row * ldc + col;
                    if (resid) v += resid[off];
                    if (do_gelu) v = gelu_exact(v);
                    C[off] = v;
                }
            }
        }
    }
}

// ========================= fused flash attention ============================
// grid (ceil(NT/128), B*H), block 256 (8 warps x 16 q-rows).
// S = (Qhi+Qlo)Khi + Qhi*Klo ; online softmax ; O += (Phi+Plo)Vhi + Phi*Vlo.
#define FA_LD 136   // smem row stride in bf16 (272B, 16B aligned)
__global__ void __launch_bounds__(256, 2) flash_attn_kernel(
    const float* __restrict__ qkv, const float* __restrict__ relt,
    const int* __restrict__ relidx, float* __restrict__ o) {
    extern __shared__ __nv_bfloat16 fsm[];
    __nv_bfloat16* sQ = fsm;                    // [128][FA_LD]  cols 0..63 hi, 64..127 lo
    __nv_bfloat16* sK = fsm + 128 * FA_LD;      // [64][FA_LD]
    __nv_bfloat16* sV = sK + 64 * FA_LD;        // [64][FA_LD]  [d][j] (transposed)

    int tid = threadIdx.x, wid = tid >> 5, lane = tid & 31;
    int i0 = blockIdx.x * 128;
    int z = blockIdx.y;
    int b = z / HEADS, h = z % HEADS;
    const float* qb = qkv + (size_t)b * NT * 2304 + h * 64;
    const float* kb = qb + 768;
    const float* vb = qb + 1536;

    // load Q block (scale folded), split hi/lo
    for (int idx = tid; idx < 128 * 64; idx += 256) {
        int r = idx >> 6, c = idx & 63;
        int gi = i0 + r;
        float v = (gi < NT) ? qb[(size_t)gi * 2304 + c] * 0.125f : 0.f;
        __nv_bfloat16 hi = __float2bfloat16(v);
        sQ[r * FA_LD + c] = hi;
        sQ[r * FA_LD + 64 + c] = __float2bfloat16(v - __bfloat162float(hi));
    }

    float m0 = -1e30f, m1 = -1e30f, l0 = 0.f, l1 = 0.f;
    float O[8][4];
#pragma unroll
    for (int t = 0; t < 8; t++)
#pragma unroll
        for (int e = 0; e < 4; e++) O[t][e] = 0.f;

    int r0g = i0 + wid * 16 + (lane >> 2);   // global row for c0/c1
    int r1g = r0g + 8;                       // global row for c2/c3

    for (int j0 = 0; j0 < NT; j0 += 64) {
        __syncthreads();
        // load K (split) and V (split, transposed)
        for (int idx = tid; idx < 64 * 64; idx += 256) {
            int r = idx >> 6, c = idx & 63;
            int gj = j0 + r;
            float kv = (gj < NT) ? kb[(size_t)gj * 2304 + c] : 0.f;
            __nv_bfloat16 khi = __float2bfloat16(kv);
            sK[r * FA_LD + c] = khi;
            sK[r * FA_LD + 64 + c] = __float2bfloat16(kv - __bfloat162float(khi));
            float vv = (gj < NT) ? vb[(size_t)gj * 2304 + c] : 0.f;
            __nv_bfloat16 vhi = __float2bfloat16(vv);
            sV[c * FA_LD + r] = vhi;
            sV[c * FA_LD + 64 + r] = __float2bfloat16(vv - __bfloat162float(vhi));
        }
        __syncthreads();

        // ---- S = Q K^T (split, 3 products) ----
        float S[8][4];
#pragma unroll
        for (int t = 0; t < 8; t++)
#pragma unroll
            for (int e = 0; e < 4; e++) S[t][e] = 0.f;

        const int qsec[3] = {0, 1, 0}, ksec[3] = {0, 0, 1};
#pragma unroll
        for (int sp = 0; sp < 3; sp++) {
#pragma unroll
            for (int kk = 0; kk < 4; kk++) {
                uint32_t a0, a1, a2, a3;
                uint32_t addr = smem_u32(&sQ[(wid * 16 + (lane & 15)) * FA_LD +
                                             qsec[sp] * 64 + kk * 16 + (lane >> 4) * 8]);
                LDSM_X4(a0, a1, a2, a3, addr);
                uint32_t bf[8][2];
#pragma unroll
                for (int p = 0; p < 4; p++) {
                    uint32_t ba = smem_u32(&sK[(p * 16 + ((lane >> 4) << 3) + (lane & 7)) * FA_LD +
                                               ksec[sp] * 64 + kk * 16 + ((lane >> 3) & 1) * 8]);
                    LDSM_X4(bf[2 * p][0], bf[2 * p][1], bf[2 * p + 1][0], bf[2 * p + 1][1], ba);
                }
#pragma unroll
                for (int nt = 0; nt < 8; nt++)
                    MMA16816(S[nt], a0, a1, a2, a3, bf[nt][0], bf[nt][1]);
            }
        }

        // ---- rel bias + mask ----
#pragma unroll
        for (int nt = 0; nt < 8; nt++) {
            int c0 = j0 + nt * 8 + (lane & 3) * 2;
#pragma unroll
            for (int e = 0; e < 2; e++) {
                int jj = c0 + e;
                if (jj < NT) {
                    if (r0g < NT) S[nt][e]     += relt[(size_t)relidx[(size_t)r0g * NT + jj] * HEADS + h];
                    if (r1g < NT) S[nt][2 + e] += relt[(size_t)relidx[(size_t)r1g * NT + jj] * HEADS + h];
                } else {
                    S[nt][e] = -1e30f;
                    S[nt][2 + e] = -1e30f;
                }
            }
        }

        // ---- online softmax ----
        float t0 = -1e30f, t1 = -1e30f;
#pragma unroll
        for (int nt = 0; nt < 8; nt++) {
            t0 = fmaxf(t0, fmaxf(S[nt][0], S[nt][1]));
            t1 = fmaxf(t1, fmaxf(S[nt][2], S[nt][3]));
        }
        t0 = fmaxf(t0, __shfl_xor_sync(0xffffffff, t0, 1));
        t0 = fmaxf(t0, __shfl_xor_sync(0xffffffff, t0, 2));
        t1 = fmaxf(t1, __shfl_xor_sync(0xffffffff, t1, 1));
        t1 = fmaxf(t1, __shfl_xor_sync(0xffffffff, t1, 2));
        float mn0 = fmaxf(m0, t0), mn1 = fmaxf(m1, t1);
        float al0 = __expf(m0 - mn0), al1 = __expf(m1 - mn1);
#pragma unroll
        for (int nt = 0; nt < 8; nt++) {
            O[nt][0] *= al0; O[nt][1] *= al0;
            O[nt][2] *= al1; O[nt][3] *= al1;
        }
        float ls0 = 0.f, ls1 = 0.f;
        uint32_t phi[4][4], plo[4][4];
#pragma unroll
        for (int kk = 0; kk < 4; kk++) {
#pragma unroll
            for (int tt = 0; tt < 2; tt++) {
                int t = 2 * kk + tt;
                float p0 = __expf(S[t][0] - mn0), p1 = __expf(S[t][1] - mn0);
                float p2 = __expf(S[t][2] - mn1), p3 = __expf(S[t][3] - mn1);
                ls0 += p0 + p1; ls1 += p2 + p3;
                float h0 = __bfloat162float(__float2bfloat16(p0));
                float h1 = __bfloat162float(__float2bfloat16(p1));
                float h2 = __bfloat162float(__float2bfloat16(p2));
                float h3 = __bfloat162float(__float2bfloat16(p3));
                phi[kk][tt * 2]     = pack_bf16(h0, h1);
                phi[kk][tt * 2 + 1] = pack_bf16(h2, h3);
                plo[kk][tt * 2]     = pack_bf16(p0 - h0, p1 - h1);
                plo[kk][tt * 2 + 1] = pack_bf16(p2 - h2, p3 - h3);
            }
        }
        ls0 += __shfl_xor_sync(0xffffffff, ls0, 1);
        ls0 += __shfl_xor_sync(0xffffffff, ls0, 2);
        ls1 += __shfl_xor_sync(0xffffffff, ls1, 1);
        ls1 += __shfl_xor_sync(0xffffffff, ls1, 2);
        l0 = l0 * al0 + ls0;
        l1 = l1 * al1 + ls1;
        m0 = mn0; m1 = mn1;

        // ---- O += P V (split, 3 products) ----
        const int vsec[3] = {0, 0, 1};  // paired with P sections hi, lo, hi
#pragma unroll
        for (int sp = 0; sp < 3; sp++) {
#pragma unroll
            for (int kk = 0; kk < 4; kk++) {
                uint32_t* A = (sp == 1) ? plo[kk] : phi[kk];
                uint32_t bf[8][2];
#pragma unroll
                for (int p = 0; p < 4; p++) {
                    uint32_t ba = smem_u32(&sV[(p * 16 + ((lane >> 4) << 3) + (lane & 7)) * FA_LD +
                                               vsec[sp] * 64 + kk * 16 + ((lane >> 3) & 1) * 8]);
                    LDSM_X4(bf[2 * p][0], bf[2 * p][1], bf[2 * p + 1][0], bf[2 * p + 1][1], ba);
                }
#pragma unroll
                for (int nt = 0; nt < 8; nt++)
                    MMA16816(O[nt], A[0], A[1], A[2], A[3], bf[nt][0], bf[nt][1]);
            }
        }
    }

    // ---- normalize + store ----
    float il0 = 1.0f / l0, il1 = 1.0f / l1;
#pragma unroll
    for (int nt = 0; nt < 8; nt++) {
        int d = h * 64 + nt * 8 + (lane & 3) * 2;
        if (r0g < NT) {
            float2 v = make_float2(O[nt][0] * il0, O[nt][1] * il0);
            *(float2*)&o[((size_t)b * NT + r0g) * EMB + d] = v;
        }
        if (r1g < NT) {
            float2 v = make_float2(O[nt][2] * il1, O[nt][3] * il1);
            *(float2*)&o[((size_t)b * NT + r1g) * EMB + d] = v;
        }
    }
}

// ------------------------- elementwise helpers ------------------------------
__global__ void patchify_kernel(const float* __restrict__ x, float* __restrict__ A) {
    int idx = blockIdx.x * 256 + threadIdx.x;
    if (idx >= BATCH * 1024 * EMB) return;
    int col = idx % EMB;
    int m = idx / EMB;
    int b = m / 1024, g = m % 1024;
    int gh = g / 32, gw = g % 32;
    int c = col / 256, rem = col % 256;
    int i = rem / 16, j = rem % 16;
    A[idx] = x[(((size_t)(b * 3 + c) * 512) + gh * 16 + i) * 512 + gw * 16 + j];
}

__global__ void assemble_kernel(const float* __restrict__ tok, const float* __restrict__ cls,
                                const float* __restrict__ pos, float* __restrict__ t) {
    int idx = blockIdx.x * 256 + threadIdx.x;
    if (idx >= BATCH * NT * EMB) return;
    int d = idx % EMB;
    int n = (idx / EMB) % NT;
    int b = idx / (EMB * NT);
    float v = (n == 0) ? cls[d] : tok[((size_t)b * 1024 + (n - 1)) * EMB + d];
    t[idx] = v + pos[n * EMB + d];
}

__global__ void ln_kernel(const float* __restrict__ x, const float* __restrict__ w,
                          const float* __restrict__ b, float* __restrict__ out) {
    int r = blockIdx.x;
    const float* xr = x + (size_t)r * EMB;
    __shared__ float red[256];
    int tid = threadIdx.x;
    float s = 0.f;
    for (int i = tid; i < EMB; i += 256) s += xr[i];
    red[tid] = s; __syncthreads();
    for (int st = 128; st > 0; st >>= 1) { if (tid < st) red[tid] += red[tid + st]; __syncthreads(); }
    float mean = red[0] * (1.0f / EMB);
    __syncthreads();
    float s2 = 0.f;
    for (int i = tid; i < EMB; i += 256) { float d = xr[i] - mean; s2 += d * d; }
    red[tid] = s2; __syncthreads();
    for (int st = 128; st > 0; st >>= 1) { if (tid < st) red[tid] += red[tid + st]; __syncthreads(); }
    float inv = rsqrtf(red[0] * (1.0f / EMB) + 1e-6f);
    for (int i = tid; i < EMB; i += 256)
        out[(size_t)r * EMB + i] = (xr[i] - mean) * inv * w[i] + b[i];
}

__global__ void biaspack_kernel(const float* __restrict__ qb, const float* __restrict__ vb,
                                float* __restrict__ out) {
    int i = blockIdx.x * 256 + threadIdx.x;
    if (i >= 3 * EMB) return;
    out[i] = (i < EMB) ? qb[i] : ((i < 2 * EMB) ? 0.f : vb[i - 2 * EMB]);
}

__global__ void copy_kernel(const float* __restrict__ src, float* __restrict__ dst, int n) {
    int i = blockIdx.x * 256 + threadIdx.x;
    if (i < n) dst[i] = src[i];
}

__global__ void repack_w_kernel(const float* __restrict__ w, float* __restrict__ wp) {
    int idx = blockIdx.x * 256 + threadIdx.x;
    if (idx >= 3072 * 768) return;
    int c = idx % 768, n = idx / 768;
    int ij = n / 768, d = n % 768;
    wp[idx] = w[(size_t)c * 3072 + d * 4 + ij];
}

__global__ void scatter_bhwc_kernel(const float* __restrict__ tmp, const float* __restrict__ bias,
                                    float* __restrict__ y, int HW) {
    int total = BATCH * HW * HW * 4 * 768;
    int idx = blockIdx.x * 256 + threadIdx.x;
    if (idx >= total) return;
    int d = idx % 768;
    int ij = (idx / 768) % 4;
    int p = (idx / 3072) % (HW * HW);
    int b = idx / (3072 * HW * HW);
    int h = p / HW, w = p % HW, i = ij / 2, j = ij % 2;
    int W2 = 2 * HW;
    y[(((size_t)b * W2 + 2 * h + i) * W2 + (2 * w + j)) * 768 + d] = tmp[idx] + bias[d];
}

__global__ void scatter_bchw_kernel(const float* __restrict__ tmp, const float* __restrict__ bias,
                                    float* __restrict__ out, int HW) {
    int total = BATCH * HW * HW * 4 * 768;
    int idx = blockIdx.x * 256 + threadIdx.x;
    if (idx >= total) return;
    int d = idx % 768;
    int ij = (idx / 768) % 4;
    int p = (idx / 3072) % (HW * HW);
    int b = idx / (3072 * HW * HW);
    int h = p / HW, w = p % HW, i = ij / 2, j = ij % 2;
    int W2 = 2 * HW;
    out[(((size_t)b * 768 + d) * W2 + 2 * h + i) * W2 + (2 * w + j)] = tmp[idx] + bias[d];
}

__global__ void bn_gelu_kernel(float* __restrict__ y, const float* __restrict__ w,
                               const float* __restrict__ b, const float* __restrict__ mean,
                               const float* __restrict__ var) {
    int idx = blockIdx.x * 256 + threadIdx.x;
    if (idx >= BATCH * 64 * 64 * 768) return;
    int c = idx % 768;
    float v = y[idx];
    v = (v - mean[c]) * rsqrtf(var[c] + 1e-5f) * w[c] + b[c];
    y[idx] = gelu_exact(v);
}

__global__ void to_map_kernel(const float* __restrict__ feat, float* __restrict__ out) {
    int idx = blockIdx.x * 256 + threadIdx.x;
    if (idx >= BATCH * 768 * 32 * 32) return;
    int xw = idx % 32;
    int yh = (idx / 32) % 32;
    int c = (idx / 1024) % 768;
    int b = idx / (1024 * 768);
    out[idx] = feat[((size_t)b * NT + 1 + yh * 32 + xw) * EMB + c];
}

__global__ void maxpool_kernel(const float* __restrict__ feat, float* __restrict__ out) {
    int idx = blockIdx.x * 256 + threadIdx.x;
    if (idx >= BATCH * 768 * 16 * 16) return;
    int xw = idx % 16;
    int yh = (idx / 16) % 16;
    int c = (idx / 256) % 768;
    int b = idx / (256 * 768);
    float m = -1e30f;
#pragma unroll
    for (int i = 0; i < 2; i++)
#pragma unroll
        for (int j = 0; j < 2; j++) {
            int Y = 2 * yh + i, X = 2 * xw + j;
            m = fmaxf(m, feat[((size_t)b * NT + 1 + Y * 32 + X) * EMB + c]);
        }
    out[idx] = m;
}

// ------------------------- host helpers -------------------------------------
static void packA(const float* in, __nv_bfloat16* out, int M, int K, int Kp,
                  size_t irs, size_t ics, size_t ibs0, size_t ibs1, int nh,
                  size_t obs, float scale, int nz) {
    dim3 g((M * Kp + 255) / 256, nz);
    packA_kernel<<<g, 256>>>(in, out, M, K, Kp, irs, ics, ibs0, ibs1, nh, obs, scale);
}
static void packB(const float* in, __nv_bfloat16* out, int M, int K, int Kp,
                  size_t irs, size_t ics, size_t ibs0, size_t ibs1, int nh,
                  size_t obs, int nz) {
    dim3 g((M * Kp + 255) / 256, nz);
    packB_kernel<<<g, 256>>>(in, out, M, K, Kp, irs, ics, ibs0, ibs1, nh, obs, 1.0f);
}
static void gemm_tc(const __nv_bfloat16* A, const __nv_bfloat16* B, float* C,
                    const float* bias, const float* resid, int M, int N, int Ktot,
                    size_t lda, size_t ldb, size_t Abs, size_t Bbs, size_t ldc,
                    size_t cs0, size_t cs1, int nh, int gelu, int nz) {
    int gm = (M + 127) / 128;
    int g128 = ((N + 127) / 128) * gm * nz;
    if (N % 64 == 0 && (N % 128 != 0 || g128 < 148)) {
        dim3 g(N / 64, gm, nz);
        hgemm<64><<<g, 256>>>(A, B, C, bias, resid, M, N, Ktot, lda, ldb, Abs, Bbs,
                              ldc, cs0, cs1, nh, gelu);
    } else {
        dim3 g((N + 127) / 128, gm, nz);
        hgemm<128><<<g, 256>>>(A, B, C, bias, resid, M, N, Ktot, lda, ldb, Abs, Bbs,
                               ldc, cs0, cs1, nh, gelu);
    }
}

extern "C" void kernel_launch(void* const* d_in, const int* in_sizes, int n_in,
                              void* d_out, int out_size) {
    const float* x         = (const float*)d_in[0];
    const float* patch_w   = (const float*)d_in[1];
    const float* patch_b   = (const float*)d_in[2];
    const float* cls_token = (const float*)d_in[3];
    const float* pos_embed = (const float*)d_in[4];
    const float* ln1_w     = (const float*)d_in[5];
    const float* ln1_b     = (const float*)d_in[6];
    const float* qkv_w     = (const float*)d_in[7];
    const float* q_bias    = (const float*)d_in[8];
    const float* v_bias    = (const float*)d_in[9];
    const float* rel_tab   = (const float*)d_in[10];
    const float* proj_w    = (const float*)d_in[11];
    const float* proj_b    = (const float*)d_in[12];
    const float* ln2_w     = (const float*)d_in[13];
    const float* ln2_b     = (const float*)d_in[14];
    const float* fc1_w     = (const float*)d_in[15];
    const float* fc1_b     = (const float*)d_in[16];
    const float* fc2_w     = (const float*)d_in[17];
    const float* fc2_b     = (const float*)d_in[18];
    const float* d1_w      = (const float*)d_in[19];
    const float* d1_b      = (const float*)d_in[20];
    const float* bn_w      = (const float*)d_in[21];
    const float* bn_b      = (const float*)d_in[22];
    const float* bn_mean   = (const float*)d_in[23];
    const float* bn_var    = (const float*)d_in[24];
    const float* d2_w      = (const float*)d_in[25];
    const float* d2_b      = (const float*)d_in[26];
    const float* f2w       = (const float*)d_in[27];
    const float* f2b       = (const float*)d_in[28];
    const int*   rel_idx   = (const int*)d_in[29];

    float* out = (float*)d_out;
    float* out1 = out;
    float* out2 = out1 + (size_t)BATCH * 768 * 128 * 128;
    float* out3 = out2 + (size_t)BATCH * 768 * 64 * 64;
    float* out4 = out3 + (size_t)BATCH * 768 * 32 * 32;

    static float *pt = nullptr, *ph, *pqkv, *po, *pmlp, *ppatch, *ptok;
    static float *pf0, *pf1, *pf2, *pf3, *py, *ptmp, *pwp, *pqb;
    static __nv_bfloat16 *pa, *pb;
    if (!pt) {
        cudaGetSymbolAddress((void**)&pt, g_t);
        cudaGetSymbolAddress((void**)&ph, g_h);
        cudaGetSymbolAddress((void**)&pqkv, g_qkv);
        cudaGetSymbolAddress((void**)&po, g_o);
        cudaGetSymbolAddress((void**)&pmlp, g_mlp);
        cudaGetSymbolAddress((void**)&ppatch, g_patch);
        cudaGetSymbolAddress((void**)&ptok, g_tok);
        cudaGetSymbolAddress((void**)&pf0, g_feat0);
        cudaGetSymbolAddress((void**)&pf1, g_feat1);
        cudaGetSymbolAddress((void**)&pf2, g_feat2);
        cudaGetSymbolAddress((void**)&pf3, g_feat3);
        cudaGetSymbolAddress((void**)&py, g_y);
        cudaGetSymbolAddress((void**)&ptmp, g_tmp);
        cudaGetSymbolAddress((void**)&pwp, g_wpack);
        cudaGetSymbolAddress((void**)&pqb, g_qkvbias);
        cudaGetSymbolAddress((void**)&pa, g_pa);
        cudaGetSymbolAddress((void**)&pb, g_pb);
        cudaFuncSetAttribute(flash_attn_kernel,
                             cudaFuncAttributeMaxDynamicSharedMemorySize,
                             (128 + 64 + 64) * FA_LD * 2);
    }

    const int TOKELEMS = BATCH * NT * EMB;
    const int M = BATCH * NT;  // 2050
    const int FA_SMEM = (128 + 64 + 64) * FA_LD * 2;

    // ---- patch embed ----
    patchify_kernel<<<(BATCH * 1024 * EMB + 255) / 256, 256>>>(x, ppatch);
    packA(ppatch, pa, 2048, 768, 768, 768, 1, 0, 0, 1, 0, 1.0f, 1);
    packB(patch_w, pb, 768, 768, 768, 768, 1, 0, 0, 1, 0, 1);
    gemm_tc(pa, pb, ptok, patch_b, nullptr, 2048, 768, 2304, 2304, 2304, 0, 0,
            768, 0, 0, 1, 0, 1);
    assemble_kernel<<<(TOKELEMS + 255) / 256, 256>>>(ptok, cls_token, pos_embed, pt);

    // ---- transformer layers ----
    for (int l = 0; l < 12; l++) {
        ln_kernel<<<M, 256>>>(pt, ln1_w + l * EMB, ln1_b + l * EMB, ph);
        biaspack_kernel<<<(3 * EMB + 255) / 256, 256>>>(q_bias + l * EMB, v_bias + l * EMB, pqb);
        packA(ph, pa, M, 768, 768, 768, 1, 0, 0, 1, 0, 1.0f, 1);
        packB(qkv_w + (size_t)l * 2304 * 768, pb, 2304, 768, 768, 768, 1, 0, 0, 1, 0, 1);
        gemm_tc(pa, pb, pqkv, pqb, nullptr, M, 2304, 2304, 2304, 2304, 0, 0,
                2304, 0, 0, 1, 0, 1);
        // fused attention (QK^T + rel bias + softmax + PV)
        {
            dim3 g((NT + 127) / 128, BATCH * HEADS);
            flash_attn_kernel<<<g, 256, FA_SMEM>>>(pqkv, rel_tab + (size_t)l * NREL * HEADS,
                                                   rel_idx, po);
        }
        // proj (+residual)
        packA(po, pa, M, 768, 768, 768, 1, 0, 0, 1, 0, 1.0f, 1);
        packB(proj_w + (size_t)l * 768 * 768, pb, 768, 768, 768, 768, 1, 0, 0, 1, 0, 1);
        gemm_tc(pa, pb, pt, proj_b + l * EMB, pt, M, 768, 2304, 2304, 2304, 0, 0,
                768, 0, 0, 1, 0, 1);
        // MLP
        ln_kernel<<<M, 256>>>(pt, ln2_w + l * EMB, ln2_b + l * EMB, ph);
        packA(ph, pa, M, 768, 768, 768, 1, 0, 0, 1, 0, 1.0f, 1);
        packB(fc1_w + (size_t)l * 3072 * 768, pb, 3072, 768, 768, 768, 1, 0, 0, 1, 0, 1);
        gemm_tc(pa, pb, pmlp, fc1_b + l * 4 * EMB, nullptr, M, 3072, 2304, 2304, 2304, 0, 0,
                3072, 0, 0, 1, 1, 1);
        packA(pmlp, pa, M, 3072, 3072, 3072, 1, 0, 0, 1, 0, 1.0f, 1);
        packB(fc2_w + (size_t)l * 768 * 3072, pb, 768, 3072, 3072, 3072, 1, 0, 0, 1, 0, 1);
        gemm_tc(pa, pb, pt, fc2_b + l * EMB, pt, M, 768, 9216, 9216, 9216, 0, 0,
                768, 0, 0, 1, 0, 1);
        float* fdst = nullptr;
        if (l == 3) fdst = pf0;
        else if (l == 5) fdst = pf1;
        else if (l == 7) fdst = pf2;
        else if (l == 11) fdst = pf3;
        if (fdst) copy_kernel<<<(TOKELEMS + 255) / 256, 256>>>(pt, fdst, TOKELEMS);
    }

    // ---- o3 / o4 ----
    to_map_kernel<<<(BATCH * 768 * 1024 + 255) / 256, 256>>>(pf2, out3);
    maxpool_kernel<<<(BATCH * 768 * 256 + 255) / 256, 256>>>(pf3, out4);

    // ---- fpn1 stage 1 ----
    repack_w_kernel<<<(3072 * 768 + 255) / 256, 256>>>(d1_w, pwp);
    packB(pwp, pb, 3072, 768, 768, 768, 1, 0, 0, 1, 0, 1);
    packA(pf0 + 768, pa, 1024, 768, 768, 768, 1, (size_t)NT * 768, 0, 1,
          (size_t)1024 * 2304, 1.0f, BATCH);
    gemm_tc(pa, pb, ptmp, nullptr, nullptr, 1024, 3072, 2304, 2304, 2304,
            (size_t)1024 * 2304, 0, 3072, (size_t)1024 * 3072, 0, 1, 0, BATCH);
    scatter_bhwc_kernel<<<(BATCH * 1024 * 3072 + 255) / 256, 256>>>(ptmp, d1_b, py, 32);
    bn_gelu_kernel<<<(BATCH * 64 * 64 * 768 + 255) / 256, 256>>>(py, bn_w, bn_b, bn_mean, bn_var);

    // ---- fpn1 stage 2 ----
    repack_w_kernel<<<(3072 * 768 + 255) / 256, 256>>>(d2_w, pwp);
    packB(pwp, pb, 3072, 768, 768, 768, 1, 0, 0, 1, 0, 1);
    packA(py, pa, 4096, 768, 768, 768, 1, (size_t)4096 * 768, 0, 1,
          (size_t)4096 * 2304, 1.0f, BATCH);
    gemm_tc(pa, pb, ptmp, nullptr, nullptr, 4096, 3072, 2304, 2304, 2304,
            (size_t)4096 * 2304, 0, 3072, (size_t)4096 * 3072, 0, 1, 0, BATCH);
    scatter_bchw_kernel<<<(BATCH * 4096 * 3072 + 255) / 256, 256>>>(ptmp, d2_b, out1, 64);

    // ---- o2 ----
    repack_w_kernel<<<(3072 * 768 + 255) / 256, 256>>>(f2w, pwp);
    packB(pwp, pb, 3072, 768, 768, 768, 1, 0, 0, 1, 0, 1);
    packA(pf1 + 768, pa, 1024, 768, 768, 768, 1, (size_t)NT * 768, 0, 1,
          (size_t)1024 * 2304, 1.0f, BATCH);
    gemm_tc(pa, pb, ptmp, nullptr, nullptr, 1024, 3072, 2304, 2304, 2304,
            (size_t)1024 * 2304, 0, 3072, (size_t)1024 * 3072, 0, 1, 0, BATCH);
    scatter_bchw_kernel<<<(BATCH * 1024 * 3072 + 255) / 256, 256>>>(ptmp, f2b, out2, 32);

    (void)in_sizes; (void)n_in; (void)out_size;
}

// round 6
// speedup vs baseline: 2.5322x; 1.0625x over previous
#include <cuda_runtime.h>
#include <cuda_bf16.h>
#include <math.h>
#include <stdint.h>

#define NT    1025
#define EMB   768
#define BATCH 2
#define HEADS 12
#define NREL  3972

// ------------------------- device scratch (no allocs allowed) ---------------
__device__ float g_t[BATCH * NT * EMB];
__device__ float g_h[BATCH * NT * EMB];
__device__ float g_qkv[BATCH * NT * 3 * EMB];
__device__ float g_o[BATCH * NT * EMB];
__device__ float g_mlp[BATCH * NT * 4 * EMB];
__device__ float g_patch[BATCH * 1024 * EMB];
__device__ float g_tok[BATCH * 1024 * EMB];
__device__ float g_feat0[BATCH * NT * EMB];
__device__ float g_feat1[BATCH * NT * EMB];
__device__ float g_feat2[BATCH * NT * EMB];
__device__ float g_feat3[BATCH * NT * EMB];
__device__ float g_y[BATCH * 64 * 64 * EMB];
__device__ float g_tmp[(size_t)BATCH * 4096 * 3072];
__device__ float g_wpack[3072 * 768];
__device__ float g_qkvbias[3 * EMB];
__device__ __nv_bfloat16 g_pa[20000000];
__device__ __nv_bfloat16 g_pb[7500000];

__device__ __forceinline__ float gelu_exact(float x) {
    return 0.5f * x * (1.0f + erff(x * 0.70710678118654752f));
}

__device__ __forceinline__ uint32_t smem_u32(const void* p) {
    uint32_t a;
    asm("{ .reg .u64 t; cvta.to.shared.u64 t, %1; cvt.u32.u64 %0, t; }" : "=r"(a) : "l"(p));
    return a;
}

#define LDSM_X4(r0, r1, r2, r3, addr) \
    asm volatile("ldmatrix.sync.aligned.m8n8.x4.shared.b16 {%0,%1,%2,%3}, [%4];" \
                 : "=r"(r0), "=r"(r1), "=r"(r2), "=r"(r3) : "r"(addr))

#define MMA16816(d, a0, a1, a2, a3, b0, b1) \
    asm volatile("mma.sync.aligned.m16n8k16.row.col.f32.bf16.bf16.f32 " \
                 "{%0,%1,%2,%3}, {%4,%5,%6,%7}, {%8,%9}, {%0,%1,%2,%3};" \
                 : "+f"((d)[0]), "+f"((d)[1]), "+f"((d)[2]), "+f"((d)[3]) \
                 : "r"(a0), "r"(a1), "r"(a2), "r"(a3), "r"(b0), "r"(b1))

#define CP_ASYNC16(dst, src, sz) \
    asm volatile("cp.async.cg.shared.global [%0], [%1], 16, %2;" \
                 :: "r"(dst), "l"(src), "r"(sz))

__device__ __forceinline__ uint32_t pack_bf16(float x, float y) {
    __nv_bfloat162 t = __floats2bfloat162_rn(x, y);
    return *(uint32_t*)&t;
}

// ========================= split-bf16 pack kernels ==========================
__global__ void packA_kernel(const float* __restrict__ in, __nv_bfloat16* __restrict__ out,
                             int M, int K, int Kp, size_t irs, size_t ics,
                             size_t ibs0, size_t ibs1, int nh, size_t obs, float scale) {
    int idx = blockIdx.x * 256 + threadIdx.x;
    int z = blockIdx.y;
    if (idx >= M * Kp) return;
    int k = idx % Kp, m = idx / Kp;
    const float* src = in + (size_t)(z / nh) * ibs0 + (size_t)(z % nh) * ibs1;
    float v = (k < K) ? src[(size_t)m * irs + (size_t)k * ics] * scale : 0.f;
    __nv_bfloat16 hi = __float2bfloat16(v);
    __nv_bfloat16 lo = __float2bfloat16(v - __bfloat162float(hi));
    __nv_bfloat16* o = out + (size_t)z * obs + (size_t)m * (3 * (size_t)Kp);
    o[k] = hi; o[Kp + k] = lo; o[2 * Kp + k] = hi;
}
__global__ void packB_kernel(const float* __restrict__ in, __nv_bfloat16* __restrict__ out,
                             int M, int K, int Kp, size_t irs, size_t ics,
                             size_t ibs0, size_t ibs1, int nh, size_t obs, float scale) {
    int idx = blockIdx.x * 256 + threadIdx.x;
    int z = blockIdx.y;
    if (idx >= M * Kp) return;
    int k = idx % Kp, m = idx / Kp;
    const float* src = in + (size_t)(z / nh) * ibs0 + (size_t)(z % nh) * ibs1;
    float v = (k < K) ? src[(size_t)m * irs + (size_t)k * ics] * scale : 0.f;
    __nv_bfloat16 hi = __float2bfloat16(v);
    __nv_bfloat16 lo = __float2bfloat16(v - __bfloat162float(hi));
    __nv_bfloat16* o = out + (size_t)z * obs + (size_t)m * (3 * (size_t)Kp);
    o[k] = hi; o[Kp + k] = hi; o[2 * Kp + k] = lo;
}

// ========================= HMMA GEMM (mma.sync bf16) ========================
// 4-stage cp.async ring pipeline, dynamic smem. One __syncthreads per chunk.
template <int BN>
__global__ void __launch_bounds__(256, 2) hgemm(
    const __nv_bfloat16* __restrict__ A, const __nv_bfloat16* __restrict__ B,
    float* __restrict__ C, const float* __restrict__ bias, const float* __restrict__ resid,
    int M, int Nreal, int Ktot, size_t lda, size_t ldb, size_t Abs, size_t Bbs,
    size_t ldc, size_t cs0, size_t cs1, int nh, int do_gelu) {
    constexpr int WTN = BN / 4;
    constexpr int NT8 = WTN / 8;
    constexpr int NB4 = BN / 64;
    constexpr int STAGE = (128 + BN) * 40;      // bf16 elements per stage
    extern __shared__ __nv_bfloat16 dsm[];

    int tid = threadIdx.x;
    int wid = tid >> 5, lane = tid & 31;
    int warp_m = wid >> 2, warp_n = wid & 3;
    int m0 = blockIdx.y * 128, n0 = blockIdx.x * BN;
    int z = blockIdx.z;

    const __nv_bfloat16* Az = A + (size_t)z * Abs;
    const __nv_bfloat16* Bz = B + (size_t)z * Bbs;

    float acc[4][NT8][4];
#pragma unroll
    for (int i = 0; i < 4; i++)
#pragma unroll
        for (int j = 0; j < NT8; j++)
#pragma unroll
            for (int e = 0; e < 4; e++) acc[i][j][e] = 0.f;

    int nk = Ktot >> 5;

    auto load_body = [&](int c, int s) {
        __nv_bfloat16* sA = dsm + s * STAGE;
        __nv_bfloat16* sB = sA + 128 * 40;
#pragma unroll
        for (int i = 0; i < 2; i++) {
            int idx = tid + i * 256, row = idx >> 2, cg = idx & 3;
            uint32_t dst = smem_u32(sA + row * 40 + cg * 8);
            const __nv_bfloat16* src = Az + (size_t)(m0 + row) * lda + c * 32 + cg * 8;
            CP_ASYNC16(dst, src, (m0 + row < M) ? 16 : 0);
        }
#pragma unroll
        for (int i = 0; i < NB4; i++) {
            int idx = tid + i * 256, row = idx >> 2, cg = idx & 3;
            uint32_t dst = smem_u32(sB + row * 40 + cg * 8);
            const __nv_bfloat16* src = Bz + (size_t)(n0 + row) * ldb + c * 32 + cg * 8;
            CP_ASYNC16(dst, src, (n0 + row < Nreal) ? 16 : 0);
        }
    };

    // prologue: stages 0..2 (always commit 3 groups)
#pragma unroll
    for (int s = 0; s < 3; s++) {
        if (s < nk) load_body(s, s);
        asm volatile("cp.async.commit_group;");
    }

    for (int c = 0; c < nk; c++) {
        asm volatile("cp.async.wait_group 2;");
        __syncthreads();
        {
            int ncd = c + 3;
            if (ncd < nk) load_body(ncd, ncd & 3);
            asm volatile("cp.async.commit_group;");
        }
        int s = c & 3;
        __nv_bfloat16* sA = dsm + s * STAGE;
        __nv_bfloat16* sB = sA + 128 * 40;
#pragma unroll
        for (int kk = 0; kk < 2; kk++) {
            uint32_t af[4][4];
#pragma unroll
            for (int mt = 0; mt < 4; mt++) {
                uint32_t addr = smem_u32(sA + (warp_m * 64 + mt * 16 + (lane & 15)) * 40 +
                                         kk * 16 + (lane >> 4) * 8);
                LDSM_X4(af[mt][0], af[mt][1], af[mt][2], af[mt][3], addr);
            }
            uint32_t bf[NT8][2];
#pragma unroll
            for (int p = 0; p < NT8 / 2; p++) {
                uint32_t addr = smem_u32(sB + (warp_n * WTN + p * 16 + ((lane >> 4) << 3) + (lane & 7)) * 40 +
                                         kk * 16 + ((lane >> 3) & 1) * 8);
                LDSM_X4(bf[2 * p][0], bf[2 * p][1], bf[2 * p + 1][0], bf[2 * p + 1][1], addr);
            }
#pragma unroll
            for (int mt = 0; mt < 4; mt++)
#pragma unroll
                for (int nt = 0; nt < NT8; nt++)
                    MMA16816(acc[mt][nt], af[mt][0], af[mt][1], af[mt][2], af[mt][3],
                             bf[nt][0], bf[nt][1]);
        }
    }

    size_t cbase = (size_t)(z / nh) * cs0 + (size_t)(z % nh) * cs1;
    int mrow = lane >> 2, ncol = (lane & 3) * 2;
#pragma unroll
    for (int mt = 0; mt < 4; mt++) {
#pragma unroll
        for (int half = 0; half < 2; half++) {
            int row = m0 + warp_m * 64 + mt * 16 + mrow + half * 8;
            if (row >= M) continue;
#pragma unroll
            for (int nt = 0; nt < NT8; nt++) {
#pragma unroll
                for (int e = 0; e < 2; e++) {
                    int col = n0 + warp_n * WTN + nt * 8 + ncol + e;
                    if (col >= Nreal) continue;
                    float v = acc[mt][nt][half * 2 + e];
                    if (bias) v += bias[col];
                    size_t off = cbase + (size_t)row * ldc + col;
                    if (resid) v += resid[off];
                    if (do_gelu) v = gelu_exact(v);
                    C[off] = v;
                }
            }
        }
    }
}

// ========================= fused flash attention ============================
#define FA_LD 136
__global__ void __launch_bounds__(256, 2) flash_attn_kernel(
    const float* __restrict__ qkv, const float* __restrict__ relt,
    const int* __restrict__ relidx, float* __restrict__ o) {
    extern __shared__ __nv_bfloat16 fsm[];
    __nv_bfloat16* sQ = fsm;
    __nv_bfloat16* sK = fsm + 128 * FA_LD;
    __nv_bfloat16* sV = sK + 64 * FA_LD;

    int tid = threadIdx.x, wid = tid >> 5, lane = tid & 31;
    int i0 = blockIdx.x * 128;
    int z = blockIdx.y;
    int b = z / HEADS, h = z % HEADS;
    const float* qb = qkv + (size_t)b * NT * 2304 + h * 64;
    const float* kb = qb + 768;
    const float* vb = qb + 1536;

    for (int idx = tid; idx < 128 * 64; idx += 256) {
        int r = idx >> 6, c = idx & 63;
        int gi = i0 + r;
        float v = (gi < NT) ? qb[(size_t)gi * 2304 + c] * 0.125f : 0.f;
        __nv_bfloat16 hi = __float2bfloat16(v);
        sQ[r * FA_LD + c] = hi;
        sQ[r * FA_LD + 64 + c] = __float2bfloat16(v - __bfloat162float(hi));
    }

    float m0 = -1e30f, m1 = -1e30f, l0 = 0.f, l1 = 0.f;
    float O[8][4];
#pragma unroll
    for (int t = 0; t < 8; t++)
#pragma unroll
        for (int e = 0; e < 4; e++) O[t][e] = 0.f;

    int r0g = i0 + wid * 16 + (lane >> 2);
    int r1g = r0g + 8;

    for (int j0 = 0; j0 < NT; j0 += 64) {
        __syncthreads();
        for (int idx = tid; idx < 64 * 64; idx += 256) {
            int r = idx >> 6, c = idx & 63;
            int gj = j0 + r;
            float kv = (gj < NT) ? kb[(size_t)gj * 2304 + c] : 0.f;
            __nv_bfloat16 khi = __float2bfloat16(kv);
            sK[r * FA_LD + c] = khi;
            sK[r * FA_LD + 64 + c] = __float2bfloat16(kv - __bfloat162float(khi));
            float vv = (gj < NT) ? vb[(size_t)gj * 2304 + c] : 0.f;
            __nv_bfloat16 vhi = __float2bfloat16(vv);
            sV[c * FA_LD + r] = vhi;
            sV[c * FA_LD + 64 + r] = __float2bfloat16(vv - __bfloat162float(vhi));
        }
        __syncthreads();

        float S[8][4];
#pragma unroll
        for (int t = 0; t < 8; t++)
#pragma unroll
            for (int e = 0; e < 4; e++) S[t][e] = 0.f;

        const int qsec[3] = {0, 1, 0}, ksec[3] = {0, 0, 1};
#pragma unroll
        for (int sp = 0; sp < 3; sp++) {
#pragma unroll
            for (int kk = 0; kk < 4; kk++) {
                uint32_t a0, a1, a2, a3;
                uint32_t addr = smem_u32(&sQ[(wid * 16 + (lane & 15)) * FA_LD +
                                             qsec[sp] * 64 + kk * 16 + (lane >> 4) * 8]);
                LDSM_X4(a0, a1, a2, a3, addr);
                uint32_t bf[8][2];
#pragma unroll
                for (int p = 0; p < 4; p++) {
                    uint32_t ba = smem_u32(&sK[(p * 16 + ((lane >> 4) << 3) + (lane & 7)) * FA_LD +
                                               ksec[sp] * 64 + kk * 16 + ((lane >> 3) & 1) * 8]);
                    LDSM_X4(bf[2 * p][0], bf[2 * p][1], bf[2 * p + 1][0], bf[2 * p + 1][1], ba);
                }
#pragma unroll
                for (int nt = 0; nt < 8; nt++)
                    MMA16816(S[nt], a0, a1, a2, a3, bf[nt][0], bf[nt][1]);
            }
        }

#pragma unroll
        for (int nt = 0; nt < 8; nt++) {
            int c0 = j0 + nt * 8 + (lane & 3) * 2;
#pragma unroll
            for (int e = 0; e < 2; e++) {
                int jj = c0 + e;
                if (jj < NT) {
                    if (r0g < NT) S[nt][e]     += relt[(size_t)relidx[(size_t)r0g * NT + jj] * HEADS + h];
                    if (r1g < NT) S[nt][2 + e] += relt[(size_t)relidx[(size_t)r1g * NT + jj] * HEADS + h];
                } else {
                    S[nt][e] = -1e30f;
                    S[nt][2 + e] = -1e30f;
                }
            }
        }

        float t0 = -1e30f, t1 = -1e30f;
#pragma unroll
        for (int nt = 0; nt < 8; nt++) {
            t0 = fmaxf(t0, fmaxf(S[nt][0], S[nt][1]));
            t1 = fmaxf(t1, fmaxf(S[nt][2], S[nt][3]));
        }
        t0 = fmaxf(t0, __shfl_xor_sync(0xffffffff, t0, 1));
        t0 = fmaxf(t0, __shfl_xor_sync(0xffffffff, t0, 2));
        t1 = fmaxf(t1, __shfl_xor_sync(0xffffffff, t1, 1));
        t1 = fmaxf(t1, __shfl_xor_sync(0xffffffff, t1, 2));
        float mn0 = fmaxf(m0, t0), mn1 = fmaxf(m1, t1);
        float al0 = __expf(m0 - mn0), al1 = __expf(m1 - mn1);
#pragma unroll
        for (int nt = 0; nt < 8; nt++) {
            O[nt][0] *= al0; O[nt][1] *= al0;
            O[nt][2] *= al1; O[nt][3] *= al1;
        }
        float ls0 = 0.f, ls1 = 0.f;
        uint32_t phi[4][4], plo[4][4];
#pragma unroll
        for (int kk = 0; kk < 4; kk++) {
#pragma unroll
            for (int tt = 0; tt < 2; tt++) {
                int t = 2 * kk + tt;
                float p0 = __expf(S[t][0] - mn0), p1 = __expf(S[t][1] - mn0);
                float p2 = __expf(S[t][2] - mn1), p3 = __expf(S[t][3] - mn1);
                ls0 += p0 + p1; ls1 += p2 + p3;
                float h0 = __bfloat162float(__float2bfloat16(p0));
                float h1 = __bfloat162float(__float2bfloat16(p1));
                float h2 = __bfloat162float(__float2bfloat16(p2));
                float h3 = __bfloat162float(__float2bfloat16(p3));
                phi[kk][tt * 2]     = pack_bf16(h0, h1);
                phi[kk][tt * 2 + 1] = pack_bf16(h2, h3);
                plo[kk][tt * 2]     = pack_bf16(p0 - h0, p1 - h1);
                plo[kk][tt * 2 + 1] = pack_bf16(p2 - h2, p3 - h3);
            }
        }
        ls0 += __shfl_xor_sync(0xffffffff, ls0, 1);
        ls0 += __shfl_xor_sync(0xffffffff, ls0, 2);
        ls1 += __shfl_xor_sync(0xffffffff, ls1, 1);
        ls1 += __shfl_xor_sync(0xffffffff, ls1, 2);
        l0 = l0 * al0 + ls0;
        l1 = l1 * al1 + ls1;
        m0 = mn0; m1 = mn1;

        const int vsec[3] = {0, 0, 1};
#pragma unroll
        for (int sp = 0; sp < 3; sp++) {
#pragma unroll
            for (int kk = 0; kk < 4; kk++) {
                uint32_t* A = (sp == 1) ? plo[kk] : phi[kk];
                uint32_t bf[8][2];
#pragma unroll
                for (int p = 0; p < 4; p++) {
                    uint32_t ba = smem_u32(&sV[(p * 16 + ((lane >> 4) << 3) + (lane & 7)) * FA_LD +
                                               vsec[sp] * 64 + kk * 16 + ((lane >> 3) & 1) * 8]);
                    LDSM_X4(bf[2 * p][0], bf[2 * p][1], bf[2 * p + 1][0], bf[2 * p + 1][1], ba);
                }
#pragma unroll
                for (int nt = 0; nt < 8; nt++)
                    MMA16816(O[nt], A[0], A[1], A[2], A[3], bf[nt][0], bf[nt][1]);
            }
        }
    }

    float il0 = 1.0f / l0, il1 = 1.0f / l1;
#pragma unroll
    for (int nt = 0; nt < 8; nt++) {
        int d = h * 64 + nt * 8 + (lane & 3) * 2;
        if (r0g < NT) {
            float2 v = make_float2(O[nt][0] * il0, O[nt][1] * il0);
            *(float2*)&o[((size_t)b * NT + r0g) * EMB + d] = v;
        }
        if (r1g < NT) {
            float2 v = make_float2(O[nt][2] * il1, O[nt][3] * il1);
            *(float2*)&o[((size_t)b * NT + r1g) * EMB + d] = v;
        }
    }
}

// ------------------------- elementwise helpers ------------------------------
__global__ void patchify_kernel(const float* __restrict__ x, float* __restrict__ A) {
    int idx = blockIdx.x * 256 + threadIdx.x;
    if (idx >= BATCH * 1024 * EMB) return;
    int col = idx % EMB;
    int m = idx / EMB;
    int b = m / 1024, g = m % 1024;
    int gh = g / 32, gw = g % 32;
    int c = col / 256, rem = col % 256;
    int i = rem / 16, j = rem % 16;
    A[idx] = x[(((size_t)(b * 3 + c) * 512) + gh * 16 + i) * 512 + gw * 16 + j];
}

__global__ void assemble_kernel(const float* __restrict__ tok, const float* __restrict__ cls,
                                const float* __restrict__ pos, float* __restrict__ t) {
    int idx = blockIdx.x * 256 + threadIdx.x;
    if (idx >= BATCH * NT * EMB) return;
    int d = idx % EMB;
    int n = (idx / EMB) % NT;
    int b = idx / (EMB * NT);
    float v = (n == 0) ? cls[d] : tok[((size_t)b * 1024 + (n - 1)) * EMB + d];
    t[idx] = v + pos[n * EMB + d];
}

__global__ void ln_kernel(const float* __restrict__ x, const float* __restrict__ w,
                          const float* __restrict__ b, float* __restrict__ out) {
    int r = blockIdx.x;
    const float* xr = x + (size_t)r * EMB;
    __shared__ float red[256];
    int tid = threadIdx.x;
    float s = 0.f;
    for (int i = tid; i < EMB; i += 256) s += xr[i];
    red[tid] = s; __syncthreads();
    for (int st = 128; st > 0; st >>= 1) { if (tid < st) red[tid] += red[tid + st]; __syncthreads(); }
    float mean = red[0] * (1.0f / EMB);
    __syncthreads();
    float s2 = 0.f;
    for (int i = tid; i < EMB; i += 256) { float d = xr[i] - mean; s2 += d * d; }
    red[tid] = s2; __syncthreads();
    for (int st = 128; st > 0; st >>= 1) { if (tid < st) red[tid] += red[tid + st]; __syncthreads(); }
    float inv = rsqrtf(red[0] * (1.0f / EMB) + 1e-6f);
    for (int i = tid; i < EMB; i += 256)
        out[(size_t)r * EMB + i] = (xr[i] - mean) * inv * w[i] + b[i];
}

__global__ void biaspack_kernel(const float* __restrict__ qb, const float* __restrict__ vb,
                                float* __restrict__ out) {
    int i = blockIdx.x * 256 + threadIdx.x;
    if (i >= 3 * EMB) return;
    out[i] = (i < EMB) ? qb[i] : ((i < 2 * EMB) ? 0.f : vb[i - 2 * EMB]);
}

__global__ void copy_kernel(const float* __restrict__ src, float* __restrict__ dst, int n) {
    int i = blockIdx.x * 256 + threadIdx.x;
    if (i < n) dst[i] = src[i];
}

__global__ void repack_w_kernel(const float* __restrict__ w, float* __restrict__ wp) {
    int idx = blockIdx.x * 256 + threadIdx.x;
    if (idx >= 3072 * 768) return;
    int c = idx % 768, n = idx / 768;
    int ij = n / 768, d = n % 768;
    wp[idx] = w[(size_t)c * 3072 + d * 4 + ij];
}

__global__ void scatter_bhwc_kernel(const float* __restrict__ tmp, const float* __restrict__ bias,
                                    float* __restrict__ y, int HW) {
    int total = BATCH * HW * HW * 4 * 768;
    int idx = blockIdx.x * 256 + threadIdx.x;
    if (idx >= total) return;
    int d = idx % 768;
    int ij = (idx / 768) % 4;
    int p = (idx / 3072) % (HW * HW);
    int b = idx / (3072 * HW * HW);
    int h = p / HW, w = p % HW, i = ij / 2, j = ij % 2;
    int W2 = 2 * HW;
    y[(((size_t)b * W2 + 2 * h + i) * W2 + (2 * w + j)) * 768 + d] = tmp[idx] + bias[d];
}

__global__ void scatter_bchw_kernel(const float* __restrict__ tmp, const float* __restrict__ bias,
                                    float* __restrict__ out, int HW) {
    int total = BATCH * HW * HW * 4 * 768;
    int idx = blockIdx.x * 256 + threadIdx.x;
    if (idx >= total) return;
    int d = idx % 768;
    int ij = (idx / 768) % 4;
    int p = (idx / 3072) % (HW * HW);
    int b = idx / (3072 * HW * HW);
    int h = p / HW, w = p % HW, i = ij / 2, j = ij % 2;
    int W2 = 2 * HW;
    out[(((size_t)b * 768 + d) * W2 + 2 * h + i) * W2 + (2 * w + j)] = tmp[idx] + bias[d];
}

__global__ void bn_gelu_kernel(float* __restrict__ y, const float* __restrict__ w,
                               const float* __restrict__ b, const float* __restrict__ mean,
                               const float* __restrict__ var) {
    int idx = blockIdx.x * 256 + threadIdx.x;
    if (idx >= BATCH * 64 * 64 * 768) return;
    int c = idx % 768;
    float v = y[idx];
    v = (v - mean[c]) * rsqrtf(var[c] + 1e-5f) * w[c] + b[c];
    y[idx] = gelu_exact(v);
}

__global__ void to_map_kernel(const float* __restrict__ feat, float* __restrict__ out) {
    int idx = blockIdx.x * 256 + threadIdx.x;
    if (idx >= BATCH * 768 * 32 * 32) return;
    int xw = idx % 32;
    int yh = (idx / 32) % 32;
    int c = (idx / 1024) % 768;
    int b = idx / (1024 * 768);
    out[idx] = feat[((size_t)b * NT + 1 + yh * 32 + xw) * EMB + c];
}

__global__ void maxpool_kernel(const float* __restrict__ feat, float* __restrict__ out) {
    int idx = blockIdx.x * 256 + threadIdx.x;
    if (idx >= BATCH * 768 * 16 * 16) return;
    int xw = idx % 16;
    int yh = (idx / 16) % 16;
    int c = (idx / 256) % 768;
    int b = idx / (256 * 768);
    float m = -1e30f;
#pragma unroll
    for (int i = 0; i < 2; i++)
#pragma unroll
        for (int j = 0; j < 2; j++) {
            int Y = 2 * yh + i, X = 2 * xw + j;
            m = fmaxf(m, feat[((size_t)b * NT + 1 + Y * 32 + X) * EMB + c]);
        }
    out[idx] = m;
}

// ------------------------- host helpers -------------------------------------
static void packA(const float* in, __nv_bfloat16* out, int M, int K, int Kp,
                  size_t irs, size_t ics, size_t ibs0, size_t ibs1, int nh,
                  size_t obs, float scale, int nz) {
    dim3 g((M * Kp + 255) / 256, nz);
    packA_kernel<<<g, 256>>>(in, out, M, K, Kp, irs, ics, ibs0, ibs1, nh, obs, scale);
}
static void packB(const float* in, __nv_bfloat16* out, int M, int K, int Kp,
                  size_t irs, size_t ics, size_t ibs0, size_t ibs1, int nh,
                  size_t obs, int nz) {
    dim3 g((M * Kp + 255) / 256, nz);
    packB_kernel<<<g, 256>>>(in, out, M, K, Kp, irs, ics, ibs0, ibs1, nh, obs, 1.0f);
}
#define SMEM64  (4 * (128 + 64) * 40 * 2)
#define SMEM128 (4 * (128 + 128) * 40 * 2)
static void gemm_tc(const __nv_bfloat16* A, const __nv_bfloat16* B, float* C,
                    const float* bias, const float* resid, int M, int N, int Ktot,
                    size_t lda, size_t ldb, size_t Abs, size_t Bbs, size_t ldc,
                    size_t cs0, size_t cs1, int nh, int gelu, int nz) {
    int gm = (M + 127) / 128;
    int g128 = ((N + 127) / 128) * gm * nz;
    if (N % 64 == 0 && (N % 128 != 0 || g128 < 148)) {
        dim3 g(N / 64, gm, nz);
        hgemm<64><<<g, 256, SMEM64>>>(A, B, C, bias, resid, M, N, Ktot, lda, ldb, Abs, Bbs,
                                      ldc, cs0, cs1, nh, gelu);
    } else {
        dim3 g((N + 127) / 128, gm, nz);
        hgemm<128><<<g, 256, SMEM128>>>(A, B, C, bias, resid, M, N, Ktot, lda, ldb, Abs, Bbs,
                                        ldc, cs0, cs1, nh, gelu);
    }
}

extern "C" void kernel_launch(void* const* d_in, const int* in_sizes, int n_in,
                              void* d_out, int out_size) {
    const float* x         = (const float*)d_in[0];
    const float* patch_w   = (const float*)d_in[1];
    const float* patch_b   = (const float*)d_in[2];
    const float* cls_token = (const float*)d_in[3];
    const float* pos_embed = (const float*)d_in[4];
    const float* ln1_w     = (const float*)d_in[5];
    const float* ln1_b     = (const float*)d_in[6];
    const float* qkv_w     = (const float*)d_in[7];
    const float* q_bias    = (const float*)d_in[8];
    const float* v_bias    = (const float*)d_in[9];
    const float* rel_tab   = (const float*)d_in[10];
    const float* proj_w    = (const float*)d_in[11];
    const float* proj_b    = (const float*)d_in[12];
    const float* ln2_w     = (const float*)d_in[13];
    const float* ln2_b     = (const float*)d_in[14];
    const float* fc1_w     = (const float*)d_in[15];
    const float* fc1_b     = (const float*)d_in[16];
    const float* fc2_w     = (const float*)d_in[17];
    const float* fc2_b     = (const float*)d_in[18];
    const float* d1_w      = (const float*)d_in[19];
    const float* d1_b      = (const float*)d_in[20];
    const float* bn_w      = (const float*)d_in[21];
    const float* bn_b      = (const float*)d_in[22];
    const float* bn_mean   = (const float*)d_in[23];
    const float* bn_var    = (const float*)d_in[24];
    const float* d2_w      = (const float*)d_in[25];
    const float* d2_b      = (const float*)d_in[26];
    const float* f2w       = (const float*)d_in[27];
    const float* f2b       = (const float*)d_in[28];
    const int*   rel_idx   = (const int*)d_in[29];

    float* out = (float*)d_out;
    float* out1 = out;
    float* out2 = out1 + (size_t)BATCH * 768 * 128 * 128;
    float* out3 = out2 + (size_t)BATCH * 768 * 64 * 64;
    float* out4 = out3 + (size_t)BATCH * 768 * 32 * 32;

    static float *pt = nullptr, *ph, *pqkv, *po, *pmlp, *ppatch, *ptok;
    static float *pf0, *pf1, *pf2, *pf3, *py, *ptmp, *pwp, *pqb;
    static __nv_bfloat16 *pa, *pb;
    if (!pt) {
        cudaGetSymbolAddress((void**)&pt, g_t);
        cudaGetSymbolAddress((void**)&ph, g_h);
        cudaGetSymbolAddress((void**)&pqkv, g_qkv);
        cudaGetSymbolAddress((void**)&po, g_o);
        cudaGetSymbolAddress((void**)&pmlp, g_mlp);
        cudaGetSymbolAddress((void**)&ppatch, g_patch);
        cudaGetSymbolAddress((void**)&ptok, g_tok);
        cudaGetSymbolAddress((void**)&pf0, g_feat0);
        cudaGetSymbolAddress((void**)&pf1, g_feat1);
        cudaGetSymbolAddress((void**)&pf2, g_feat2);
        cudaGetSymbolAddress((void**)&pf3, g_feat3);
        cudaGetSymbolAddress((void**)&py, g_y);
        cudaGetSymbolAddress((void**)&ptmp, g_tmp);
        cudaGetSymbolAddress((void**)&pwp, g_wpack);
        cudaGetSymbolAddress((void**)&pqb, g_qkvbias);
        cudaGetSymbolAddress((void**)&pa, g_pa);
        cudaGetSymbolAddress((void**)&pb, g_pb);
        cudaFuncSetAttribute(flash_attn_kernel,
                             cudaFuncAttributeMaxDynamicSharedMemorySize,
                             (128 + 64 + 64) * FA_LD * 2);
        cudaFuncSetAttribute(hgemm<64>,
                             cudaFuncAttributeMaxDynamicSharedMemorySize, SMEM64);
        cudaFuncSetAttribute(hgemm<128>,
                             cudaFuncAttributeMaxDynamicSharedMemorySize, SMEM128);
    }

    const int TOKELEMS = BATCH * NT * EMB;
    const int M = BATCH * NT;  // 2050
    const int FA_SMEM = (128 + 64 + 64) * FA_LD * 2;

    // ---- patch embed ----
    patchify_kernel<<<(BATCH * 1024 * EMB + 255) / 256, 256>>>(x, ppatch);
    packA(ppatch, pa, 2048, 768, 768, 768, 1, 0, 0, 1, 0, 1.0f, 1);
    packB(patch_w, pb, 768, 768, 768, 768, 1, 0, 0, 1, 0, 1);
    gemm_tc(pa, pb, ptok, patch_b, nullptr, 2048, 768, 2304, 2304, 2304, 0, 0,
            768, 0, 0, 1, 0, 1);
    assemble_kernel<<<(TOKELEMS + 255) / 256, 256>>>(ptok, cls_token, pos_embed, pt);

    // ---- transformer layers ----
    for (int l = 0; l < 12; l++) {
        ln_kernel<<<M, 256>>>(pt, ln1_w + l * EMB, ln1_b + l * EMB, ph);
        biaspack_kernel<<<(3 * EMB + 255) / 256, 256>>>(q_bias + l * EMB, v_bias + l * EMB, pqb);
        packA(ph, pa, M, 768, 768, 768, 1, 0, 0, 1, 0, 1.0f, 1);
        packB(qkv_w + (size_t)l * 2304 * 768, pb, 2304, 768, 768, 768, 1, 0, 0, 1, 0, 1);
        gemm_tc(pa, pb, pqkv, pqb, nullptr, M, 2304, 2304, 2304, 2304, 0, 0,
                2304, 0, 0, 1, 0, 1);
        {
            dim3 g((NT + 127) / 128, BATCH * HEADS);
            flash_attn_kernel<<<g, 256, FA_SMEM>>>(pqkv, rel_tab + (size_t)l * NREL * HEADS,
                                                   rel_idx, po);
        }
        packA(po, pa, M, 768, 768, 768, 1, 0, 0, 1, 0, 1.0f, 1);
        packB(proj_w + (size_t)l * 768 * 768, pb, 768, 768, 768, 768, 1, 0, 0, 1, 0, 1);
        gemm_tc(pa, pb, pt, proj_b + l * EMB, pt, M, 768, 2304, 2304, 2304, 0, 0,
                768, 0, 0, 1, 0, 1);
        ln_kernel<<<M, 256>>>(pt, ln2_w + l * EMB, ln2_b + l * EMB, ph);
        packA(ph, pa, M, 768, 768, 768, 1, 0, 0, 1, 0, 1.0f, 1);
        packB(fc1_w + (size_t)l * 3072 * 768, pb, 3072, 768, 768, 768, 1, 0, 0, 1, 0, 1);
        gemm_tc(pa, pb, pmlp, fc1_b + l * 4 * EMB, nullptr, M, 3072, 2304, 2304, 2304, 0, 0,
                3072, 0, 0, 1, 1, 1);
        packA(pmlp, pa, M, 3072, 3072, 3072, 1, 0, 0, 1, 0, 1.0f, 1);
        packB(fc2_w + (size_t)l * 768 * 3072, pb, 768, 3072, 3072, 3072, 1, 0, 0, 1, 0, 1);
        gemm_tc(pa, pb, pt, fc2_b + l * EMB, pt, M, 768, 9216, 9216, 9216, 0, 0,
                768, 0, 0, 1, 0, 1);
        float* fdst = nullptr;
        if (l == 3) fdst = pf0;
        else if (l == 5) fdst = pf1;
        else if (l == 7) fdst = pf2;
        else if (l == 11) fdst = pf3;
        if (fdst) copy_kernel<<<(TOKELEMS + 255) / 256, 256>>>(pt, fdst, TOKELEMS);
    }

    // ---- o3 / o4 ----
    to_map_kernel<<<(BATCH * 768 * 1024 + 255) / 256, 256>>>(pf2, out3);
    maxpool_kernel<<<(BATCH * 768 * 256 + 255) / 256, 256>>>(pf3, out4);

    // ---- fpn1 stage 1 ----
    repack_w_kernel<<<(3072 * 768 + 255) / 256, 256>>>(d1_w, pwp);
    packB(pwp, pb, 3072, 768, 768, 768, 1, 0, 0, 1, 0, 1);
    packA(pf0 + 768, pa, 1024, 768, 768, 768, 1, (size_t)NT * 768, 0, 1,
          (size_t)1024 * 2304, 1.0f, BATCH);
    gemm_tc(pa, pb, ptmp, nullptr, nullptr, 1024, 3072, 2304, 2304, 2304,
            (size_t)1024 * 2304, 0, 3072, (size_t)1024 * 3072, 0, 1, 0, BATCH);
    scatter_bhwc_kernel<<<(BATCH * 1024 * 3072 + 255) / 256, 256>>>(ptmp, d1_b, py, 32);
    bn_gelu_kernel<<<(BATCH * 64 * 64 * 768 + 255) / 256, 256>>>(py, bn_w, bn_b, bn_mean, bn_var);

    // ---- fpn1 stage 2 ----
    repack_w_kernel<<<(3072 * 768 + 255) / 256, 256>>>(d2_w, pwp);
    packB(pwp, pb, 3072, 768, 768, 768, 1, 0, 0, 1, 0, 1);
    packA(py, pa, 4096, 768, 768, 768, 1, (size_t)4096 * 768, 0, 1,
          (size_t)4096 * 2304, 1.0f, BATCH);
    gemm_tc(pa, pb, ptmp, nullptr, nullptr, 4096, 3072, 2304, 2304, 2304,
            (size_t)4096 * 2304, 0, 3072, (size_t)4096 * 3072, 0, 1, 0, BATCH);
    scatter_bchw_kernel<<<(BATCH * 4096 * 3072 + 255) / 256, 256>>>(ptmp, d2_b, out1, 64);

    // ---- o2 ----
    repack_w_kernel<<<(3072 * 768 + 255) / 256, 256>>>(f2w, pwp);
    packB(pwp, pb, 3072, 768, 768, 768, 1, 0, 0, 1, 0, 1);
    packA(pf1 + 768, pa, 1024, 768, 768, 768, 1, (size_t)NT * 768, 0, 1,
          (size_t)1024 * 2304, 1.0f, BATCH);
    gemm_tc(pa, pb, ptmp, nullptr, nullptr, 1024, 3072, 2304, 2304, 2304,
            (size_t)1024 * 2304, 0, 3072, (size_t)1024 * 3072, 0, 1, 0, BATCH);
    scatter_bchw_kernel<<<(BATCH * 1024 * 3072 + 255) / 256, 256>>>(ptmp, f2b, out2, 32);

    (void)in_sizes; (void)n_in; (void)out_size;
}

// round 7
// speedup vs baseline: 2.7119x; 1.0710x over previous
#include <cuda_runtime.h>
#include <cuda_bf16.h>
#include <math.h>
#include <stdint.h>

#define NT    1025
#define EMB   768
#define BATCH 2
#define HEADS 12
#define NREL  3972

// ------------------------- device scratch (no allocs allowed) ---------------
__device__ float g_t[BATCH * NT * EMB];
__device__ float g_h[BATCH * NT * EMB];
__device__ float g_qkv[BATCH * NT * 3 * EMB];
__device__ float g_o[BATCH * NT * EMB];
__device__ float g_mlp[BATCH * NT * 4 * EMB];
__device__ float g_patch[BATCH * 1024 * EMB];
__device__ float g_tok[BATCH * 1024 * EMB];
__device__ float g_feat0[BATCH * NT * EMB];
__device__ float g_feat1[BATCH * NT * EMB];
__device__ float g_feat2[BATCH * NT * EMB];
__device__ float g_feat3[BATCH * NT * EMB];
__device__ float g_y[BATCH * 64 * 64 * EMB];
__device__ float g_tmp[(size_t)BATCH * 4096 * 3072];
__device__ float g_wpack[3072 * 768];
__device__ float g_qkvbias[3 * EMB];
__device__ __nv_bfloat16 g_pa[14000000];   // max: fc2 A 2050*6144 = 12.6M
__device__ __nv_bfloat16 g_pb[5000000];    // max: fc1 B 3072*1536 = 4.7M

__device__ __forceinline__ float gelu_exact(float x) {
    return 0.5f * x * (1.0f + erff(x * 0.70710678118654752f));
}

__device__ __forceinline__ uint32_t smem_u32(const void* p) {
    uint32_t a;
    asm("{ .reg .u64 t; cvta.to.shared.u64 t, %1; cvt.u32.u64 %0, t; }" : "=r"(a) : "l"(p));
    return a;
}

#define LDSM_X4(r0, r1, r2, r3, addr) \
    asm volatile("ldmatrix.sync.aligned.m8n8.x4.shared.b16 {%0,%1,%2,%3}, [%4];" \
                 : "=r"(r0), "=r"(r1), "=r"(r2), "=r"(r3) : "r"(addr))

#define MMA16816(d, a0, a1, a2, a3, b0, b1) \
    asm volatile("mma.sync.aligned.m16n8k16.row.col.f32.bf16.bf16.f32 " \
                 "{%0,%1,%2,%3}, {%4,%5,%6,%7}, {%8,%9}, {%0,%1,%2,%3};" \
                 : "+f"((d)[0]), "+f"((d)[1]), "+f"((d)[2]), "+f"((d)[3]) \
                 : "r"(a0), "r"(a1), "r"(a2), "r"(a3), "r"(b0), "r"(b1))

#define CP_ASYNC16(dst, src, sz) \
    asm volatile("cp.async.cg.shared.global [%0], [%1], 16, %2;" \
                 :: "r"(dst), "l"(src), "r"(sz))

__device__ __forceinline__ uint32_t pack_bf16(float x, float y) {
    __nv_bfloat162 t = __floats2bfloat162_rn(x, y);
    return *(uint32_t*)&t;
}

// ========================= split-bf16 pack (2 sections: [hi|lo]) ============
__global__ void pack_kernel(const float* __restrict__ in, __nv_bfloat16* __restrict__ out,
                            int M, int K, int Kp, size_t irs, size_t ics,
                            size_t ibs0, size_t ibs1, int nh, size_t obs, float scale) {
    int idx = blockIdx.x * 256 + threadIdx.x;
    int z = blockIdx.y;
    if (idx >= M * Kp) return;
    int k = idx % Kp, m = idx / Kp;
    const float* src = in + (size_t)(z / nh) * ibs0 + (size_t)(z % nh) * ibs1;
    float v = (k < K) ? src[(size_t)m * irs + (size_t)k * ics] * scale : 0.f;
    __nv_bfloat16 hi = __float2bfloat16(v);
    __nv_bfloat16 lo = __float2bfloat16(v - __bfloat162float(hi));
    __nv_bfloat16* o = out + (size_t)z * obs + (size_t)m * (2 * (size_t)Kp);
    o[k] = hi; o[Kp + k] = lo;
}

// ========================= HMMA GEMM (split-product reuse) ==================
// Operands packed [hi|lo] along K (row stride 2*Kp). For each 32-K chunk the
// kernel loads Ahi/Alo/Bhi/Blo into smem and issues the 3 products
// S += Ahi*Bhi + Alo*Bhi + Ahi*Blo from the same resident data.
// NSTAGE-ring cp.async pipeline.
template <int BN, int NSTAGE>
__global__ void __launch_bounds__(256, 2) hgemm2(
    const __nv_bfloat16* __restrict__ A, const __nv_bfloat16* __restrict__ B,
    float* __restrict__ C, const float* __restrict__ bias, const float* __restrict__ resid,
    int M, int Nreal, int Kp, size_t Abs, size_t Bbs,
    size_t ldc, size_t cs0, size_t cs1, int nh, int do_gelu) {
    constexpr int WTN = BN / 4;
    constexpr int NT8 = WTN / 8;
    constexpr int NB4 = BN / 64;
    constexpr int AHALF = 128 * 40;           // one A section (bf16 elems)
    constexpr int BHALF = BN * 40;
    constexpr int STAGE = 2 * (AHALF + BHALF);
    extern __shared__ __nv_bfloat16 dsm[];

    int tid = threadIdx.x;
    int wid = tid >> 5, lane = tid & 31;
    int warp_m = wid >> 2, warp_n = wid & 3;
    int m0 = blockIdx.y * 128, n0 = blockIdx.x * BN;
    int z = blockIdx.z;

    const size_t lda = 2 * (size_t)Kp, ldb = 2 * (size_t)Kp;
    const __nv_bfloat16* Az = A + (size_t)z * Abs;
    const __nv_bfloat16* Bz = B + (size_t)z * Bbs;

    float acc[4][NT8][4];
#pragma unroll
    for (int i = 0; i < 4; i++)
#pragma unroll
        for (int j = 0; j < NT8; j++)
#pragma unroll
            for (int e = 0; e < 4; e++) acc[i][j][e] = 0.f;

    int nk = Kp >> 5;

    auto load_body = [&](int c, int s) {
        __nv_bfloat16* st = dsm + s * STAGE;
        // A: 2 sections x 128 rows x 32 bf16
#pragma unroll
        for (int sec = 0; sec < 2; sec++) {
#pragma unroll
            for (int i = 0; i < 2; i++) {
                int idx = tid + i * 256, row = idx >> 2, cg = idx & 3;
                uint32_t dst = smem_u32(st + sec * AHALF + row * 40 + cg * 8);
                const __nv_bfloat16* src = Az + (size_t)(m0 + row) * lda +
                                           (size_t)sec * Kp + c * 32 + cg * 8;
                CP_ASYNC16(dst, src, (m0 + row < M) ? 16 : 0);
            }
        }
#pragma unroll
        for (int sec = 0; sec < 2; sec++) {
#pragma unroll
            for (int i = 0; i < NB4; i++) {
                int idx = tid + i * 256, row = idx >> 2, cg = idx & 3;
                uint32_t dst = smem_u32(st + 2 * AHALF + sec * BHALF + row * 40 + cg * 8);
                const __nv_bfloat16* src = Bz + (size_t)(n0 + row) * ldb +
                                           (size_t)sec * Kp + c * 32 + cg * 8;
                CP_ASYNC16(dst, src, (n0 + row < Nreal) ? 16 : 0);
            }
        }
    };

    // prologue
#pragma unroll
    for (int s = 0; s < NSTAGE - 1; s++) {
        if (s < nk) load_body(s, s);
        asm volatile("cp.async.commit_group;");
    }

    // per-lane ldsm address offsets (elements), hoisted
    uint32_t aoff = (warp_m * 64 + (lane & 15)) * 40 + (lane >> 4) * 8;
    uint32_t boff = (warp_n * WTN + ((lane >> 4) << 3) + (lane & 7)) * 40 + ((lane >> 3) & 1) * 8;
    uint32_t dsm0 = smem_u32(dsm);

    for (int c = 0; c < nk; c++) {
        asm volatile("cp.async.wait_group %0;" :: "n"(NSTAGE - 2));
        __syncthreads();
        {
            int ncd = c + NSTAGE - 1;
            if (ncd < nk) load_body(ncd, ncd % NSTAGE);
            asm volatile("cp.async.commit_group;");
        }
        uint32_t sbase = dsm0 + (c % NSTAGE) * STAGE * 2;          // byte addr
#pragma unroll
        for (int kk = 0; kk < 2; kk++) {
            uint32_t ahi[4][4], alo[4][4];
#pragma unroll
            for (int mt = 0; mt < 4; mt++) {
                uint32_t ad = sbase + (aoff + mt * 16 * 40 + kk * 16) * 2;
                LDSM_X4(ahi[mt][0], ahi[mt][1], ahi[mt][2], ahi[mt][3], ad);
                LDSM_X4(alo[mt][0], alo[mt][1], alo[mt][2], alo[mt][3], ad + AHALF * 2);
            }
            uint32_t bhi[NT8][2], blo[NT8][2];
#pragma unroll
            for (int p = 0; p < NT8 / 2; p++) {
                uint32_t bd = sbase + 2 * AHALF * 2 + (boff + p * 16 * 40 + kk * 16) * 2;
                LDSM_X4(bhi[2 * p][0], bhi[2 * p][1], bhi[2 * p + 1][0], bhi[2 * p + 1][1], bd);
                LDSM_X4(blo[2 * p][0], blo[2 * p][1], blo[2 * p + 1][0], blo[2 * p + 1][1],
                        bd + BHALF * 2);
            }
            // product 1: Ahi * Bhi
#pragma unroll
            for (int mt = 0; mt < 4; mt++)
#pragma unroll
                for (int nt = 0; nt < NT8; nt++)
                    MMA16816(acc[mt][nt], ahi[mt][0], ahi[mt][1], ahi[mt][2], ahi[mt][3],
                             bhi[nt][0], bhi[nt][1]);
            // product 2: Ahi * Blo
#pragma unroll
            for (int mt = 0; mt < 4; mt++)
#pragma unroll
                for (int nt = 0; nt < NT8; nt++)
                    MMA16816(acc[mt][nt], ahi[mt][0], ahi[mt][1], ahi[mt][2], ahi[mt][3],
                             blo[nt][0], blo[nt][1]);
            // product 3: Alo * Bhi
#pragma unroll
            for (int mt = 0; mt < 4; mt++)
#pragma unroll
                for (int nt = 0; nt < NT8; nt++)
                    MMA16816(acc[mt][nt], alo[mt][0], alo[mt][1], alo[mt][2], alo[mt][3],
                             bhi[nt][0], bhi[nt][1]);
        }
    }

    size_t cbase = (size_t)(z / nh) * cs0 + (size_t)(z % nh) * cs1;
    int mrow = lane >> 2, ncol = (lane & 3) * 2;
#pragma unroll
    for (int mt = 0; mt < 4; mt++) {
#pragma unroll
        for (int half = 0; half < 2; half++) {
            int row = m0 + warp_m * 64 + mt * 16 + mrow + half * 8;
            if (row >= M) continue;
#pragma unroll
            for (int nt = 0; nt < NT8; nt++) {
#pragma unroll
                for (int e = 0; e < 2; e++) {
                    int col = n0 + warp_n * WTN + nt * 8 + ncol + e;
                    if (col >= Nreal) continue;
                    float v = acc[mt][nt][half * 2 + e];
                    if (bias) v += bias[col];
                    size_t off = cbase + (size_t)row * ldc + col;
                    if (resid) v += resid[off];
                    if (do_gelu) v = gelu_exact(v);
                    C[off] = v;
                }
            }
        }
    }
}

// ========================= fused flash attention ============================
#define FA_LD 136
__global__ void __launch_bounds__(256, 2) flash_attn_kernel(
    const float* __restrict__ qkv, const float* __restrict__ relt,
    const int* __restrict__ relidx, float* __restrict__ o) {
    extern __shared__ __nv_bfloat16 fsm[];
    __nv_bfloat16* sQ = fsm;
    __nv_bfloat16* sK = fsm + 128 * FA_LD;
    __nv_bfloat16* sV = sK + 64 * FA_LD;

    int tid = threadIdx.x, wid = tid >> 5, lane = tid & 31;
    int i0 = blockIdx.x * 128;
    int z = blockIdx.y;
    int b = z / HEADS, h = z % HEADS;
    const float* qb = qkv + (size_t)b * NT * 2304 + h * 64;
    const float* kb = qb + 768;
    const float* vb = qb + 1536;

    for (int idx = tid; idx < 128 * 64; idx += 256) {
        int r = idx >> 6, c = idx & 63;
        int gi = i0 + r;
        float v = (gi < NT) ? qb[(size_t)gi * 2304 + c] * 0.125f : 0.f;
        __nv_bfloat16 hi = __float2bfloat16(v);
        sQ[r * FA_LD + c] = hi;
        sQ[r * FA_LD + 64 + c] = __float2bfloat16(v - __bfloat162float(hi));
    }

    float m0 = -1e30f, m1 = -1e30f, l0 = 0.f, l1 = 0.f;
    float O[8][4];
#pragma unroll
    for (int t = 0; t < 8; t++)
#pragma unroll
        for (int e = 0; e < 4; e++) O[t][e] = 0.f;

    int r0g = i0 + wid * 16 + (lane >> 2);
    int r1g = r0g + 8;

    for (int j0 = 0; j0 < NT; j0 += 64) {
        __syncthreads();
        for (int idx = tid; idx < 64 * 64; idx += 256) {
            int r = idx >> 6, c = idx & 63;
            int gj = j0 + r;
            float kv = (gj < NT) ? kb[(size_t)gj * 2304 + c] : 0.f;
            __nv_bfloat16 khi = __float2bfloat16(kv);
            sK[r * FA_LD + c] = khi;
            sK[r * FA_LD + 64 + c] = __float2bfloat16(kv - __bfloat162float(khi));
            float vv = (gj < NT) ? vb[(size_t)gj * 2304 + c] : 0.f;
            __nv_bfloat16 vhi = __float2bfloat16(vv);
            sV[c * FA_LD + r] = vhi;
            sV[c * FA_LD + 64 + r] = __float2bfloat16(vv - __bfloat162float(vhi));
        }
        __syncthreads();

        float S[8][4];
#pragma unroll
        for (int t = 0; t < 8; t++)
#pragma unroll
            for (int e = 0; e < 4; e++) S[t][e] = 0.f;

        const int qsec[3] = {0, 1, 0}, ksec[3] = {0, 0, 1};
#pragma unroll
        for (int sp = 0; sp < 3; sp++) {
#pragma unroll
            for (int kk = 0; kk < 4; kk++) {
                uint32_t a0, a1, a2, a3;
                uint32_t addr = smem_u32(&sQ[(wid * 16 + (lane & 15)) * FA_LD +
                                             qsec[sp] * 64 + kk * 16 + (lane >> 4) * 8]);
                LDSM_X4(a0, a1, a2, a3, addr);
                uint32_t bf[8][2];
#pragma unroll
                for (int p = 0; p < 4; p++) {
                    uint32_t ba = smem_u32(&sK[(p * 16 + ((lane >> 4) << 3) + (lane & 7)) * FA_LD +
                                               ksec[sp] * 64 + kk * 16 + ((lane >> 3) & 1) * 8]);
                    LDSM_X4(bf[2 * p][0], bf[2 * p][1], bf[2 * p + 1][0], bf[2 * p + 1][1], ba);
                }
#pragma unroll
                for (int nt = 0; nt < 8; nt++)
                    MMA16816(S[nt], a0, a1, a2, a3, bf[nt][0], bf[nt][1]);
            }
        }

#pragma unroll
        for (int nt = 0; nt < 8; nt++) {
            int c0 = j0 + nt * 8 + (lane & 3) * 2;
#pragma unroll
            for (int e = 0; e < 2; e++) {
                int jj = c0 + e;
                if (jj < NT) {
                    if (r0g < NT) S[nt][e]     += relt[(size_t)relidx[(size_t)r0g * NT + jj] * HEADS + h];
                    if (r1g < NT) S[nt][2 + e] += relt[(size_t)relidx[(size_t)r1g * NT + jj] * HEADS + h];
                } else {
                    S[nt][e] = -1e30f;
                    S[nt][2 + e] = -1e30f;
                }
            }
        }

        float t0 = -1e30f, t1 = -1e30f;
#pragma unroll
        for (int nt = 0; nt < 8; nt++) {
            t0 = fmaxf(t0, fmaxf(S[nt][0], S[nt][1]));
            t1 = fmaxf(t1, fmaxf(S[nt][2], S[nt][3]));
        }
        t0 = fmaxf(t0, __shfl_xor_sync(0xffffffff, t0, 1));
        t0 = fmaxf(t0, __shfl_xor_sync(0xffffffff, t0, 2));
        t1 = fmaxf(t1, __shfl_xor_sync(0xffffffff, t1, 1));
        t1 = fmaxf(t1, __shfl_xor_sync(0xffffffff, t1, 2));
        float mn0 = fmaxf(m0, t0), mn1 = fmaxf(m1, t1);
        float al0 = __expf(m0 - mn0), al1 = __expf(m1 - mn1);
#pragma unroll
        for (int nt = 0; nt < 8; nt++) {
            O[nt][0] *= al0; O[nt][1] *= al0;
            O[nt][2] *= al1; O[nt][3] *= al1;
        }
        float ls0 = 0.f, ls1 = 0.f;
        uint32_t phi[4][4], plo[4][4];
#pragma unroll
        for (int kk = 0; kk < 4; kk++) {
#pragma unroll
            for (int tt = 0; tt < 2; tt++) {
                int t = 2 * kk + tt;
                float p0 = __expf(S[t][0] - mn0), p1 = __expf(S[t][1] - mn0);
                float p2 = __expf(S[t][2] - mn1), p3 = __expf(S[t][3] - mn1);
                ls0 += p0 + p1; ls1 += p2 + p3;
                float h0 = __bfloat162float(__float2bfloat16(p0));
                float h1 = __bfloat162float(__float2bfloat16(p1));
                float h2 = __bfloat162float(__float2bfloat16(p2));
                float h3 = __bfloat162float(__float2bfloat16(p3));
                phi[kk][tt * 2]     = pack_bf16(h0, h1);
                phi[kk][tt * 2 + 1] = pack_bf16(h2, h3);
                plo[kk][tt * 2]     = pack_bf16(p0 - h0, p1 - h1);
                plo[kk][tt * 2 + 1] = pack_bf16(p2 - h2, p3 - h3);
            }
        }
        ls0 += __shfl_xor_sync(0xffffffff, ls0, 1);
        ls0 += __shfl_xor_sync(0xffffffff, ls0, 2);
        ls1 += __shfl_xor_sync(0xffffffff, ls1, 1);
        ls1 += __shfl_xor_sync(0xffffffff, ls1, 2);
        l0 = l0 * al0 + ls0;
        l1 = l1 * al1 + ls1;
        m0 = mn0; m1 = mn1;

        const int vsec[3] = {0, 0, 1};
#pragma unroll
        for (int sp = 0; sp < 3; sp++) {
#pragma unroll
            for (int kk = 0; kk < 4; kk++) {
                uint32_t* A = (sp == 1) ? plo[kk] : phi[kk];
                uint32_t bf[8][2];
#pragma unroll
                for (int p = 0; p < 4; p++) {
                    uint32_t ba = smem_u32(&sV[(p * 16 + ((lane >> 4) << 3) + (lane & 7)) * FA_LD +
                                               vsec[sp] * 64 + kk * 16 + ((lane >> 3) & 1) * 8]);
                    LDSM_X4(bf[2 * p][0], bf[2 * p][1], bf[2 * p + 1][0], bf[2 * p + 1][1], ba);
                }
#pragma unroll
                for (int nt = 0; nt < 8; nt++)
                    MMA16816(O[nt], A[0], A[1], A[2], A[3], bf[nt][0], bf[nt][1]);
            }
        }
    }

    float il0 = 1.0f / l0, il1 = 1.0f / l1;
#pragma unroll
    for (int nt = 0; nt < 8; nt++) {
        int d = h * 64 + nt * 8 + (lane & 3) * 2;
        if (r0g < NT) {
            float2 v = make_float2(O[nt][0] * il0, O[nt][1] * il0);
            *(float2*)&o[((size_t)b * NT + r0g) * EMB + d] = v;
        }
        if (r1g < NT) {
            float2 v = make_float2(O[nt][2] * il1, O[nt][3] * il1);
            *(float2*)&o[((size_t)b * NT + r1g) * EMB + d] = v;
        }
    }
}

// ------------------------- elementwise helpers ------------------------------
__global__ void patchify_kernel(const float* __restrict__ x, float* __restrict__ A) {
    int idx = blockIdx.x * 256 + threadIdx.x;
    if (idx >= BATCH * 1024 * EMB) return;
    int col = idx % EMB;
    int m = idx / EMB;
    int b = m / 1024, g = m % 1024;
    int gh = g / 32, gw = g % 32;
    int c = col / 256, rem = col % 256;
    int i = rem / 16, j = rem % 16;
    A[idx] = x[(((size_t)(b * 3 + c) * 512) + gh * 16 + i) * 512 + gw * 16 + j];
}

__global__ void assemble_kernel(const float* __restrict__ tok, const float* __restrict__ cls,
                                const float* __restrict__ pos, float* __restrict__ t) {
    int idx = blockIdx.x * 256 + threadIdx.x;
    if (idx >= BATCH * NT * EMB) return;
    int d = idx % EMB;
    int n = (idx / EMB) % NT;
    int b = idx / (EMB * NT);
    float v = (n == 0) ? cls[d] : tok[((size_t)b * 1024 + (n - 1)) * EMB + d];
    t[idx] = v + pos[n * EMB + d];
}

__global__ void ln_kernel(const float* __restrict__ x, const float* __restrict__ w,
                          const float* __restrict__ b, float* __restrict__ out) {
    int r = blockIdx.x;
    const float* xr = x + (size_t)r * EMB;
    __shared__ float red[256];
    int tid = threadIdx.x;
    float s = 0.f;
    for (int i = tid; i < EMB; i += 256) s += xr[i];
    red[tid] = s; __syncthreads();
    for (int st = 128; st > 0; st >>= 1) { if (tid < st) red[tid] += red[tid + st]; __syncthreads(); }
    float mean = red[0] * (1.0f / EMB);
    __syncthreads();
    float s2 = 0.f;
    for (int i = tid; i < EMB; i += 256) { float d = xr[i] - mean; s2 += d * d; }
    red[tid] = s2; __syncthreads();
    for (int st = 128; st > 0; st >>= 1) { if (tid < st) red[tid] += red[tid + st]; __syncthreads(); }
    float inv = rsqrtf(red[0] * (1.0f / EMB) + 1e-6f);
    for (int i = tid; i < EMB; i += 256)
        out[(size_t)r * EMB + i] = (xr[i] - mean) * inv * w[i] + b[i];
}

__global__ void biaspack_kernel(const float* __restrict__ qb, const float* __restrict__ vb,
                                float* __restrict__ out) {
    int i = blockIdx.x * 256 + threadIdx.x;
    if (i >= 3 * EMB) return;
    out[i] = (i < EMB) ? qb[i] : ((i < 2 * EMB) ? 0.f : vb[i - 2 * EMB]);
}

__global__ void copy_kernel(const float* __restrict__ src, float* __restrict__ dst, int n) {
    int i = blockIdx.x * 256 + threadIdx.x;
    if (i < n) dst[i] = src[i];
}

__global__ void repack_w_kernel(const float* __restrict__ w, float* __restrict__ wp) {
    int idx = blockIdx.x * 256 + threadIdx.x;
    if (idx >= 3072 * 768) return;
    int c = idx % 768, n = idx / 768;
    int ij = n / 768, d = n % 768;
    wp[idx] = w[(size_t)c * 3072 + d * 4 + ij];
}

__global__ void scatter_bhwc_kernel(const float* __restrict__ tmp, const float* __restrict__ bias,
                                    float* __restrict__ y, int HW) {
    int total = BATCH * HW * HW * 4 * 768;
    int idx = blockIdx.x * 256 + threadIdx.x;
    if (idx >= total) return;
    int d = idx % 768;
    int ij = (idx / 768) % 4;
    int p = (idx / 3072) % (HW * HW);
    int b = idx / (3072 * HW * HW);
    int h = p / HW, w = p % HW, i = ij / 2, j = ij % 2;
    int W2 = 2 * HW;
    y[(((size_t)b * W2 + 2 * h + i) * W2 + (2 * w + j)) * 768 + d] = tmp[idx] + bias[d];
}

__global__ void scatter_bchw_kernel(const float* __restrict__ tmp, const float* __restrict__ bias,
                                    float* __restrict__ out, int HW) {
    int total = BATCH * HW * HW * 4 * 768;
    int idx = blockIdx.x * 256 + threadIdx.x;
    if (idx >= total) return;
    int d = idx % 768;
    int ij = (idx / 768) % 4;
    int p = (idx / 3072) % (HW * HW);
    int b = idx / (3072 * HW * HW);
    int h = p / HW, w = p % HW, i = ij / 2, j = ij % 2;
    int W2 = 2 * HW;
    out[(((size_t)b * 768 + d) * W2 + 2 * h + i) * W2 + (2 * w + j)] = tmp[idx] + bias[d];
}

__global__ void bn_gelu_kernel(float* __restrict__ y, const float* __restrict__ w,
                               const float* __restrict__ b, const float* __restrict__ mean,
                               const float* __restrict__ var) {
    int idx = blockIdx.x * 256 + threadIdx.x;
    if (idx >= BATCH * 64 * 64 * 768) return;
    int c = idx % 768;
    float v = y[idx];
    v = (v - mean[c]) * rsqrtf(var[c] + 1e-5f) * w[c] + b[c];
    y[idx] = gelu_exact(v);
}

__global__ void to_map_kernel(const float* __restrict__ feat, float* __restrict__ out) {
    int idx = blockIdx.x * 256 + threadIdx.x;
    if (idx >= BATCH * 768 * 32 * 32) return;
    int xw = idx % 32;
    int yh = (idx / 32) % 32;
    int c = (idx / 1024) % 768;
    int b = idx / (1024 * 768);
    out[idx] = feat[((size_t)b * NT + 1 + yh * 32 + xw) * EMB + c];
}

__global__ void maxpool_kernel(const float* __restrict__ feat, float* __restrict__ out) {
    int idx = blockIdx.x * 256 + threadIdx.x;
    if (idx >= BATCH * 768 * 16 * 16) return;
    int xw = idx % 16;
    int yh = (idx / 16) % 16;
    int c = (idx / 256) % 768;
    int b = idx / (256 * 768);
    float m = -1e30f;
#pragma unroll
    for (int i = 0; i < 2; i++)
#pragma unroll
        for (int j = 0; j < 2; j++) {
            int Y = 2 * yh + i, X = 2 * xw + j;
            m = fmaxf(m, feat[((size_t)b * NT + 1 + Y * 32 + X) * EMB + c]);
        }
    out[idx] = m;
}

// ------------------------- host helpers -------------------------------------
static void pack(const float* in, __nv_bfloat16* out, int M, int K, int Kp,
                 size_t irs, size_t ics, size_t ibs0, size_t ibs1, int nh,
                 size_t obs, float scale, int nz) {
    dim3 g((M * Kp + 255) / 256, nz);
    pack_kernel<<<g, 256>>>(in, out, M, K, Kp, irs, ics, ibs0, ibs1, nh, obs, scale);
}
#define SMEM64  (3 * 2 * (128 + 64) * 40 * 2)    // 92160
#define SMEM128 (2 * 2 * (128 + 128) * 40 * 2)   // 81920
static void gemm_tc(const __nv_bfloat16* A, const __nv_bfloat16* B, float* C,
                    const float* bias, const float* resid, int M, int N, int Kp,
                    size_t Abs, size_t Bbs, size_t ldc,
                    size_t cs0, size_t cs1, int nh, int gelu, int nz) {
    int gm = (M + 127) / 128;
    int g128 = ((N + 127) / 128) * gm * nz;
    if (N % 64 == 0 && (N % 128 != 0 || g128 < 148)) {
        dim3 g(N / 64, gm, nz);
        hgemm2<64, 3><<<g, 256, SMEM64>>>(A, B, C, bias, resid, M, N, Kp, Abs, Bbs,
                                          ldc, cs0, cs1, nh, gelu);
    } else {
        dim3 g((N + 127) / 128, gm, nz);
        hgemm2<128, 2><<<g, 256, SMEM128>>>(A, B, C, bias, resid, M, N, Kp, Abs, Bbs,
                                            ldc, cs0, cs1, nh, gelu);
    }
}

extern "C" void kernel_launch(void* const* d_in, const int* in_sizes, int n_in,
                              void* d_out, int out_size) {
    const float* x         = (const float*)d_in[0];
    const float* patch_w   = (const float*)d_in[1];
    const float* patch_b   = (const float*)d_in[2];
    const float* cls_token = (const float*)d_in[3];
    const float* pos_embed = (const float*)d_in[4];
    const float* ln1_w     = (const float*)d_in[5];
    const float* ln1_b     = (const float*)d_in[6];
    const float* qkv_w     = (const float*)d_in[7];
    const float* q_bias    = (const float*)d_in[8];
    const float* v_bias    = (const float*)d_in[9];
    const float* rel_tab   = (const float*)d_in[10];
    const float* proj_w    = (const float*)d_in[11];
    const float* proj_b    = (const float*)d_in[12];
    const float* ln2_w     = (const float*)d_in[13];
    const float* ln2_b     = (const float*)d_in[14];
    const float* fc1_w     = (const float*)d_in[15];
    const float* fc1_b     = (const float*)d_in[16];
    const float* fc2_w     = (const float*)d_in[17];
    const float* fc2_b     = (const float*)d_in[18];
    const float* d1_w      = (const float*)d_in[19];
    const float* d1_b      = (const float*)d_in[20];
    const float* bn_w      = (const float*)d_in[21];
    const float* bn_b      = (const float*)d_in[22];
    const float* bn_mean   = (const float*)d_in[23];
    const float* bn_var    = (const float*)d_in[24];
    const float* d2_w      = (const float*)d_in[25];
    const float* d2_b      = (const float*)d_in[26];
    const float* f2w       = (const float*)d_in[27];
    const float* f2b       = (const float*)d_in[28];
    const int*   rel_idx   = (const int*)d_in[29];

    float* out = (float*)d_out;
    float* out1 = out;
    float* out2 = out1 + (size_t)BATCH * 768 * 128 * 128;
    float* out3 = out2 + (size_t)BATCH * 768 * 64 * 64;
    float* out4 = out3 + (size_t)BATCH * 768 * 32 * 32;

    static float *pt = nullptr, *ph, *pqkv, *po, *pmlp, *ppatch, *ptok;
    static float *pf0, *pf1, *pf2, *pf3, *py, *ptmp, *pwp, *pqb;
    static __nv_bfloat16 *pa, *pb;
    if (!pt) {
        cudaGetSymbolAddress((void**)&pt, g_t);
        cudaGetSymbolAddress((void**)&ph, g_h);
        cudaGetSymbolAddress((void**)&pqkv, g_qkv);
        cudaGetSymbolAddress((void**)&po, g_o);
        cudaGetSymbolAddress((void**)&pmlp, g_mlp);
        cudaGetSymbolAddress((void**)&ppatch, g_patch);
        cudaGetSymbolAddress((void**)&ptok, g_tok);
        cudaGetSymbolAddress((void**)&pf0, g_feat0);
        cudaGetSymbolAddress((void**)&pf1, g_feat1);
        cudaGetSymbolAddress((void**)&pf2, g_feat2);
        cudaGetSymbolAddress((void**)&pf3, g_feat3);
        cudaGetSymbolAddress((void**)&py, g_y);
        cudaGetSymbolAddress((void**)&ptmp, g_tmp);
        cudaGetSymbolAddress((void**)&pwp, g_wpack);
        cudaGetSymbolAddress((void**)&pqb, g_qkvbias);
        cudaGetSymbolAddress((void**)&pa, g_pa);
        cudaGetSymbolAddress((void**)&pb, g_pb);
        cudaFuncSetAttribute(flash_attn_kernel,
                             cudaFuncAttributeMaxDynamicSharedMemorySize,
                             (128 + 64 + 64) * FA_LD * 2);
        cudaFuncSetAttribute((const void*)hgemm2<64, 3>,
                             cudaFuncAttributeMaxDynamicSharedMemorySize, SMEM64);
        cudaFuncSetAttribute((const void*)hgemm2<128, 2>,
                             cudaFuncAttributeMaxDynamicSharedMemorySize, SMEM128);
    }

    const int TOKELEMS = BATCH * NT * EMB;
    const int M = BATCH * NT;  // 2050
    const int FA_SMEM = (128 + 64 + 64) * FA_LD * 2;

    // ---- patch embed ----
    patchify_kernel<<<(BATCH * 1024 * EMB + 255) / 256, 256>>>(x, ppatch);
    pack(ppatch, pa, 2048, 768, 768, 768, 1, 0, 0, 1, 0, 1.0f, 1);
    pack(patch_w, pb, 768, 768, 768, 768, 1, 0, 0, 1, 0, 1.0f, 1);
    gemm_tc(pa, pb, ptok, patch_b, nullptr, 2048, 768, 768, 0, 0,
            768, 0, 0, 1, 0, 1);
    assemble_kernel<<<(TOKELEMS + 255) / 256, 256>>>(ptok, cls_token, pos_embed, pt);

    // ---- transformer layers ----
    for (int l = 0; l < 12; l++) {
        ln_kernel<<<M, 256>>>(pt, ln1_w + l * EMB, ln1_b + l * EMB, ph);
        biaspack_kernel<<<(3 * EMB + 255) / 256, 256>>>(q_bias + l * EMB, v_bias + l * EMB, pqb);
        pack(ph, pa, M, 768, 768, 768, 1, 0, 0, 1, 0, 1.0f, 1);
        pack(qkv_w + (size_t)l * 2304 * 768, pb, 2304, 768, 768, 768, 1, 0, 0, 1, 0, 1.0f, 1);
        gemm_tc(pa, pb, pqkv, pqb, nullptr, M, 2304, 768, 0, 0,
                2304, 0, 0, 1, 0, 1);
        {
            dim3 g((NT + 127) / 128, BATCH * HEADS);
            flash_attn_kernel<<<g, 256, FA_SMEM>>>(pqkv, rel_tab + (size_t)l * NREL * HEADS,
                                                   rel_idx, po);
        }
        pack(po, pa, M, 768, 768, 768, 1, 0, 0, 1, 0, 1.0f, 1);
        pack(proj_w + (size_t)l * 768 * 768, pb, 768, 768, 768, 768, 1, 0, 0, 1, 0, 1.0f, 1);
        gemm_tc(pa, pb, pt, proj_b + l * EMB, pt, M, 768, 768, 0, 0,
                768, 0, 0, 1, 0, 1);
        ln_kernel<<<M, 256>>>(pt, ln2_w + l * EMB, ln2_b + l * EMB, ph);
        pack(ph, pa, M, 768, 768, 768, 1, 0, 0, 1, 0, 1.0f, 1);
        pack(fc1_w + (size_t)l * 3072 * 768, pb, 3072, 768, 768, 768, 1, 0, 0, 1, 0, 1.0f, 1);
        gemm_tc(pa, pb, pmlp, fc1_b + l * 4 * EMB, nullptr, M, 3072, 768, 0, 0,
                3072, 0, 0, 1, 1, 1);
        pack(pmlp, pa, M, 3072, 3072, 3072, 1, 0, 0, 1, 0, 1.0f, 1);
        pack(fc2_w + (size_t)l * 768 * 3072, pb, 768, 3072, 3072, 3072, 1, 0, 0, 1, 0, 1.0f, 1);
        gemm_tc(pa, pb, pt, fc2_b + l * EMB, pt, M, 768, 3072, 0, 0,
                768, 0, 0, 1, 0, 1);
        float* fdst = nullptr;
        if (l == 3) fdst = pf0;
        else if (l == 5) fdst = pf1;
        else if (l == 7) fdst = pf2;
        else if (l == 11) fdst = pf3;
        if (fdst) copy_kernel<<<(TOKELEMS + 255) / 256, 256>>>(pt, fdst, TOKELEMS);
    }

    // ---- o3 / o4 ----
    to_map_kernel<<<(BATCH * 768 * 1024 + 255) / 256, 256>>>(pf2, out3);
    maxpool_kernel<<<(BATCH * 768 * 256 + 255) / 256, 256>>>(pf3, out4);

    // ---- fpn1 stage 1 ----
    repack_w_kernel<<<(3072 * 768 + 255) / 256, 256>>>(d1_w, pwp);
    pack(pwp, pb, 3072, 768, 768, 768, 1, 0, 0, 1, 0, 1.0f, 1);
    pack(pf0 + 768, pa, 1024, 768, 768, 768, 1, (size_t)NT * 768, 0, 1,
         (size_t)1024 * 1536, 1.0f, BATCH);
    gemm_tc(pa, pb, ptmp, nullptr, nullptr, 1024, 3072, 768,
            (size_t)1024 * 1536, 0, 3072, (size_t)1024 * 3072, 0, 1, 0, BATCH);
    scatter_bhwc_kernel<<<(BATCH * 1024 * 3072 + 255) / 256, 256>>>(ptmp, d1_b, py, 32);
    bn_gelu_kernel<<<(BATCH * 64 * 64 * 768 + 255) / 256, 256>>>(py, bn_w, bn_b, bn_mean, bn_var);

    // ---- fpn1 stage 2 ----
    repack_w_kernel<<<(3072 * 768 + 255) / 256, 256>>>(d2_w, pwp);
    pack(pwp, pb, 3072, 768, 768, 768, 1, 0, 0, 1, 0, 1.0f, 1);
    pack(py, pa, 4096, 768, 768, 768, 1, (size_t)4096 * 768, 0, 1,
         (size_t)4096 * 1536, 1.0f, BATCH);
    gemm_tc(pa, pb, ptmp, nullptr, nullptr, 4096, 3072, 768,
            (size_t)4096 * 1536, 0, 3072, (size_t)4096 * 3072, 0, 1, 0, BATCH);
    scatter_bchw_kernel<<<(BATCH * 4096 * 3072 + 255) / 256, 256>>>(ptmp, d2_b, out1, 64);

    // ---- o2 ----
    repack_w_kernel<<<(3072 * 768 + 255) / 256, 256>>>(f2w, pwp);
    pack(pwp, pb, 3072, 768, 768, 768, 1, 0, 0, 1, 0, 1.0f, 1);
    pack(pf1 + 768, pa, 1024, 768, 768, 768, 1, (size_t)NT * 768, 0, 1,
         (size_t)1024 * 1536, 1.0f, BATCH);
    gemm_tc(pa, pb, ptmp, nullptr, nullptr, 1024, 3072, 768,
            (size_t)1024 * 1536, 0, 3072, (size_t)1024 * 3072, 0, 1, 0, BATCH);
    scatter_bchw_kernel<<<(BATCH * 1024 * 3072 + 255) / 256, 256>>>(ptmp, f2b, out2, 32);

    (void)in_sizes; (void)n_in; (void)out_size;
}

// round 9
// speedup vs baseline: 2.9372x; 1.0831x over previous
#include <cuda_runtime.h>
#include <cuda_bf16.h>
#include <math.h>
#include <stdint.h>

#define NT    1025
#define EMB   768
#define BATCH 2
#define HEADS 12
#define NREL  3972

// ------------------------- device scratch (no allocs allowed) ---------------
__device__ float g_t[BATCH * NT * EMB];
__device__ float g_qkv[BATCH * NT * 3 * EMB];
__device__ float g_patch[BATCH * 1024 * EMB];
__device__ float g_tok[BATCH * 1024 * EMB];
__device__ float g_feat0[BATCH * NT * EMB];
__device__ float g_feat1[BATCH * NT * EMB];
__device__ float g_feat2[BATCH * NT * EMB];
__device__ float g_feat3[BATCH * NT * EMB];
__device__ float g_y[BATCH * 64 * 64 * EMB];
__device__ float g_tmp[(size_t)BATCH * 4096 * 3072];
__device__ float g_wpack[3072 * 768];
__device__ float g_qkvbias[3 * EMB];
__device__ __nv_bfloat16 g_pa[14000000];   // A operands (ln/attn/fpn packs)
__device__ __nv_bfloat16 g_pb[5000000];    // B operands (max fc1: 3072*1536=4.7M)
__device__ __nv_bfloat16 g_pc[12700000];   // fc2 A operand (2050*6144=12.6M) - DEDICATED

__device__ __forceinline__ float gelu_exact(float x) {
    return 0.5f * x * (1.0f + erff(x * 0.70710678118654752f));
}

__device__ __forceinline__ uint32_t smem_u32(const void* p) {
    uint32_t a;
    asm("{ .reg .u64 t; cvta.to.shared.u64 t, %1; cvt.u32.u64 %0, t; }" : "=r"(a) : "l"(p));
    return a;
}

#define LDSM_X4(r0, r1, r2, r3, addr) \
    asm volatile("ldmatrix.sync.aligned.m8n8.x4.shared.b16 {%0,%1,%2,%3}, [%4];" \
                 : "=r"(r0), "=r"(r1), "=r"(r2), "=r"(r3) : "r"(addr))

#define MMA16816(d, a0, a1, a2, a3, b0, b1) \
    asm volatile("mma.sync.aligned.m16n8k16.row.col.f32.bf16.bf16.f32 " \
                 "{%0,%1,%2,%3}, {%4,%5,%6,%7}, {%8,%9}, {%0,%1,%2,%3};" \
                 : "+f"((d)[0]), "+f"((d)[1]), "+f"((d)[2]), "+f"((d)[3]) \
                 : "r"(a0), "r"(a1), "r"(a2), "r"(a3), "r"(b0), "r"(b1))

#define CP_ASYNC16(dst, src, sz) \
    asm volatile("cp.async.cg.shared.global [%0], [%1], 16, %2;" \
                 :: "r"(dst), "l"(src), "r"(sz))

__device__ __forceinline__ uint32_t pack_bf16(float x, float y) {
    __nv_bfloat162 t = __floats2bfloat162_rn(x, y);
    return *(uint32_t*)&t;
}
__device__ __forceinline__ void split2(float v, __nv_bfloat16& hi, __nv_bfloat16& lo) {
    hi = __float2bfloat16(v);
    lo = __float2bfloat16(v - __bfloat162float(hi));
}

// ========================= split-bf16 pack ([hi|lo]) ========================
__global__ void pack_kernel(const float* __restrict__ in, __nv_bfloat16* __restrict__ out,
                            int M, int K, int Kp, size_t irs, size_t ics,
                            size_t ibs0, size_t ibs1, int nh, size_t obs, float scale) {
    int idx = blockIdx.x * 256 + threadIdx.x;
    int z = blockIdx.y;
    if (idx >= M * Kp) return;
    int k = idx % Kp, m = idx / Kp;
    const float* src = in + (size_t)(z / nh) * ibs0 + (size_t)(z % nh) * ibs1;
    float v = (k < K) ? src[(size_t)m * irs + (size_t)k * ics] * scale : 0.f;
    __nv_bfloat16 hi, lo; split2(v, hi, lo);
    __nv_bfloat16* o = out + (size_t)z * obs + (size_t)m * (2 * (size_t)Kp);
    o[k] = hi; o[Kp + k] = lo;
}

// ---------------- fused LayerNorm + split-bf16 pack -------------------------
__global__ void ln_pack_kernel(const float* __restrict__ x, const float* __restrict__ w,
                               const float* __restrict__ b, __nv_bfloat16* __restrict__ out) {
    int r = blockIdx.x;
    const float* xr = x + (size_t)r * EMB;
    __shared__ float red[256];
    int tid = threadIdx.x;
    float s = 0.f;
    for (int i = tid; i < EMB; i += 256) s += xr[i];
    red[tid] = s; __syncthreads();
    for (int st = 128; st > 0; st >>= 1) { if (tid < st) red[tid] += red[tid + st]; __syncthreads(); }
    float mean = red[0] * (1.0f / EMB);
    __syncthreads();
    float s2 = 0.f;
    for (int i = tid; i < EMB; i += 256) { float d = xr[i] - mean; s2 += d * d; }
    red[tid] = s2; __syncthreads();
    for (int st = 128; st > 0; st >>= 1) { if (tid < st) red[tid] += red[tid + st]; __syncthreads(); }
    float inv = rsqrtf(red[0] * (1.0f / EMB) + 1e-6f);
    __nv_bfloat16* o = out + (size_t)r * (2 * EMB);
    for (int i = tid; i < EMB; i += 256) {
        float v = (xr[i] - mean) * inv * w[i] + b[i];
        __nv_bfloat16 hi, lo; split2(v, hi, lo);
        o[i] = hi; o[EMB + i] = lo;
    }
}

// ========================= HMMA GEMM (split-product reuse) ==================
template <int BN, int NSTAGE>
__global__ void __launch_bounds__(256, 2) hgemm2(
    const __nv_bfloat16* __restrict__ A, const __nv_bfloat16* __restrict__ B,
    float* __restrict__ C, __nv_bfloat16* __restrict__ Cp,
    const float* __restrict__ bias, const float* __restrict__ resid,
    int M, int Nreal, int Kp, size_t Abs, size_t Bbs,
    size_t ldc, size_t cs0, size_t cs1, int nh, int do_gelu) {
    constexpr int WTN = BN / 4;
    constexpr int NT8 = WTN / 8;
    constexpr int NB4 = BN / 64;
    constexpr int AHALF = 128 * 40;
    constexpr int BHALF = BN * 40;
    constexpr int STAGE = 2 * (AHALF + BHALF);
    extern __shared__ __nv_bfloat16 dsm[];

    int tid = threadIdx.x;
    int wid = tid >> 5, lane = tid & 31;
    int warp_m = wid >> 2, warp_n = wid & 3;
    int m0 = blockIdx.y * 128, n0 = blockIdx.x * BN;
    int z = blockIdx.z;

    const size_t lda = 2 * (size_t)Kp, ldb = 2 * (size_t)Kp;
    const __nv_bfloat16* Az = A + (size_t)z * Abs;
    const __nv_bfloat16* Bz = B + (size_t)z * Bbs;

    float acc[4][NT8][4];
#pragma unroll
    for (int i = 0; i < 4; i++)
#pragma unroll
        for (int j = 0; j < NT8; j++)
#pragma unroll
            for (int e = 0; e < 4; e++) acc[i][j][e] = 0.f;

    int nk = Kp >> 5;

    auto load_body = [&](int c, int s) {
        __nv_bfloat16* st = dsm + s * STAGE;
#pragma unroll
        for (int sec = 0; sec < 2; sec++) {
#pragma unroll
            for (int i = 0; i < 2; i++) {
                int idx = tid + i * 256, row = idx >> 2, cg = idx & 3;
                uint32_t dst = smem_u32(st + sec * AHALF + row * 40 + cg * 8);
                const __nv_bfloat16* src = Az + (size_t)(m0 + row) * lda +
                                           (size_t)sec * Kp + c * 32 + cg * 8;
                CP_ASYNC16(dst, src, (m0 + row < M) ? 16 : 0);
            }
        }
#pragma unroll
        for (int sec = 0; sec < 2; sec++) {
#pragma unroll
            for (int i = 0; i < NB4; i++) {
                int idx = tid + i * 256, row = idx >> 2, cg = idx & 3;
                uint32_t dst = smem_u32(st + 2 * AHALF + sec * BHALF + row * 40 + cg * 8);
                const __nv_bfloat16* src = Bz + (size_t)(n0 + row) * ldb +
                                           (size_t)sec * Kp + c * 32 + cg * 8;
                CP_ASYNC16(dst, src, (n0 + row < Nreal) ? 16 : 0);
            }
        }
    };

#pragma unroll
    for (int s = 0; s < NSTAGE - 1; s++) {
        if (s < nk) load_body(s, s);
        asm volatile("cp.async.commit_group;");
    }

    uint32_t aoff = (warp_m * 64 + (lane & 15)) * 40 + (lane >> 4) * 8;
    uint32_t boff = (warp_n * WTN + ((lane >> 4) << 3) + (lane & 7)) * 40 + ((lane >> 3) & 1) * 8;
    uint32_t dsm0 = smem_u32(dsm);

    for (int c = 0; c < nk; c++) {
        asm volatile("cp.async.wait_group %0;" :: "n"(NSTAGE - 2));
        __syncthreads();
        {
            int ncd = c + NSTAGE - 1;
            if (ncd < nk) load_body(ncd, ncd % NSTAGE);
            asm volatile("cp.async.commit_group;");
        }
        uint32_t sbase = dsm0 + (c % NSTAGE) * STAGE * 2;
#pragma unroll
        for (int kk = 0; kk < 2; kk++) {
            uint32_t ahi[4][4], alo[4][4];
#pragma unroll
            for (int mt = 0; mt < 4; mt++) {
                uint32_t ad = sbase + (aoff + mt * 16 * 40 + kk * 16) * 2;
                LDSM_X4(ahi[mt][0], ahi[mt][1], ahi[mt][2], ahi[mt][3], ad);
                LDSM_X4(alo[mt][0], alo[mt][1], alo[mt][2], alo[mt][3], ad + AHALF * 2);
            }
            uint32_t bhi[NT8][2], blo[NT8][2];
#pragma unroll
            for (int p = 0; p < NT8 / 2; p++) {
                uint32_t bd = sbase + 2 * AHALF * 2 + (boff + p * 16 * 40 + kk * 16) * 2;
                LDSM_X4(bhi[2 * p][0], bhi[2 * p][1], bhi[2 * p + 1][0], bhi[2 * p + 1][1], bd);
                LDSM_X4(blo[2 * p][0], blo[2 * p][1], blo[2 * p + 1][0], blo[2 * p + 1][1],
                        bd + BHALF * 2);
            }
#pragma unroll
            for (int mt = 0; mt < 4; mt++)
#pragma unroll
                for (int nt = 0; nt < NT8; nt++)
                    MMA16816(acc[mt][nt], ahi[mt][0], ahi[mt][1], ahi[mt][2], ahi[mt][3],
                             bhi[nt][0], bhi[nt][1]);
#pragma unroll
            for (int mt = 0; mt < 4; mt++)
#pragma unroll
                for (int nt = 0; nt < NT8; nt++)
                    MMA16816(acc[mt][nt], ahi[mt][0], ahi[mt][1], ahi[mt][2], ahi[mt][3],
                             blo[nt][0], blo[nt][1]);
#pragma unroll
            for (int mt = 0; mt < 4; mt++)
#pragma unroll
                for (int nt = 0; nt < NT8; nt++)
                    MMA16816(acc[mt][nt], alo[mt][0], alo[mt][1], alo[mt][2], alo[mt][3],
                             bhi[nt][0], bhi[nt][1]);
        }
    }

    size_t cbase = (size_t)(z / nh) * cs0 + (size_t)(z % nh) * cs1;
    int mrow = lane >> 2, ncol = (lane & 3) * 2;
#pragma unroll
    for (int mt = 0; mt < 4; mt++) {
#pragma unroll
        for (int half = 0; half < 2; half++) {
            int row = m0 + warp_m * 64 + mt * 16 + mrow + half * 8;
            if (row >= M) continue;
#pragma unroll
            for (int nt = 0; nt < NT8; nt++) {
                int col = n0 + warp_n * WTN + nt * 8 + ncol;
                float v0 = acc[mt][nt][half * 2];
                float v1 = acc[mt][nt][half * 2 + 1];
                if (bias) { v0 += bias[col]; v1 += bias[col + 1]; }
                if (resid) {
                    size_t off = cbase + (size_t)row * ldc + col;
                    v0 += resid[off]; v1 += resid[off + 1];
                }
                if (do_gelu) { v0 = gelu_exact(v0); v1 = gelu_exact(v1); }
                if (C) {
                    size_t off = cbase + (size_t)row * ldc + col;
                    if (col < Nreal) C[off] = v0;
                    if (col + 1 < Nreal) C[off + 1] = v1;
                }
                if (Cp) {
                    __nv_bfloat16 h0, l0b, h1, l1b;
                    split2(v0, h0, l0b); split2(v1, h1, l1b);
                    __nv_bfloat16* o = Cp + (size_t)row * (2 * (size_t)Nreal);
                    if (col + 1 < Nreal) {
                        *(uint32_t*)&o[col] = pack_bf16(__bfloat162float(h0), __bfloat162float(h1));
                        *(uint32_t*)&o[Nreal + col] = pack_bf16(__bfloat162float(l0b), __bfloat162float(l1b));
                    } else if (col < Nreal) {
                        o[col] = h0; o[Nreal + col] = l0b;
                    }
                }
            }
        }
    }
}

// ========================= fused flash attention ============================
// Writes output directly as packed split-bf16 [hi(768) | lo(768)] per row.
#define FA_LD 136
__global__ void __launch_bounds__(256, 2) flash_attn_kernel(
    const float* __restrict__ qkv, const float* __restrict__ relt,
    const int* __restrict__ relidx, __nv_bfloat16* __restrict__ opk) {
    extern __shared__ __nv_bfloat16 fsm[];
    __nv_bfloat16* sQ = fsm;
    __nv_bfloat16* sK = fsm + 128 * FA_LD;
    __nv_bfloat16* sV = sK + 64 * FA_LD;

    int tid = threadIdx.x, wid = tid >> 5, lane = tid & 31;
    int i0 = blockIdx.x * 128;
    int z = blockIdx.y;
    int b = z / HEADS, h = z % HEADS;
    const float* qb = qkv + (size_t)b * NT * 2304 + h * 64;
    const float* kb = qb + 768;
    const float* vb = qb + 1536;

    for (int idx = tid; idx < 128 * 64; idx += 256) {
        int r = idx >> 6, c = idx & 63;
        int gi = i0 + r;
        float v = (gi < NT) ? qb[(size_t)gi * 2304 + c] * 0.125f : 0.f;
        __nv_bfloat16 hi, lo; split2(v, hi, lo);
        sQ[r * FA_LD + c] = hi;
        sQ[r * FA_LD + 64 + c] = lo;
    }

    float m0 = -1e30f, m1 = -1e30f, l0 = 0.f, l1 = 0.f;
    float O[8][4];
#pragma unroll
    for (int t = 0; t < 8; t++)
#pragma unroll
        for (int e = 0; e < 4; e++) O[t][e] = 0.f;

    int r0g = i0 + wid * 16 + (lane >> 2);
    int r1g = r0g + 8;

    for (int j0 = 0; j0 < NT; j0 += 64) {
        __syncthreads();
        for (int idx = tid; idx < 64 * 64; idx += 256) {
            int r = idx >> 6, c = idx & 63;
            int gj = j0 + r;
            float kv = (gj < NT) ? kb[(size_t)gj * 2304 + c] : 0.f;
            __nv_bfloat16 khi, klo; split2(kv, khi, klo);
            sK[r * FA_LD + c] = khi;
            sK[r * FA_LD + 64 + c] = klo;
            float vv = (gj < NT) ? vb[(size_t)gj * 2304 + c] : 0.f;
            __nv_bfloat16 vhi, vlo; split2(vv, vhi, vlo);
            sV[c * FA_LD + r] = vhi;
            sV[c * FA_LD + 64 + r] = vlo;
        }
        __syncthreads();

        float S[8][4];
#pragma unroll
        for (int t = 0; t < 8; t++)
#pragma unroll
            for (int e = 0; e < 4; e++) S[t][e] = 0.f;

        const int qsec[3] = {0, 1, 0}, ksec[3] = {0, 0, 1};
#pragma unroll
        for (int sp = 0; sp < 3; sp++) {
#pragma unroll
            for (int kk = 0; kk < 4; kk++) {
                uint32_t a0, a1, a2, a3;
                uint32_t addr = smem_u32(&sQ[(wid * 16 + (lane & 15)) * FA_LD +
                                             qsec[sp] * 64 + kk * 16 + (lane >> 4) * 8]);
                LDSM_X4(a0, a1, a2, a3, addr);
                uint32_t bf[8][2];
#pragma unroll
                for (int p = 0; p < 4; p++) {
                    uint32_t ba = smem_u32(&sK[(p * 16 + ((lane >> 4) << 3) + (lane & 7)) * FA_LD +
                                               ksec[sp] * 64 + kk * 16 + ((lane >> 3) & 1) * 8]);
                    LDSM_X4(bf[2 * p][0], bf[2 * p][1], bf[2 * p + 1][0], bf[2 * p + 1][1], ba);
                }
#pragma unroll
                for (int nt = 0; nt < 8; nt++)
                    MMA16816(S[nt], a0, a1, a2, a3, bf[nt][0], bf[nt][1]);
            }
        }

#pragma unroll
        for (int nt = 0; nt < 8; nt++) {
            int c0 = j0 + nt * 8 + (lane & 3) * 2;
#pragma unroll
            for (int e = 0; e < 2; e++) {
                int jj = c0 + e;
                if (jj < NT) {
                    if (r0g < NT) S[nt][e]     += relt[(size_t)relidx[(size_t)r0g * NT + jj] * HEADS + h];
                    if (r1g < NT) S[nt][2 + e] += relt[(size_t)relidx[(size_t)r1g * NT + jj] * HEADS + h];
                } else {
                    S[nt][e] = -1e30f;
                    S[nt][2 + e] = -1e30f;
                }
            }
        }

        float t0 = -1e30f, t1 = -1e30f;
#pragma unroll
        for (int nt = 0; nt < 8; nt++) {
            t0 = fmaxf(t0, fmaxf(S[nt][0], S[nt][1]));
            t1 = fmaxf(t1, fmaxf(S[nt][2], S[nt][3]));
        }
        t0 = fmaxf(t0, __shfl_xor_sync(0xffffffff, t0, 1));
        t0 = fmaxf(t0, __shfl_xor_sync(0xffffffff, t0, 2));
        t1 = fmaxf(t1, __shfl_xor_sync(0xffffffff, t1, 1));
        t1 = fmaxf(t1, __shfl_xor_sync(0xffffffff, t1, 2));
        float mn0 = fmaxf(m0, t0), mn1 = fmaxf(m1, t1);
        float al0 = __expf(m0 - mn0), al1 = __expf(m1 - mn1);
#pragma unroll
        for (int nt = 0; nt < 8; nt++) {
            O[nt][0] *= al0; O[nt][1] *= al0;
            O[nt][2] *= al1; O[nt][3] *= al1;
        }
        float ls0 = 0.f, ls1 = 0.f;
        uint32_t phi[4][4], plo[4][4];
#pragma unroll
        for (int kk = 0; kk < 4; kk++) {
#pragma unroll
            for (int tt = 0; tt < 2; tt++) {
                int t = 2 * kk + tt;
                float p0 = __expf(S[t][0] - mn0), p1 = __expf(S[t][1] - mn0);
                float p2 = __expf(S[t][2] - mn1), p3 = __expf(S[t][3] - mn1);
                ls0 += p0 + p1; ls1 += p2 + p3;
                float h0 = __bfloat162float(__float2bfloat16(p0));
                float h1 = __bfloat162float(__float2bfloat16(p1));
                float h2 = __bfloat162float(__float2bfloat16(p2));
                float h3 = __bfloat162float(__float2bfloat16(p3));
                phi[kk][tt * 2]     = pack_bf16(h0, h1);
                phi[kk][tt * 2 + 1] = pack_bf16(h2, h3);
                plo[kk][tt * 2]     = pack_bf16(p0 - h0, p1 - h1);
                plo[kk][tt * 2 + 1] = pack_bf16(p2 - h2, p3 - h3);
            }
        }
        ls0 += __shfl_xor_sync(0xffffffff, ls0, 1);
        ls0 += __shfl_xor_sync(0xffffffff, ls0, 2);
        ls1 += __shfl_xor_sync(0xffffffff, ls1, 1);
        ls1 += __shfl_xor_sync(0xffffffff, ls1, 2);
        l0 = l0 * al0 + ls0;
        l1 = l1 * al1 + ls1;
        m0 = mn0; m1 = mn1;

        const int vsec[3] = {0, 0, 1};
#pragma unroll
        for (int sp = 0; sp < 3; sp++) {
#pragma unroll
            for (int kk = 0; kk < 4; kk++) {
                uint32_t* A = (sp == 1) ? plo[kk] : phi[kk];
                uint32_t bf[8][2];
#pragma unroll
                for (int p = 0; p < 4; p++) {
                    uint32_t ba = smem_u32(&sV[(p * 16 + ((lane >> 4) << 3) + (lane & 7)) * FA_LD +
                                               vsec[sp] * 64 + kk * 16 + ((lane >> 3) & 1) * 8]);
                    LDSM_X4(bf[2 * p][0], bf[2 * p][1], bf[2 * p + 1][0], bf[2 * p + 1][1], ba);
                }
#pragma unroll
                for (int nt = 0; nt < 8; nt++)
                    MMA16816(O[nt], A[0], A[1], A[2], A[3], bf[nt][0], bf[nt][1]);
            }
        }
    }

    float il0 = 1.0f / l0, il1 = 1.0f / l1;
#pragma unroll
    for (int nt = 0; nt < 8; nt++) {
        int d = h * 64 + nt * 8 + (lane & 3) * 2;
        if (r0g < NT) {
            float v0 = O[nt][0] * il0, v1 = O[nt][1] * il0;
            __nv_bfloat16 h0, lo0, h1, lo1;
            split2(v0, h0, lo0); split2(v1, h1, lo1);
            __nv_bfloat16* o = opk + ((size_t)b * NT + r0g) * 1536;
            *(uint32_t*)&o[d] = pack_bf16(__bfloat162float(h0), __bfloat162float(h1));
            *(uint32_t*)&o[768 + d] = pack_bf16(__bfloat162float(lo0), __bfloat162float(lo1));
        }
        if (r1g < NT) {
            float v0 = O[nt][2] * il1, v1 = O[nt][3] * il1;
            __nv_bfloat16 h0, lo0, h1, lo1;
            split2(v0, h0, lo0); split2(v1, h1, lo1);
            __nv_bfloat16* o = opk + ((size_t)b * NT + r1g) * 1536;
            *(uint32_t*)&o[d] = pack_bf16(__bfloat162float(h0), __bfloat162float(h1));
            *(uint32_t*)&o[768 + d] = pack_bf16(__bfloat162float(lo0), __bfloat162float(lo1));
        }
    }
}

// ------------------------- elementwise helpers ------------------------------
__global__ void patchify_kernel(const float* __restrict__ x, float* __restrict__ A) {
    int idx = blockIdx.x * 256 + threadIdx.x;
    if (idx >= BATCH * 1024 * EMB) return;
    int col = idx % EMB;
    int m = idx / EMB;
    int b = m / 1024, g = m % 1024;
    int gh = g / 32, gw = g % 32;
    int c = col / 256, rem = col % 256;
    int i = rem / 16, j = rem % 16;
    A[idx] = x[(((size_t)(b * 3 + c) * 512) + gh * 16 + i) * 512 + gw * 16 + j];
}

__global__ void assemble_kernel(const float* __restrict__ tok, const float* __restrict__ cls,
                                const float* __restrict__ pos, float* __restrict__ t) {
    int idx = blockIdx.x * 256 + threadIdx.x;
    if (idx >= BATCH * NT * EMB) return;
    int d = idx % EMB;
    int n = (idx / EMB) % NT;
    int b = idx / (EMB * NT);
    float v = (n == 0) ? cls[d] : tok[((size_t)b * 1024 + (n - 1)) * EMB + d];
    t[idx] = v + pos[n * EMB + d];
}

__global__ void biaspack_kernel(const float* __restrict__ qb, const float* __restrict__ vb,
                                float* __restrict__ out) {
    int i = blockIdx.x * 256 + threadIdx.x;
    if (i >= 3 * EMB) return;
    out[i] = (i < EMB) ? qb[i] : ((i < 2 * EMB) ? 0.f : vb[i - 2 * EMB]);
}

__global__ void copy_kernel(const float* __restrict__ src, float* __restrict__ dst, int n) {
    int i = blockIdx.x * 256 + threadIdx.x;
    if (i < n) dst[i] = src[i];
}

__global__ void repack_w_kernel(const float* __restrict__ w, float* __restrict__ wp) {
    int idx = blockIdx.x * 256 + threadIdx.x;
    if (idx >= 3072 * 768) return;
    int c = idx % 768, n = idx / 768;
    int ij = n / 768, d = n % 768;
    wp[idx] = w[(size_t)c * 3072 + d * 4 + ij];
}

__global__ void scatter_bhwc_kernel(const float* __restrict__ tmp, const float* __restrict__ bias,
                                    float* __restrict__ y, int HW) {
    int total = BATCH * HW * HW * 4 * 768;
    int idx = blockIdx.x * 256 + threadIdx.x;
    if (idx >= total) return;
    int d = idx % 768;
    int ij = (idx / 768) % 4;
    int p = (idx / 3072) % (HW * HW);
    int b = idx / (3072 * HW * HW);
    int h = p / HW, w = p % HW, i = ij / 2, j = ij % 2;
    int W2 = 2 * HW;
    y[(((size_t)b * W2 + 2 * h + i) * W2 + (2 * w + j)) * 768 + d] = tmp[idx] + bias[d];
}

__global__ void scatter_bchw_kernel(const float* __restrict__ tmp, const float* __restrict__ bias,
                                    float* __restrict__ out, int HW) {
    int total = BATCH * HW * HW * 4 * 768;
    int idx = blockIdx.x * 256 + threadIdx.x;
    if (idx >= total) return;
    int d = idx % 768;
    int ij = (idx / 768) % 4;
    int p = (idx / 3072) % (HW * HW);
    int b = idx / (3072 * HW * HW);
    int h = p / HW, w = p % HW, i = ij / 2, j = ij % 2;
    int W2 = 2 * HW;
    out[(((size_t)b * 768 + d) * W2 + 2 * h + i) * W2 + (2 * w + j)] = tmp[idx] + bias[d];
}

__global__ void bn_gelu_kernel(float* __restrict__ y, const float* __restrict__ w,
                               const float* __restrict__ b, const float* __restrict__ mean,
                               const float* __restrict__ var) {
    int idx = blockIdx.x * 256 + threadIdx.x;
    if (idx >= BATCH * 64 * 64 * 768) return;
    int c = idx % 768;
    float v = y[idx];
    v = (v - mean[c]) * rsqrtf(var[c] + 1e-5f) * w[c] + b[c];
    y[idx] = gelu_exact(v);
}

__global__ void to_map_kernel(const float* __restrict__ feat, float* __restrict__ out) {
    int idx = blockIdx.x * 256 + threadIdx.x;
    if (idx >= BATCH * 768 * 32 * 32) return;
    int xw = idx % 32;
    int yh = (idx / 32) % 32;
    int c = (idx / 1024) % 768;
    int b = idx / (1024 * 768);
    out[idx] = feat[((size_t)b * NT + 1 + yh * 32 + xw) * EMB + c];
}

__global__ void maxpool_kernel(const float* __restrict__ feat, float* __restrict__ out) {
    int idx = blockIdx.x * 256 + threadIdx.x;
    if (idx >= BATCH * 768 * 16 * 16) return;
    int xw = idx % 16;
    int yh = (idx / 16) % 16;
    int c = (idx / 256) % 768;
    int b = idx / (256 * 768);
    float m = -1e30f;
#pragma unroll
    for (int i = 0; i < 2; i++)
#pragma unroll
        for (int j = 0; j < 2; j++) {
            int Y = 2 * yh + i, X = 2 * xw + j;
            m = fmaxf(m, feat[((size_t)b * NT + 1 + Y * 32 + X) * EMB + c]);
        }
    out[idx] = m;
}

// ------------------------- host helpers -------------------------------------
static void pack(const float* in, __nv_bfloat16* out, int M, int K, int Kp,
                 size_t irs, size_t ics, size_t ibs0, size_t ibs1, int nh,
                 size_t obs, float scale, int nz) {
    dim3 g((M * Kp + 255) / 256, nz);
    pack_kernel<<<g, 256>>>(in, out, M, K, Kp, irs, ics, ibs0, ibs1, nh, obs, scale);
}
#define SMEM64  (3 * 2 * (128 + 64) * 40 * 2)    // 92160
#define SMEM128 (2 * 2 * (128 + 128) * 40 * 2)   // 81920
static void gemm_tc(const __nv_bfloat16* A, const __nv_bfloat16* B, float* C,
                    __nv_bfloat16* Cp, const float* bias, const float* resid,
                    int M, int N, int Kp, size_t Abs, size_t Bbs, size_t ldc,
                    size_t cs0, size_t cs1, int nh, int gelu, int nz) {
    int gm = (M + 127) / 128;
    int g128 = ((N + 127) / 128) * gm * nz;
    if (N % 64 == 0 && (N % 128 != 0 || g128 < 148)) {
        dim3 g(N / 64, gm, nz);
        hgemm2<64, 3><<<g, 256, SMEM64>>>(A, B, C, Cp, bias, resid, M, N, Kp, Abs, Bbs,
                                          ldc, cs0, cs1, nh, gelu);
    } else {
        dim3 g((N + 127) / 128, gm, nz);
        hgemm2<128, 2><<<g, 256, SMEM128>>>(A, B, C, Cp, bias, resid, M, N, Kp, Abs, Bbs,
                                            ldc, cs0, cs1, nh, gelu);
    }
}

extern "C" void kernel_launch(void* const* d_in, const int* in_sizes, int n_in,
                              void* d_out, int out_size) {
    const float* x         = (const float*)d_in[0];
    const float* patch_w   = (const float*)d_in[1];
    const float* patch_b   = (const float*)d_in[2];
    const float* cls_token = (const float*)d_in[3];
    const float* pos_embed = (const float*)d_in[4];
    const float* ln1_w     = (const float*)d_in[5];
    const float* ln1_b     = (const float*)d_in[6];
    const float* qkv_w     = (const float*)d_in[7];
    const float* q_bias    = (const float*)d_in[8];
    const float* v_bias    = (const float*)d_in[9];
    const float* rel_tab   = (const float*)d_in[10];
    const float* proj_w    = (const float*)d_in[11];
    const float* proj_b    = (const float*)d_in[12];
    const float* ln2_w     = (const float*)d_in[13];
    const float* ln2_b     = (const float*)d_in[14];
    const float* fc1_w     = (const float*)d_in[15];
    const float* fc1_b     = (const float*)d_in[16];
    const float* fc2_w     = (const float*)d_in[17];
    const float* fc2_b     = (const float*)d_in[18];
    const float* d1_w      = (const float*)d_in[19];
    const float* d1_b      = (const float*)d_in[20];
    const float* bn_w      = (const float*)d_in[21];
    const float* bn_b      = (const float*)d_in[22];
    const float* bn_mean   = (const float*)d_in[23];
    const float* bn_var    = (const float*)d_in[24];
    const float* d2_w      = (const float*)d_in[25];
    const float* d2_b      = (const float*)d_in[26];
    const float* f2w       = (const float*)d_in[27];
    const float* f2b       = (const float*)d_in[28];
    const int*   rel_idx   = (const int*)d_in[29];

    float* out = (float*)d_out;
    float* out1 = out;
    float* out2 = out1 + (size_t)BATCH * 768 * 128 * 128;
    float* out3 = out2 + (size_t)BATCH * 768 * 64 * 64;
    float* out4 = out3 + (size_t)BATCH * 768 * 32 * 32;

    static float *pt = nullptr, *pqkv, *ppatch, *ptok;
    static float *pf0, *pf1, *pf2, *pf3, *py, *ptmp, *pwp, *pqb;
    static __nv_bfloat16 *pa, *pb, *pc;
    if (!pt) {
        cudaGetSymbolAddress((void**)&pt, g_t);
        cudaGetSymbolAddress((void**)&pqkv, g_qkv);
        cudaGetSymbolAddress((void**)&ppatch, g_patch);
        cudaGetSymbolAddress((void**)&ptok, g_tok);
        cudaGetSymbolAddress((void**)&pf0, g_feat0);
        cudaGetSymbolAddress((void**)&pf1, g_feat1);
        cudaGetSymbolAddress((void**)&pf2, g_feat2);
        cudaGetSymbolAddress((void**)&pf3, g_feat3);
        cudaGetSymbolAddress((void**)&py, g_y);
        cudaGetSymbolAddress((void**)&ptmp, g_tmp);
        cudaGetSymbolAddress((void**)&pwp, g_wpack);
        cudaGetSymbolAddress((void**)&pqb, g_qkvbias);
        cudaGetSymbolAddress((void**)&pa, g_pa);
        cudaGetSymbolAddress((void**)&pb, g_pb);
        cudaGetSymbolAddress((void**)&pc, g_pc);
        cudaFuncSetAttribute(flash_attn_kernel,
                             cudaFuncAttributeMaxDynamicSharedMemorySize,
                             (128 + 64 + 64) * FA_LD * 2);
        cudaFuncSetAttribute((const void*)hgemm2<64, 3>,
                             cudaFuncAttributeMaxDynamicSharedMemorySize, SMEM64);
        cudaFuncSetAttribute((const void*)hgemm2<128, 2>,
                             cudaFuncAttributeMaxDynamicSharedMemorySize, SMEM128);
    }

    const int TOKELEMS = BATCH * NT * EMB;
    const int M = BATCH * NT;  // 2050
    const int FA_SMEM = (128 + 64 + 64) * FA_LD * 2;

    // ---- patch embed ----
    patchify_kernel<<<(BATCH * 1024 * EMB + 255) / 256, 256>>>(x, ppatch);
    pack(ppatch, pa, 2048, 768, 768, 768, 1, 0, 0, 1, 0, 1.0f, 1);
    pack(patch_w, pb, 768, 768, 768, 768, 1, 0, 0, 1, 0, 1.0f, 1);
    gemm_tc(pa, pb, ptok, nullptr, patch_b, nullptr, 2048, 768, 768, 0, 0,
            768, 0, 0, 1, 0, 1);
    assemble_kernel<<<(TOKELEMS + 255) / 256, 256>>>(ptok, cls_token, pos_embed, pt);

    // ---- transformer layers ----
    for (int l = 0; l < 12; l++) {
        // LN1 fused with split-pack -> pa
        ln_pack_kernel<<<M, 256>>>(pt, ln1_w + l * EMB, ln1_b + l * EMB, pa);
        biaspack_kernel<<<(3 * EMB + 255) / 256, 256>>>(q_bias + l * EMB, v_bias + l * EMB, pqb);
        pack(qkv_w + (size_t)l * 2304 * 768, pb, 2304, 768, 768, 768, 1, 0, 0, 1, 0, 1.0f, 1);
        gemm_tc(pa, pb, pqkv, nullptr, pqb, nullptr, M, 2304, 768, 0, 0,
                2304, 0, 0, 1, 0, 1);
        // fused attention -> packed proj-A directly in pa
        {
            dim3 g((NT + 127) / 128, BATCH * HEADS);
            flash_attn_kernel<<<g, 256, FA_SMEM>>>(pqkv, rel_tab + (size_t)l * NREL * HEADS,
                                                   rel_idx, pa);
        }
        pack(proj_w + (size_t)l * 768 * 768, pb, 768, 768, 768, 768, 1, 0, 0, 1, 0, 1.0f, 1);
        gemm_tc(pa, pb, pt, nullptr, proj_b + l * EMB, pt, M, 768, 768, 0, 0,
                768, 0, 0, 1, 0, 1);
        // LN2 fused pack -> pa ; fc1 emits packed fc2-A into DEDICATED pc buffer
        ln_pack_kernel<<<M, 256>>>(pt, ln2_w + l * EMB, ln2_b + l * EMB, pa);
        pack(fc1_w + (size_t)l * 3072 * 768, pb, 3072, 768, 768, 768, 1, 0, 0, 1, 0, 1.0f, 1);
        gemm_tc(pa, pb, nullptr, pc, fc1_b + l * 4 * EMB, nullptr, M, 3072, 768, 0, 0,
                3072, 0, 0, 1, 1, 1);
        pack(fc2_w + (size_t)l * 768 * 3072, pb, 768, 3072, 3072, 3072, 1, 0, 0, 1, 0, 1.0f, 1);
        gemm_tc(pc, pb, pt, nullptr, fc2_b + l * EMB, pt, M, 768, 3072, 0, 0,
                768, 0, 0, 1, 0, 1);
        float* fdst = nullptr;
        if (l == 3) fdst = pf0;
        else if (l == 5) fdst = pf1;
        else if (l == 7) fdst = pf2;
        else if (l == 11) fdst = pf3;
        if (fdst) copy_kernel<<<(TOKELEMS + 255) / 256, 256>>>(pt, fdst, TOKELEMS);
    }

    // ---- o3 / o4 ----
    to_map_kernel<<<(BATCH * 768 * 1024 + 255) / 256, 256>>>(pf2, out3);
    maxpool_kernel<<<(BATCH * 768 * 256 + 255) / 256, 256>>>(pf3, out4);

    // ---- fpn1 stage 1 ----
    repack_w_kernel<<<(3072 * 768 + 255) / 256, 256>>>(d1_w, pwp);
    pack(pwp, pb, 3072, 768, 768, 768, 1, 0, 0, 1, 0, 1.0f, 1);
    pack(pf0 + 768, pa, 1024, 768, 768, 768, 1, (size_t)NT * 768, 0, 1,
         (size_t)1024 * 1536, 1.0f, BATCH);
    gemm_tc(pa, pb, ptmp, nullptr, nullptr, nullptr, 1024, 3072, 768,
            (size_t)1024 * 1536, 0, 3072, (size_t)1024 * 3072, 0, 1, 0, BATCH);
    scatter_bhwc_kernel<<<(BATCH * 1024 * 3072 + 255) / 256, 256>>>(ptmp, d1_b, py, 32);
    bn_gelu_kernel<<<(BATCH * 64 * 64 * 768 + 255) / 256, 256>>>(py, bn_w, bn_b, bn_mean, bn_var);

    // ---- fpn1 stage 2 ----
    repack_w_kernel<<<(3072 * 768 + 255) / 256, 256>>>(d2_w, pwp);
    pack(pwp, pb, 3072, 768, 768, 768, 1, 0, 0, 1, 0, 1.0f, 1);
    pack(py, pa, 4096, 768, 768, 768, 1, (size_t)4096 * 768, 0, 1,
         (size_t)4096 * 1536, 1.0f, BATCH);
    gemm_tc(pa, pb, ptmp, nullptr, nullptr, nullptr, 4096, 3072, 768,
            (size_t)4096 * 1536, 0, 3072, (size_t)4096 * 3072, 0, 1, 0, BATCH);
    scatter_bchw_kernel<<<(BATCH * 4096 * 3072 + 255) / 256, 256>>>(ptmp, d2_b, out1, 64);

    // ---- o2 ----
    repack_w_kernel<<<(3072 * 768 + 255) / 256, 256>>>(f2w, pwp);
    pack(pwp, pb, 3072, 768, 768, 768, 1, 0, 0, 1, 0, 1.0f, 1);
    pack(pf1 + 768, pa, 1024, 768, 768, 768, 1, (size_t)NT * 768, 0, 1,
         (size_t)1024 * 1536, 1.0f, BATCH);
    gemm_tc(pa, pb, ptmp, nullptr, nullptr, nullptr, 1024, 3072, 768,
            (size_t)1024 * 1536, 0, 3072, (size_t)1024 * 3072, 0, 1, 0, BATCH);
    scatter_bchw_kernel<<<(BATCH * 1024 * 3072 + 255) / 256, 256>>>(ptmp, f2b, out2, 32);

    (void)in_sizes; (void)n_in; (void)out_size;
}